// round 6
// baseline (speedup 1.0000x reference)
#include <cuda_runtime.h>
#include <cuda_bf16.h>
#include <math.h>
#include <stdint.h>

// Problem constants
#define MROWS 4096   // B*T
#define CEMB  2048
#define TSEQ  2048
#define NHEAD 16
#define NGROUP 4
#define DHEAD 128
#define KVC   512
#define SWIN  512
#define SINK  4
#define NQKV  3072   // 2048 + 512 + 512

// bf16 split scratch
__device__ __nv_bfloat16 g_xhi[(size_t)MROWS * CEMB];
__device__ __nv_bfloat16 g_xlo[(size_t)MROWS * CEMB];
__device__ __nv_bfloat16 g_ohi[(size_t)MROWS * CEMB];
__device__ __nv_bfloat16 g_olo[(size_t)MROWS * CEMB];
__device__ __nv_bfloat16 g_qhi[(size_t)MROWS * CEMB];   // [b,h,t,d]
__device__ __nv_bfloat16 g_qlo[(size_t)MROWS * CEMB];
__device__ __nv_bfloat16 g_khi[(size_t)MROWS * KVC];    // [b,g,t,d]
__device__ __nv_bfloat16 g_klo[(size_t)MROWS * KVC];
__device__ __nv_bfloat16 g_vhi[(size_t)MROWS * KVC];
__device__ __nv_bfloat16 g_vlo[(size_t)MROWS * KVC];
__device__ __nv_bfloat16 g_WT_hi[(size_t)NQKV * CEMB];  // packed Wq|Wk|Wv, [N,K]
__device__ __nv_bfloat16 g_WT_lo[(size_t)NQKV * CEMB];
__device__ __nv_bfloat16 g_WoT_hi[(size_t)CEMB * CEMB];
__device__ __nv_bfloat16 g_WoT_lo[(size_t)CEMB * CEMB];
__device__ float2 g_rope[(size_t)TSEQ * 64];            // (cos, sin) per (t, d)

// ---------------------------------------------------------------------------
// helpers
// ---------------------------------------------------------------------------
__device__ __forceinline__ uint32_t cvta_s(const void* p) {
    return (uint32_t)__cvta_generic_to_shared(p);
}
__device__ __forceinline__ void cp16(uint32_t dst, const void* src) {
    asm volatile("cp.async.cg.shared.global [%0], [%1], 16;\n" :: "r"(dst), "l"(src));
}
#define CP_COMMIT() asm volatile("cp.async.commit_group;\n" ::: "memory")
#define CP_WAIT(n)  asm volatile("cp.async.wait_group %0;\n" :: "n"(n) : "memory")

#define LDSM4(r, addr) \
    asm volatile("ldmatrix.sync.aligned.m8n8.x4.shared.b16 {%0,%1,%2,%3}, [%4];" \
        : "=r"((r)[0]), "=r"((r)[1]), "=r"((r)[2]), "=r"((r)[3]) : "r"(addr))

#define LDSM4T(r, addr) \
    asm volatile("ldmatrix.sync.aligned.m8n8.x4.trans.shared.b16 {%0,%1,%2,%3}, [%4];" \
        : "=r"((r)[0]), "=r"((r)[1]), "=r"((r)[2]), "=r"((r)[3]) : "r"(addr))

#define MMA16816(c, a, b0, b1) \
    asm volatile("mma.sync.aligned.m16n8k16.row.col.f32.bf16.bf16.f32 " \
        "{%0,%1,%2,%3},{%4,%5,%6,%7},{%8,%9},{%0,%1,%2,%3};" \
        : "+f"((c)[0]), "+f"((c)[1]), "+f"((c)[2]), "+f"((c)[3]) \
        : "r"((a)[0]), "r"((a)[1]), "r"((a)[2]), "r"((a)[3]), "r"(b0), "r"(b1))

// 64B-row swizzled address (BK=32 tiles)
__device__ __forceinline__ uint32_t adr32(int r, int c4) {
    return (uint32_t)((r >> 1) * 128 + (((((r & 1) << 2) | c4) ^ ((r >> 1) & 7)) << 4));
}
// 256B-row swizzled address (attention tiles)
__device__ __forceinline__ uint32_t adr128(int r, int c) {
    return (uint32_t)(r * 256 + ((c ^ (r & 7)) << 4));
}

__device__ __forceinline__ void wr_hilo2(__nv_bfloat16* hi, __nv_bfloat16* lo,
                                         float a, float b)
{
    __nv_bfloat162 hv = __floats2bfloat162_rn(a, b);
    __nv_bfloat162 lv = __floats2bfloat162_rn(a - __bfloat162float(hv.x),
                                              b - __bfloat162float(hv.y));
    *(__nv_bfloat162*)hi = hv;
    *(__nv_bfloat162*)lo = lv;
}

// ---------------------------------------------------------------------------
// rope table: (cos, sin) for every (t, d)
// ---------------------------------------------------------------------------
__global__ void rope_table(float2* tab)
{
    int i = blockIdx.x * blockDim.x + threadIdx.x;
    if (i >= TSEQ * 64) return;
    int d = i & 63, t = i >> 6;
    float inv = powf(10000.f, -(float)d * (1.f / 64.f));
    float s, c;
    sincosf((float)t * inv, &s, &c);
    tab[i] = make_float2(c, s);
}

// ---------------------------------------------------------------------------
// split fp32 -> bf16 hi/lo (vectorized by 4)
// ---------------------------------------------------------------------------
__global__ void split_f32(const float* __restrict__ s,
                          __nv_bfloat16* __restrict__ hi,
                          __nv_bfloat16* __restrict__ lo, int n4)
{
    int i = blockIdx.x * blockDim.x + threadIdx.x;
    if (i >= n4) return;
    float4 v = ((const float4*)s)[i];
    __nv_bfloat16 h0 = __float2bfloat16_rn(v.x);
    __nv_bfloat16 h1 = __float2bfloat16_rn(v.y);
    __nv_bfloat16 h2 = __float2bfloat16_rn(v.z);
    __nv_bfloat16 h3 = __float2bfloat16_rn(v.w);
    __nv_bfloat162* ph = (__nv_bfloat162*)hi;
    __nv_bfloat162* pl = (__nv_bfloat162*)lo;
    ph[i * 2 + 0] = __nv_bfloat162(h0, h1);
    ph[i * 2 + 1] = __nv_bfloat162(h2, h3);
    pl[i * 2 + 0] = __nv_bfloat162(
        __float2bfloat16_rn(v.x - __bfloat162float(h0)),
        __float2bfloat16_rn(v.y - __bfloat162float(h1)));
    pl[i * 2 + 1] = __nv_bfloat162(
        __float2bfloat16_rn(v.z - __bfloat162float(h2)),
        __float2bfloat16_rn(v.w - __bfloat162float(h3)));
}

// ---------------------------------------------------------------------------
// transpose + split: W[K][N] fp32 -> WT[N][K] bf16 hi/lo
// ---------------------------------------------------------------------------
__global__ void tsplit(const float* __restrict__ W,
                       __nv_bfloat16* __restrict__ hi,
                       __nv_bfloat16* __restrict__ lo, int K, int N)
{
    __shared__ float t[32][33];
    int n0 = blockIdx.x * 32, k0 = blockIdx.y * 32;
    int tx = threadIdx.x, ty = threadIdx.y;
#pragma unroll
    for (int i = 0; i < 4; i++)
        t[ty + 8 * i][tx] = W[(size_t)(k0 + ty + 8 * i) * N + n0 + tx];
    __syncthreads();
#pragma unroll
    for (int i = 0; i < 4; i++) {
        float v = t[tx][ty + 8 * i];
        __nv_bfloat16 h = __float2bfloat16_rn(v);
        size_t off = (size_t)(n0 + ty + 8 * i) * K + k0 + tx;
        hi[off] = h;
        lo[off] = __float2bfloat16_rn(v - __bfloat162float(h));
    }
}

// ---------------------------------------------------------------------------
// HMMA GEMM, 3-term bf16.
// mode 0: C = A@B^T + bias -> fp32 Cf [4096, 2048]
// mode 1: fused QKV epilogue: N tile routes to Q (rope->qhi/qlo), K (rope->
//         khi/klo), or V (vhi/vlo), with bias added before rope/pack.
// ---------------------------------------------------------------------------
__global__ __launch_bounds__(256, 2) void gemm_mma(
    const __nv_bfloat16* __restrict__ Ahi, const __nv_bfloat16* __restrict__ Alo,
    const __nv_bfloat16* __restrict__ Bhi, const __nv_bfloat16* __restrict__ Blo,
    float* __restrict__ Cf, const float* __restrict__ bq,
    const float* __restrict__ bk, const float* __restrict__ bv,
    __nv_bfloat16* __restrict__ qh, __nv_bfloat16* __restrict__ ql,
    __nv_bfloat16* __restrict__ kh, __nv_bfloat16* __restrict__ kl,
    __nv_bfloat16* __restrict__ vh, __nv_bfloat16* __restrict__ vl,
    const float2* __restrict__ rope, int mode)
{
    constexpr int KD = 2048, NCHUNK = 64, STG = 32768, PITCH = 132;
    extern __shared__ char dsm[];
    uint32_t sbase = (cvta_s(dsm) + 1023) & ~1023u;

    const int tid = threadIdx.x;
    const int wid = tid >> 5, lane = tid & 31;
    const int wm = wid >> 2, wn = wid & 3;
    const int m0 = blockIdx.y * 128, n0 = blockIdx.x * 128;

    uint32_t dsts[2];
    size_t gA[2], gB[2];
#pragma unroll
    for (int p = 0; p < 2; p++) {
        int idx = tid + p * 256;
        int r = idx >> 2, c = idx & 3;
        dsts[p] = adr32(r, c);
        gA[p] = (size_t)(m0 + r) * KD + c * 8;
        gB[p] = (size_t)(n0 + r) * KD + c * 8;
    }

    const int arow = (lane & 7) + ((lane >> 3) & 1) * 8;
    const int acb  = lane >> 4;
    const int brow = (lane & 7) + (lane >> 4) * 8;
    const int bcb  = (lane >> 3) & 1;
    const int cbs  = (lane & 3) * 2;

    float acc[4][4][4];
#pragma unroll
    for (int i = 0; i < 4; i++)
#pragma unroll
        for (int j = 0; j < 4; j++) {
            acc[i][j][0] = 0.f; acc[i][j][1] = 0.f;
            acc[i][j][2] = 0.f; acc[i][j][3] = 0.f;
        }

#pragma unroll
    for (int ch = 0; ch < 2; ch++) {
        uint32_t st = sbase + ch * STG;
        int k0 = ch * 32;
#pragma unroll
        for (int p = 0; p < 2; p++) {
            cp16(st +     0 + dsts[p], Ahi + gA[p] + k0);
            cp16(st +  8192 + dsts[p], Alo + gA[p] + k0);
            cp16(st + 16384 + dsts[p], Bhi + gB[p] + k0);
            cp16(st + 24576 + dsts[p], Blo + gB[p] + k0);
        }
        CP_COMMIT();
    }

    for (int c = 0; c < NCHUNK; c++) {
        if (c + 2 < NCHUNK) {
            int ch = c + 2;
            uint32_t st = sbase + (ch % 3) * STG;
            int k0 = ch * 32;
#pragma unroll
            for (int p = 0; p < 2; p++) {
                cp16(st +     0 + dsts[p], Ahi + gA[p] + k0);
                cp16(st +  8192 + dsts[p], Alo + gA[p] + k0);
                cp16(st + 16384 + dsts[p], Bhi + gB[p] + k0);
                cp16(st + 24576 + dsts[p], Blo + gB[p] + k0);
            }
            CP_COMMIT();
            CP_WAIT(2);
        } else if (c + 1 < NCHUNK) {
            CP_WAIT(1);
        } else {
            CP_WAIT(0);
        }
        __syncthreads();

        uint32_t st = sbase + (c % 3) * STG;
        uint32_t aHiB = st, aLoB = st + 8192, bHiB = st + 16384, bLoB = st + 24576;

#pragma unroll
        for (int ks = 0; ks < 2; ks++) {
            uint32_t ah[4][4], al[4][4], bh[2][4], bl[2][4];
#pragma unroll
            for (int mt = 0; mt < 4; mt++)
                LDSM4(ah[mt], aHiB + adr32(wm * 64 + mt * 16 + arow, 2 * ks + acb));
#pragma unroll
            for (int np = 0; np < 2; np++)
                LDSM4(bh[np], bHiB + adr32(wn * 32 + np * 16 + brow, 2 * ks + bcb));
#pragma unroll
            for (int mt = 0; mt < 4; mt++)
#pragma unroll
                for (int nt = 0; nt < 4; nt++)
                    MMA16816(acc[mt][nt], ah[mt], bh[nt >> 1][(nt & 1) * 2],
                             bh[nt >> 1][(nt & 1) * 2 + 1]);
#pragma unroll
            for (int np = 0; np < 2; np++)
                LDSM4(bl[np], bLoB + adr32(wn * 32 + np * 16 + brow, 2 * ks + bcb));
#pragma unroll
            for (int mt = 0; mt < 4; mt++)
#pragma unroll
                for (int nt = 0; nt < 4; nt++)
                    MMA16816(acc[mt][nt], ah[mt], bl[nt >> 1][(nt & 1) * 2],
                             bl[nt >> 1][(nt & 1) * 2 + 1]);
#pragma unroll
            for (int mt = 0; mt < 4; mt++)
                LDSM4(al[mt], aLoB + adr32(wm * 64 + mt * 16 + arow, 2 * ks + acb));
#pragma unroll
            for (int mt = 0; mt < 4; mt++)
#pragma unroll
                for (int nt = 0; nt < 4; nt++)
                    MMA16816(acc[mt][nt], al[mt], bh[nt >> 1][(nt & 1) * 2],
                             bh[nt >> 1][(nt & 1) * 2 + 1]);
        }
        __syncthreads();
    }

    if (mode == 0) {
        // plain fp32 epilogue (Wo projection)
#pragma unroll
        for (int mt = 0; mt < 4; mt++) {
            int r0 = m0 + wm * 64 + mt * 16 + (lane >> 2);
#pragma unroll
            for (int nt = 0; nt < 4; nt++) {
                int cc = n0 + wn * 32 + nt * 8 + cbs;
                float bb0 = bq[cc], bb1 = bq[cc + 1];
                float2 v0 = make_float2(acc[mt][nt][0] + bb0, acc[mt][nt][1] + bb1);
                float2 v1 = make_float2(acc[mt][nt][2] + bb0, acc[mt][nt][3] + bb1);
                *(float2*)(Cf + (size_t)r0 * CEMB + cc) = v0;
                *(float2*)(Cf + (size_t)(r0 + 8) * CEMB + cc) = v1;
            }
        }
        return;
    }

    // mode 1: fused QKV epilogue via smem staging
    const float* bias = (n0 < 2048) ? bq + n0
                      : (n0 < 2560) ? bk + (n0 - 2048)
                                    : bv + (n0 - 2560);
    float* s = (float*)((((uintptr_t)dsm) + 1023) & ~(uintptr_t)1023);

#pragma unroll
    for (int mt = 0; mt < 4; mt++) {
        int rl = wm * 64 + mt * 16 + (lane >> 2);
#pragma unroll
        for (int nt = 0; nt < 4; nt++) {
            int cl = wn * 32 + nt * 8 + cbs;
            float bb0 = bias[cl], bb1 = bias[cl + 1];
            s[rl * PITCH + cl]           = acc[mt][nt][0] + bb0;
            s[rl * PITCH + cl + 1]       = acc[mt][nt][1] + bb1;
            s[(rl + 8) * PITCH + cl]     = acc[mt][nt][2] + bb0;
            s[(rl + 8) * PITCH + cl + 1] = acc[mt][nt][3] + bb1;
        }
    }
    __syncthreads();

    if (n0 < 2560) {
        // Q or K: rope + pack
        const bool isQ = (n0 < 2048);
        const float qsc = isQ ? 0.08838834764831845f : 1.0f;
        const int hh = isQ ? (n0 >> 7) : ((n0 - 2048) >> 7);
        const int nh = isQ ? NHEAD : NGROUP;
        __nv_bfloat16* Hi = isQ ? qh : kh;
        __nv_bfloat16* Lo = isQ ? ql : kl;
#pragma unroll 4
        for (int idx = tid; idx < 128 * 32; idx += 256) {
            int r = idx >> 5, d2 = idx & 31;
            int m = m0 + r, t = m & (TSEQ - 1), b = m >> 11;
            int d0 = d2 * 2;
            float x1a = s[r * PITCH + d0],      x1b = s[r * PITCH + d0 + 1];
            float x2a = s[r * PITCH + d0 + 64], x2b = s[r * PITCH + d0 + 65];
            float2 ca = rope[t * 64 + d0], cb = rope[t * 64 + d0 + 1];
            float y1a = (x1a * ca.x - x2a * ca.y) * qsc;
            float y2a = (x1a * ca.y + x2a * ca.x) * qsc;
            float y1b = (x1b * cb.x - x2b * cb.y) * qsc;
            float y2b = (x1b * cb.y + x2b * cb.x) * qsc;
            size_t orow = ((size_t)(b * nh + hh) * TSEQ + t) * DHEAD;
            wr_hilo2(Hi + orow + d0,      Lo + orow + d0,      y1a, y1b);
            wr_hilo2(Hi + orow + 64 + d0, Lo + orow + 64 + d0, y2a, y2b);
        }
    } else {
        // V: pack only
        const int g = (n0 - 2560) >> 7;
#pragma unroll 4
        for (int idx = tid; idx < 128 * 64; idx += 256) {
            int r = idx >> 6, c2 = idx & 63;
            int m = m0 + r, t = m & (TSEQ - 1), b = m >> 11;
            int c0 = c2 * 2;
            float va = s[r * PITCH + c0], vb = s[r * PITCH + c0 + 1];
            size_t o = ((size_t)(b * NGROUP + g) * TSEQ + t) * DHEAD + c0;
            wr_hilo2(vh + o, vl + o, va, vb);
        }
    }
}

// ---------------------------------------------------------------------------
// HMMA flash attention (unchanged from R5)
// ---------------------------------------------------------------------------
__global__ __launch_bounds__(128, 2) void attn_mma(
    const __nv_bfloat16* __restrict__ qhi, const __nv_bfloat16* __restrict__ qlo,
    const __nv_bfloat16* __restrict__ khi, const __nv_bfloat16* __restrict__ klo,
    const __nv_bfloat16* __restrict__ vhi, const __nv_bfloat16* __restrict__ vlo,
    __nv_bfloat16* __restrict__ ohi, __nv_bfloat16* __restrict__ olo)
{
    extern __shared__ char sm[];
    uint32_t sb = (cvta_s(sm) + 1023) & ~1023u;
    const uint32_t sQh = sb, sQl = sb + 16384;
    const uint32_t sKV = sb + 32768;

    const int tid = threadIdx.x, w = tid >> 5, lane = tid & 31;
    const int b = blockIdx.y >> 4, h = blockIdx.y & 15, g = h >> 2;
    const int qs = blockIdx.x * 64;

    {
        size_t qb = ((size_t)(b * NHEAD + h) * TSEQ + qs) * DHEAD;
#pragma unroll
        for (int p = 0; p < 8; p++) {
            int idx = tid + p * 128;
            int row = idx >> 4, ch = idx & 15;
            uint32_t d = adr128(row, ch);
            size_t s = qb + (size_t)row * DHEAD + ch * 8;
            cp16(sQh + d, qhi + s);
            cp16(sQl + d, qlo + s);
        }
    }
    CP_COMMIT();

    int t0 = qs - SWIN; if (t0 < 0) t0 = 0;
    const int sink = (t0 > 0) ? 1 : 0;
    const int ntiles = sink + (qs + 64 - t0) / 32;
    const size_t kvbase = (size_t)(b * NGROUP + g) * TSEQ * DHEAD;

    {
        int ts = sink ? 0 : t0;
        size_t kb = kvbase + (size_t)ts * DHEAD;
#pragma unroll
        for (int p = 0; p < 4; p++) {
            int idx = tid + p * 128;
            int row = idx >> 4, ch = idx & 15;
            uint32_t d = adr128(row, ch);
            size_t s = kb + (size_t)row * DHEAD + ch * 8;
            cp16(sKV +     0 + d, khi + s);
            cp16(sKV +  8192 + d, klo + s);
            cp16(sKV + 16384 + d, vhi + s);
            cp16(sKV + 24576 + d, vlo + s);
        }
    }
    CP_COMMIT();

    const int arow = (lane & 7) + ((lane >> 3) & 1) * 8;
    const int acb  = lane >> 4;
    const int brow = (lane & 7) + (lane >> 4) * 8;
    const int bcb  = (lane >> 3) & 1;
    const int vr_i = ((lane >> 3) & 1) * 8 + (lane & 7);
    const int vc_i = lane >> 4;
    const int i0 = qs + w * 16 + (lane >> 2);
    const int i1 = i0 + 8;
    const int iwmax = qs + w * 16 + 15;
    const int cbs = (lane & 3) * 2;

    CP_WAIT(1);
    __syncthreads();
    uint32_t qh[8][4], ql[8][4];
#pragma unroll
    for (int kc = 0; kc < 8; kc++) {
        uint32_t off = adr128(w * 16 + arow, 2 * kc + acb);
        LDSM4(qh[kc], sQh + off);
        LDSM4(ql[kc], sQl + off);
    }

    float o[16][4];
#pragma unroll
    for (int i = 0; i < 16; i++) { o[i][0] = 0.f; o[i][1] = 0.f; o[i][2] = 0.f; o[i][3] = 0.f; }
    float m0 = -1e30f, m1 = -1e30f, l0 = 0.f, l1 = 0.f;

    for (int it = 0; it < ntiles; it++) {
        const bool snk = (sink && it == 0);
        const int ts = snk ? 0 : t0 + (it - sink) * 32;
        const int n2max = snk ? 1 : 2;

        if (it + 1 < ntiles) {
            int tsn = t0 + (it + 1 - sink) * 32;
            uint32_t st = sKV + ((it + 1) & 1) * 32768;
            size_t kb = kvbase + (size_t)tsn * DHEAD;
#pragma unroll
            for (int p = 0; p < 4; p++) {
                int idx = tid + p * 128;
                int row = idx >> 4, ch = idx & 15;
                uint32_t d = adr128(row, ch);
                size_t s = kb + (size_t)row * DHEAD + ch * 8;
                cp16(st +     0 + d, khi + s);
                cp16(st +  8192 + d, klo + s);
                cp16(st + 16384 + d, vhi + s);
                cp16(st + 24576 + d, vlo + s);
            }
            CP_COMMIT();
            CP_WAIT(1);
        } else {
            CP_WAIT(0);
        }
        __syncthreads();

        uint32_t stg = sKV + (it & 1) * 32768;
        uint32_t sKh = stg, sKl = stg + 8192, sVh = stg + 16384, sVl = stg + 24576;

        float sc[4][4];
#pragma unroll
        for (int i = 0; i < 4; i++) { sc[i][0] = 0.f; sc[i][1] = 0.f; sc[i][2] = 0.f; sc[i][3] = 0.f; }

        for (int n2 = 0; n2 < n2max; n2++) {
            if (ts + n2 * 16 > iwmax) break;
#pragma unroll
            for (int kc = 0; kc < 8; kc++) {
                uint32_t off = adr128(n2 * 16 + brow, 2 * kc + bcb);
                uint32_t kh_[4], kl_[4];
                LDSM4(kh_, sKh + off);
                LDSM4(kl_, sKl + off);
                MMA16816(sc[2 * n2],     qh[kc], kh_[0], kh_[1]);
                MMA16816(sc[2 * n2],     qh[kc], kl_[0], kl_[1]);
                MMA16816(sc[2 * n2],     ql[kc], kh_[0], kh_[1]);
                MMA16816(sc[2 * n2 + 1], qh[kc], kh_[2], kh_[3]);
                MMA16816(sc[2 * n2 + 1], qh[kc], kl_[2], kl_[3]);
                MMA16816(sc[2 * n2 + 1], ql[kc], kh_[2], kh_[3]);
            }
        }

        float rm0 = -1e30f, rm1 = -1e30f;
#pragma unroll
        for (int nt = 0; nt < 4; nt++) {
            int j0 = ts + nt * 8 + cbs, j1 = j0 + 1;
            sc[nt][0] = (j0 <= i0 && (j0 >= i0 - SWIN || j0 < SINK)) ? sc[nt][0] : -1e30f;
            sc[nt][1] = (j1 <= i0 && (j1 >= i0 - SWIN || j1 < SINK)) ? sc[nt][1] : -1e30f;
            sc[nt][2] = (j0 <= i1 && (j0 >= i1 - SWIN || j0 < SINK)) ? sc[nt][2] : -1e30f;
            sc[nt][3] = (j1 <= i1 && (j1 >= i1 - SWIN || j1 < SINK)) ? sc[nt][3] : -1e30f;
            rm0 = fmaxf(rm0, fmaxf(sc[nt][0], sc[nt][1]));
            rm1 = fmaxf(rm1, fmaxf(sc[nt][2], sc[nt][3]));
        }
        rm0 = fmaxf(rm0, __shfl_xor_sync(0xffffffffu, rm0, 1));
        rm0 = fmaxf(rm0, __shfl_xor_sync(0xffffffffu, rm0, 2));
        rm1 = fmaxf(rm1, __shfl_xor_sync(0xffffffffu, rm1, 1));
        rm1 = fmaxf(rm1, __shfl_xor_sync(0xffffffffu, rm1, 2));
        float mn0 = fmaxf(m0, rm0), mn1 = fmaxf(m1, rm1);
        float c0 = __expf(m0 - mn0), c1 = __expf(m1 - mn1);
        m0 = mn0; m1 = mn1;

#pragma unroll
        for (int nd = 0; nd < 16; nd++) {
            o[nd][0] *= c0; o[nd][1] *= c0; o[nd][2] *= c1; o[nd][3] *= c1;
        }

        float rs0 = 0.f, rs1 = 0.f;
        for (int k2 = 0; k2 < n2max; k2++) {
            if (ts + k2 * 16 > iwmax) break;
            uint32_t aP[4], aPl[4];
#pragma unroll
            for (int q2 = 0; q2 < 2; q2++) {
                int nt = 2 * k2 + q2;
                float p00 = __expf(sc[nt][0] - mn0), p01 = __expf(sc[nt][1] - mn0);
                float p10 = __expf(sc[nt][2] - mn1), p11 = __expf(sc[nt][3] - mn1);
                rs0 += p00 + p01; rs1 += p10 + p11;
                __nv_bfloat162 h0v = __floats2bfloat162_rn(p00, p01);
                __nv_bfloat162 h1v = __floats2bfloat162_rn(p10, p11);
                __nv_bfloat162 l0v = __floats2bfloat162_rn(
                    p00 - __bfloat162float(h0v.x), p01 - __bfloat162float(h0v.y));
                __nv_bfloat162 l1v = __floats2bfloat162_rn(
                    p10 - __bfloat162float(h1v.x), p11 - __bfloat162float(h1v.y));
                aP[2 * q2]      = *(uint32_t*)&h0v;
                aP[2 * q2 + 1]  = *(uint32_t*)&h1v;
                aPl[2 * q2]     = *(uint32_t*)&l0v;
                aPl[2 * q2 + 1] = *(uint32_t*)&l1v;
            }
#pragma unroll
            for (int ndp = 0; ndp < 8; ndp++) {
                uint32_t voff = adr128(k2 * 16 + vr_i, ndp * 2 + vc_i);
                uint32_t bv[4], bvl[4];
                LDSM4T(bv,  sVh + voff);
                LDSM4T(bvl, sVl + voff);
                MMA16816(o[ndp * 2],     aP,  bv[0],  bv[1]);
                MMA16816(o[ndp * 2],     aP,  bvl[0], bvl[1]);
                MMA16816(o[ndp * 2],     aPl, bv[0],  bv[1]);
                MMA16816(o[ndp * 2 + 1], aP,  bv[2],  bv[3]);
                MMA16816(o[ndp * 2 + 1], aP,  bvl[2], bvl[3]);
                MMA16816(o[ndp * 2 + 1], aPl, bv[2],  bv[3]);
            }
        }
        rs0 += __shfl_xor_sync(0xffffffffu, rs0, 1);
        rs0 += __shfl_xor_sync(0xffffffffu, rs0, 2);
        rs1 += __shfl_xor_sync(0xffffffffu, rs1, 1);
        rs1 += __shfl_xor_sync(0xffffffffu, rs1, 2);
        l0 = l0 * c0 + rs0;
        l1 = l1 * c1 + rs1;

        __syncthreads();
    }

    float il0 = 1.f / l0, il1 = 1.f / l1;
    size_t or0 = (size_t)(b * TSEQ + qs + w * 16 + (lane >> 2)) * CEMB + h * DHEAD;
    size_t or1 = or0 + (size_t)8 * CEMB;
#pragma unroll
    for (int nd = 0; nd < 16; nd++) {
        int col = nd * 8 + cbs;
        wr_hilo2(ohi + or0 + col, olo + or0 + col, o[nd][0] * il0, o[nd][1] * il0);
        wr_hilo2(ohi + or1 + col, olo + or1 + col, o[nd][2] * il1, o[nd][3] * il1);
    }
}

// ---------------------------------------------------------------------------
extern "C" void kernel_launch(void* const* d_in, const int* in_sizes, int n_in,
                              void* d_out, int out_size)
{
    const float* x  = (const float*)d_in[0];
    const float* Wq = (const float*)d_in[1];
    const float* bq = (const float*)d_in[2];
    const float* Wk = (const float*)d_in[3];
    const float* bk = (const float*)d_in[4];
    const float* Wv = (const float*)d_in[5];
    const float* bv = (const float*)d_in[6];
    const float* Wo = (const float*)d_in[7];
    const float* bo = (const float*)d_in[8];
    float* out = (float*)d_out;

    __nv_bfloat16 *xhi, *xlo, *ohi, *olo, *qhi, *qlo, *khi, *klo, *vhi, *vlo;
    __nv_bfloat16 *wth, *wtl, *woh, *wol;
    float2* rope;
    cudaGetSymbolAddress((void**)&xhi, g_xhi);
    cudaGetSymbolAddress((void**)&xlo, g_xlo);
    cudaGetSymbolAddress((void**)&ohi, g_ohi);
    cudaGetSymbolAddress((void**)&olo, g_olo);
    cudaGetSymbolAddress((void**)&qhi, g_qhi);
    cudaGetSymbolAddress((void**)&qlo, g_qlo);
    cudaGetSymbolAddress((void**)&khi, g_khi);
    cudaGetSymbolAddress((void**)&klo, g_klo);
    cudaGetSymbolAddress((void**)&vhi, g_vhi);
    cudaGetSymbolAddress((void**)&vlo, g_vlo);
    cudaGetSymbolAddress((void**)&wth, g_WT_hi);
    cudaGetSymbolAddress((void**)&wtl, g_WT_lo);
    cudaGetSymbolAddress((void**)&woh, g_WoT_hi);
    cudaGetSymbolAddress((void**)&wol, g_WoT_lo);
    cudaGetSymbolAddress((void**)&rope, g_rope);

    const int GEMM_SMEM = 99328;   // 3*32KB pipeline, reused as 128x132 fp32 staging
    cudaFuncSetAttribute(gemm_mma, cudaFuncAttributeMaxDynamicSharedMemorySize, GEMM_SMEM);
    const int ATTN_SMEM = 99328;
    cudaFuncSetAttribute(attn_mma, cudaFuncAttributeMaxDynamicSharedMemorySize, ATTN_SMEM);

    // rope table + input split + packed weight transposes
    rope_table<<<(TSEQ * 64) / 256, 256>>>(rope);
    {
        int n4 = (MROWS * CEMB) / 4;
        split_f32<<<(n4 + 255) / 256, 256>>>(x, xhi, xlo, n4);
    }
    tsplit<<<dim3(CEMB / 32, CEMB / 32), dim3(32, 8)>>>(Wq, wth, wtl, CEMB, CEMB);
    tsplit<<<dim3(KVC / 32, CEMB / 32), dim3(32, 8)>>>(
        Wk, wth + (size_t)2048 * CEMB, wtl + (size_t)2048 * CEMB, CEMB, KVC);
    tsplit<<<dim3(KVC / 32, CEMB / 32), dim3(32, 8)>>>(
        Wv, wth + (size_t)2560 * CEMB, wtl + (size_t)2560 * CEMB, CEMB, KVC);
    tsplit<<<dim3(CEMB / 32, CEMB / 32), dim3(32, 8)>>>(Wo, woh, wol, CEMB, CEMB);

    // fused QKV projection + rope + pack (one launch)
    gemm_mma<<<dim3(NQKV / 128, MROWS / 128), 256, GEMM_SMEM>>>(
        xhi, xlo, wth, wtl,
        nullptr, bq, bk, bv,
        qhi, qlo, khi, klo, vhi, vlo, rope, 1);

    // flash attention
    attn_mma<<<dim3(TSEQ / 64, 2 * NHEAD), 128, ATTN_SMEM>>>(
        qhi, qlo, khi, klo, vhi, vlo, ohi, olo);

    // output projection
    gemm_mma<<<dim3(CEMB / 128, MROWS / 128), 256, GEMM_SMEM>>>(
        ohi, olo, woh, wol,
        out, bo, bo, bo,
        qhi, qlo, khi, klo, vhi, vlo, rope, 0);
}

// round 7
// speedup vs baseline: 1.1747x; 1.1747x over previous
#include <cuda_runtime.h>
#include <cuda_bf16.h>
#include <cuda_fp16.h>
#include <math.h>
#include <stdint.h>

// Problem constants
#define MROWS 4096   // B*T
#define CEMB  2048
#define TSEQ  2048
#define NHEAD 16
#define NGROUP 4
#define DHEAD 128
#define KVC   512
#define SWIN  512
#define SINK  4
#define NQKV  3072

// scratch
__device__ __nv_bfloat16 g_xhi[(size_t)MROWS * CEMB];
__device__ __nv_bfloat16 g_xlo[(size_t)MROWS * CEMB];
__device__ __half        g_oh [(size_t)MROWS * CEMB];   // attention out, fp16 single
__device__ __nv_bfloat16 g_qhi[(size_t)MROWS * CEMB];   // [b,h,t,d]
__device__ __nv_bfloat16 g_qlo[(size_t)MROWS * CEMB];
__device__ __nv_bfloat16 g_khi[(size_t)MROWS * KVC];    // [b,g,t,d]
__device__ __nv_bfloat16 g_klo[(size_t)MROWS * KVC];
__device__ __half        g_vh [(size_t)MROWS * KVC];    // V fp16 single
__device__ __nv_bfloat16 g_WT_hi[(size_t)NQKV * CEMB];  // packed Wq|Wk|Wv, [N,K] bf16
__device__ __nv_bfloat16 g_WT_lo[(size_t)NQKV * CEMB];
__device__ __half        g_WoT_h[(size_t)CEMB * CEMB];  // Wo^T fp16 hi/lo
__device__ __half        g_WoT_l[(size_t)CEMB * CEMB];
__device__ float2 g_rope[(size_t)TSEQ * 64];

// ---------------------------------------------------------------------------
// helpers
// ---------------------------------------------------------------------------
__device__ __forceinline__ uint32_t cvta_s(const void* p) {
    return (uint32_t)__cvta_generic_to_shared(p);
}
__device__ __forceinline__ void cp16(uint32_t dst, const void* src) {
    asm volatile("cp.async.cg.shared.global [%0], [%1], 16;\n" :: "r"(dst), "l"(src));
}
#define CP_COMMIT() asm volatile("cp.async.commit_group;\n" ::: "memory")
#define CP_WAIT(n)  asm volatile("cp.async.wait_group %0;\n" :: "n"(n) : "memory")

#define LDSM4(r, addr) \
    asm volatile("ldmatrix.sync.aligned.m8n8.x4.shared.b16 {%0,%1,%2,%3}, [%4];" \
        : "=r"((r)[0]), "=r"((r)[1]), "=r"((r)[2]), "=r"((r)[3]) : "r"(addr))

#define LDSM4T(r, addr) \
    asm volatile("ldmatrix.sync.aligned.m8n8.x4.trans.shared.b16 {%0,%1,%2,%3}, [%4];" \
        : "=r"((r)[0]), "=r"((r)[1]), "=r"((r)[2]), "=r"((r)[3]) : "r"(addr))

#define MMA_BF(c, a, b0, b1) \
    asm volatile("mma.sync.aligned.m16n8k16.row.col.f32.bf16.bf16.f32 " \
        "{%0,%1,%2,%3},{%4,%5,%6,%7},{%8,%9},{%0,%1,%2,%3};" \
        : "+f"((c)[0]), "+f"((c)[1]), "+f"((c)[2]), "+f"((c)[3]) \
        : "r"((a)[0]), "r"((a)[1]), "r"((a)[2]), "r"((a)[3]), "r"(b0), "r"(b1))

#define MMA_H(c, a, b0, b1) \
    asm volatile("mma.sync.aligned.m16n8k16.row.col.f32.f16.f16.f32 " \
        "{%0,%1,%2,%3},{%4,%5,%6,%7},{%8,%9},{%0,%1,%2,%3};" \
        : "+f"((c)[0]), "+f"((c)[1]), "+f"((c)[2]), "+f"((c)[3]) \
        : "r"((a)[0]), "r"((a)[1]), "r"((a)[2]), "r"((a)[3]), "r"(b0), "r"(b1))

__device__ __forceinline__ uint32_t adr32(int r, int c4) {
    return (uint32_t)((r >> 1) * 128 + (((((r & 1) << 2) | c4) ^ ((r >> 1) & 7)) << 4));
}
__device__ __forceinline__ uint32_t adr128(int r, int c) {
    return (uint32_t)(r * 256 + ((c ^ (r & 7)) << 4));
}

__device__ __forceinline__ void wr_hilo2(__nv_bfloat16* hi, __nv_bfloat16* lo,
                                         float a, float b)
{
    __nv_bfloat162 hv = __floats2bfloat162_rn(a, b);
    __nv_bfloat162 lv = __floats2bfloat162_rn(a - __bfloat162float(hv.x),
                                              b - __bfloat162float(hv.y));
    *(__nv_bfloat162*)hi = hv;
    *(__nv_bfloat162*)lo = lv;
}

// ---------------------------------------------------------------------------
// rope table
// ---------------------------------------------------------------------------
__global__ void rope_table(float2* tab)
{
    int i = blockIdx.x * blockDim.x + threadIdx.x;
    if (i >= TSEQ * 64) return;
    int d = i & 63, t = i >> 6;
    float inv = powf(10000.f, -(float)d * (1.f / 64.f));
    float s, c;
    sincosf((float)t * inv, &s, &c);
    tab[i] = make_float2(c, s);
}

// ---------------------------------------------------------------------------
// split fp32 -> bf16 hi/lo
// ---------------------------------------------------------------------------
__global__ void split_f32(const float* __restrict__ s,
                          __nv_bfloat16* __restrict__ hi,
                          __nv_bfloat16* __restrict__ lo, int n4)
{
    int i = blockIdx.x * blockDim.x + threadIdx.x;
    if (i >= n4) return;
    float4 v = ((const float4*)s)[i];
    __nv_bfloat16 h0 = __float2bfloat16_rn(v.x);
    __nv_bfloat16 h1 = __float2bfloat16_rn(v.y);
    __nv_bfloat16 h2 = __float2bfloat16_rn(v.z);
    __nv_bfloat16 h3 = __float2bfloat16_rn(v.w);
    __nv_bfloat162* ph = (__nv_bfloat162*)hi;
    __nv_bfloat162* pl = (__nv_bfloat162*)lo;
    ph[i * 2 + 0] = __nv_bfloat162(h0, h1);
    ph[i * 2 + 1] = __nv_bfloat162(h2, h3);
    pl[i * 2 + 0] = __nv_bfloat162(
        __float2bfloat16_rn(v.x - __bfloat162float(h0)),
        __float2bfloat16_rn(v.y - __bfloat162float(h1)));
    pl[i * 2 + 1] = __nv_bfloat162(
        __float2bfloat16_rn(v.z - __bfloat162float(h2)),
        __float2bfloat16_rn(v.w - __bfloat162float(h3)));
}

// ---------------------------------------------------------------------------
// transpose+split QKV weights (bf16, packed rows) — ONE launch
// blockIdx.x: [0,64) Wq, [64,80) Wk, [80,96) Wv; blockIdx.y: k block
// ---------------------------------------------------------------------------
__global__ void tsplit_qkv(const float* __restrict__ Wq,
                           const float* __restrict__ Wk,
                           const float* __restrict__ Wv,
                           __nv_bfloat16* __restrict__ hi,
                           __nv_bfloat16* __restrict__ lo)
{
    __shared__ float t[32][33];
    int bx = blockIdx.x, k0 = blockIdx.y * 32;
    const float* W; int N, n0, ro;
    if (bx < 64)      { W = Wq; N = 2048; n0 = bx * 32;        ro = 0; }
    else if (bx < 80) { W = Wk; N = 512;  n0 = (bx - 64) * 32; ro = 2048; }
    else              { W = Wv; N = 512;  n0 = (bx - 80) * 32; ro = 2560; }
    int tx = threadIdx.x, ty = threadIdx.y;
#pragma unroll
    for (int i = 0; i < 4; i++)
        t[ty + 8 * i][tx] = W[(size_t)(k0 + ty + 8 * i) * N + n0 + tx];
    __syncthreads();
#pragma unroll
    for (int i = 0; i < 4; i++) {
        float v = t[tx][ty + 8 * i];
        __nv_bfloat16 h = __float2bfloat16_rn(v);
        size_t off = (size_t)(ro + n0 + ty + 8 * i) * CEMB + k0 + tx;
        hi[off] = h;
        lo[off] = __float2bfloat16_rn(v - __bfloat162float(h));
    }
}

// ---------------------------------------------------------------------------
// transpose+split Wo -> fp16 hi/lo
// ---------------------------------------------------------------------------
__global__ void tsplit_wo(const float* __restrict__ W,
                          __half* __restrict__ hi, __half* __restrict__ lo)
{
    __shared__ float t[32][33];
    int n0 = blockIdx.x * 32, k0 = blockIdx.y * 32;
    int tx = threadIdx.x, ty = threadIdx.y;
#pragma unroll
    for (int i = 0; i < 4; i++)
        t[ty + 8 * i][tx] = W[(size_t)(k0 + ty + 8 * i) * CEMB + n0 + tx];
    __syncthreads();
#pragma unroll
    for (int i = 0; i < 4; i++) {
        float v = t[tx][ty + 8 * i];
        __half h = __float2half_rn(v);
        size_t off = (size_t)(n0 + ty + 8 * i) * CEMB + k0 + tx;
        hi[off] = h;
        lo[off] = __float2half_rn(v - __half2float(h));
    }
}

// ---------------------------------------------------------------------------
// QKV GEMM, 3-term bf16, fused rope/pack epilogue (R6 mode-1, V -> fp16)
// ---------------------------------------------------------------------------
__global__ __launch_bounds__(256, 2) void gemm_qkv(
    const __nv_bfloat16* __restrict__ Ahi, const __nv_bfloat16* __restrict__ Alo,
    const __nv_bfloat16* __restrict__ Bhi, const __nv_bfloat16* __restrict__ Blo,
    const float* __restrict__ bq, const float* __restrict__ bk,
    const float* __restrict__ bv,
    __nv_bfloat16* __restrict__ qh, __nv_bfloat16* __restrict__ ql,
    __nv_bfloat16* __restrict__ kh, __nv_bfloat16* __restrict__ kl,
    __half* __restrict__ vh, const float2* __restrict__ rope)
{
    constexpr int KD = 2048, NCHUNK = 64, STG = 32768, PITCH = 132;
    extern __shared__ char dsm[];
    uint32_t sbase = (cvta_s(dsm) + 1023) & ~1023u;

    const int tid = threadIdx.x;
    const int wid = tid >> 5, lane = tid & 31;
    const int wm = wid >> 2, wn = wid & 3;
    const int m0 = blockIdx.y * 128, n0 = blockIdx.x * 128;

    uint32_t dsts[2];
    size_t gA[2], gB[2];
#pragma unroll
    for (int p = 0; p < 2; p++) {
        int idx = tid + p * 256;
        int r = idx >> 2, c = idx & 3;
        dsts[p] = adr32(r, c);
        gA[p] = (size_t)(m0 + r) * KD + c * 8;
        gB[p] = (size_t)(n0 + r) * KD + c * 8;
    }

    const int arow = (lane & 7) + ((lane >> 3) & 1) * 8;
    const int acb  = lane >> 4;
    const int brow = (lane & 7) + (lane >> 4) * 8;
    const int bcb  = (lane >> 3) & 1;
    const int cbs  = (lane & 3) * 2;

    float acc[4][4][4];
#pragma unroll
    for (int i = 0; i < 4; i++)
#pragma unroll
        for (int j = 0; j < 4; j++) {
            acc[i][j][0] = 0.f; acc[i][j][1] = 0.f;
            acc[i][j][2] = 0.f; acc[i][j][3] = 0.f;
        }

#pragma unroll
    for (int ch = 0; ch < 2; ch++) {
        uint32_t st = sbase + ch * STG;
        int k0 = ch * 32;
#pragma unroll
        for (int p = 0; p < 2; p++) {
            cp16(st +     0 + dsts[p], Ahi + gA[p] + k0);
            cp16(st +  8192 + dsts[p], Alo + gA[p] + k0);
            cp16(st + 16384 + dsts[p], Bhi + gB[p] + k0);
            cp16(st + 24576 + dsts[p], Blo + gB[p] + k0);
        }
        CP_COMMIT();
    }

    for (int c = 0; c < NCHUNK; c++) {
        if (c + 2 < NCHUNK) {
            int ch = c + 2;
            uint32_t st = sbase + (ch % 3) * STG;
            int k0 = ch * 32;
#pragma unroll
            for (int p = 0; p < 2; p++) {
                cp16(st +     0 + dsts[p], Ahi + gA[p] + k0);
                cp16(st +  8192 + dsts[p], Alo + gA[p] + k0);
                cp16(st + 16384 + dsts[p], Bhi + gB[p] + k0);
                cp16(st + 24576 + dsts[p], Blo + gB[p] + k0);
            }
            CP_COMMIT();
            CP_WAIT(2);
        } else if (c + 1 < NCHUNK) {
            CP_WAIT(1);
        } else {
            CP_WAIT(0);
        }
        __syncthreads();

        uint32_t st = sbase + (c % 3) * STG;
        uint32_t aHiB = st, aLoB = st + 8192, bHiB = st + 16384, bLoB = st + 24576;

#pragma unroll
        for (int ks = 0; ks < 2; ks++) {
            uint32_t ah[4][4], al[4][4], bh[2][4], bl[2][4];
#pragma unroll
            for (int mt = 0; mt < 4; mt++)
                LDSM4(ah[mt], aHiB + adr32(wm * 64 + mt * 16 + arow, 2 * ks + acb));
#pragma unroll
            for (int np = 0; np < 2; np++)
                LDSM4(bh[np], bHiB + adr32(wn * 32 + np * 16 + brow, 2 * ks + bcb));
#pragma unroll
            for (int mt = 0; mt < 4; mt++)
#pragma unroll
                for (int nt = 0; nt < 4; nt++)
                    MMA_BF(acc[mt][nt], ah[mt], bh[nt >> 1][(nt & 1) * 2],
                           bh[nt >> 1][(nt & 1) * 2 + 1]);
#pragma unroll
            for (int np = 0; np < 2; np++)
                LDSM4(bl[np], bLoB + adr32(wn * 32 + np * 16 + brow, 2 * ks + bcb));
#pragma unroll
            for (int mt = 0; mt < 4; mt++)
#pragma unroll
                for (int nt = 0; nt < 4; nt++)
                    MMA_BF(acc[mt][nt], ah[mt], bl[nt >> 1][(nt & 1) * 2],
                           bl[nt >> 1][(nt & 1) * 2 + 1]);
#pragma unroll
            for (int mt = 0; mt < 4; mt++)
                LDSM4(al[mt], aLoB + adr32(wm * 64 + mt * 16 + arow, 2 * ks + acb));
#pragma unroll
            for (int mt = 0; mt < 4; mt++)
#pragma unroll
                for (int nt = 0; nt < 4; nt++)
                    MMA_BF(acc[mt][nt], al[mt], bh[nt >> 1][(nt & 1) * 2],
                           bh[nt >> 1][(nt & 1) * 2 + 1]);
        }
        __syncthreads();
    }

    // fused epilogue via smem staging
    const float* bias = (n0 < 2048) ? bq + n0
                      : (n0 < 2560) ? bk + (n0 - 2048)
                                    : bv + (n0 - 2560);
    float* s = (float*)((((uintptr_t)dsm) + 1023) & ~(uintptr_t)1023);

#pragma unroll
    for (int mt = 0; mt < 4; mt++) {
        int rl = wm * 64 + mt * 16 + (lane >> 2);
#pragma unroll
        for (int nt = 0; nt < 4; nt++) {
            int cl = wn * 32 + nt * 8 + cbs;
            float bb0 = bias[cl], bb1 = bias[cl + 1];
            s[rl * PITCH + cl]           = acc[mt][nt][0] + bb0;
            s[rl * PITCH + cl + 1]       = acc[mt][nt][1] + bb1;
            s[(rl + 8) * PITCH + cl]     = acc[mt][nt][2] + bb0;
            s[(rl + 8) * PITCH + cl + 1] = acc[mt][nt][3] + bb1;
        }
    }
    __syncthreads();

    if (n0 < 2560) {
        const bool isQ = (n0 < 2048);
        const float qsc = isQ ? 0.08838834764831845f : 1.0f;
        const int hh = isQ ? (n0 >> 7) : ((n0 - 2048) >> 7);
        const int nh = isQ ? NHEAD : NGROUP;
        __nv_bfloat16* Hi = isQ ? qh : kh;
        __nv_bfloat16* Lo = isQ ? ql : kl;
#pragma unroll 4
        for (int idx = tid; idx < 128 * 32; idx += 256) {
            int r = idx >> 5, d2 = idx & 31;
            int m = m0 + r, t = m & (TSEQ - 1), b = m >> 11;
            int d0 = d2 * 2;
            float x1a = s[r * PITCH + d0],      x1b = s[r * PITCH + d0 + 1];
            float x2a = s[r * PITCH + d0 + 64], x2b = s[r * PITCH + d0 + 65];
            float2 ca = rope[t * 64 + d0], cb = rope[t * 64 + d0 + 1];
            float y1a = (x1a * ca.x - x2a * ca.y) * qsc;
            float y2a = (x1a * ca.y + x2a * ca.x) * qsc;
            float y1b = (x1b * cb.x - x2b * cb.y) * qsc;
            float y2b = (x1b * cb.y + x2b * cb.x) * qsc;
            size_t orow = ((size_t)(b * nh + hh) * TSEQ + t) * DHEAD;
            wr_hilo2(Hi + orow + d0,      Lo + orow + d0,      y1a, y1b);
            wr_hilo2(Hi + orow + 64 + d0, Lo + orow + 64 + d0, y2a, y2b);
        }
    } else {
        const int g = (n0 - 2560) >> 7;
#pragma unroll 4
        for (int idx = tid; idx < 128 * 64; idx += 256) {
            int r = idx >> 6, c2 = idx & 63;
            int m = m0 + r, t = m & (TSEQ - 1), b = m >> 11;
            int c0 = c2 * 2;
            size_t o = ((size_t)(b * NGROUP + g) * TSEQ + t) * DHEAD + c0;
            *(__half2*)(vh + o) =
                __floats2half2_rn(s[r * PITCH + c0], s[r * PITCH + c0 + 1]);
        }
    }
}

// ---------------------------------------------------------------------------
// Wo GEMM: 2-term fp16. C = A_fp16 @ (Bhi + Blo)^T + bias, fp32 out.
// ---------------------------------------------------------------------------
__global__ __launch_bounds__(256, 2) void gemm_wo(
    const __half* __restrict__ A,
    const __half* __restrict__ Bhi, const __half* __restrict__ Blo,
    const float* __restrict__ bias, float* __restrict__ C)
{
    constexpr int KD = 2048, NCHUNK = 64, STG = 24576;
    extern __shared__ char dsm[];
    uint32_t sbase = (cvta_s(dsm) + 1023) & ~1023u;

    const int tid = threadIdx.x;
    const int wid = tid >> 5, lane = tid & 31;
    const int wm = wid >> 2, wn = wid & 3;
    const int m0 = blockIdx.y * 128, n0 = blockIdx.x * 128;

    uint32_t dsts[2];
    size_t gA[2], gB[2];
#pragma unroll
    for (int p = 0; p < 2; p++) {
        int idx = tid + p * 256;
        int r = idx >> 2, c = idx & 3;
        dsts[p] = adr32(r, c);
        gA[p] = (size_t)(m0 + r) * KD + c * 8;
        gB[p] = (size_t)(n0 + r) * KD + c * 8;
    }

    const int arow = (lane & 7) + ((lane >> 3) & 1) * 8;
    const int acb  = lane >> 4;
    const int brow = (lane & 7) + (lane >> 4) * 8;
    const int bcb  = (lane >> 3) & 1;

    float acc[4][4][4];
#pragma unroll
    for (int i = 0; i < 4; i++)
#pragma unroll
        for (int j = 0; j < 4; j++) {
            acc[i][j][0] = 0.f; acc[i][j][1] = 0.f;
            acc[i][j][2] = 0.f; acc[i][j][3] = 0.f;
        }

#pragma unroll
    for (int ch = 0; ch < 2; ch++) {
        uint32_t st = sbase + ch * STG;
        int k0 = ch * 32;
#pragma unroll
        for (int p = 0; p < 2; p++) {
            cp16(st +     0 + dsts[p], A   + gA[p] + k0);
            cp16(st +  8192 + dsts[p], Bhi + gB[p] + k0);
            cp16(st + 16384 + dsts[p], Blo + gB[p] + k0);
        }
        CP_COMMIT();
    }

    for (int c = 0; c < NCHUNK; c++) {
        if (c + 2 < NCHUNK) {
            int ch = c + 2;
            uint32_t st = sbase + (ch % 3) * STG;
            int k0 = ch * 32;
#pragma unroll
            for (int p = 0; p < 2; p++) {
                cp16(st +     0 + dsts[p], A   + gA[p] + k0);
                cp16(st +  8192 + dsts[p], Bhi + gB[p] + k0);
                cp16(st + 16384 + dsts[p], Blo + gB[p] + k0);
            }
            CP_COMMIT();
            CP_WAIT(2);
        } else if (c + 1 < NCHUNK) {
            CP_WAIT(1);
        } else {
            CP_WAIT(0);
        }
        __syncthreads();

        uint32_t st = sbase + (c % 3) * STG;
        uint32_t aB = st, bHiB = st + 8192, bLoB = st + 16384;

#pragma unroll
        for (int ks = 0; ks < 2; ks++) {
            uint32_t ah[4][4], bh[2][4], bl[2][4];
#pragma unroll
            for (int mt = 0; mt < 4; mt++)
                LDSM4(ah[mt], aB + adr32(wm * 64 + mt * 16 + arow, 2 * ks + acb));
#pragma unroll
            for (int np = 0; np < 2; np++)
                LDSM4(bh[np], bHiB + adr32(wn * 32 + np * 16 + brow, 2 * ks + bcb));
#pragma unroll
            for (int mt = 0; mt < 4; mt++)
#pragma unroll
                for (int nt = 0; nt < 4; nt++)
                    MMA_H(acc[mt][nt], ah[mt], bh[nt >> 1][(nt & 1) * 2],
                          bh[nt >> 1][(nt & 1) * 2 + 1]);
#pragma unroll
            for (int np = 0; np < 2; np++)
                LDSM4(bl[np], bLoB + adr32(wn * 32 + np * 16 + brow, 2 * ks + bcb));
#pragma unroll
            for (int mt = 0; mt < 4; mt++)
#pragma unroll
                for (int nt = 0; nt < 4; nt++)
                    MMA_H(acc[mt][nt], ah[mt], bl[nt >> 1][(nt & 1) * 2],
                          bl[nt >> 1][(nt & 1) * 2 + 1]);
        }
        __syncthreads();
    }

#pragma unroll
    for (int mt = 0; mt < 4; mt++) {
        int r0 = m0 + wm * 64 + mt * 16 + (lane >> 2);
#pragma unroll
        for (int nt = 0; nt < 4; nt++) {
            int cc = n0 + wn * 32 + nt * 8 + (lane & 3) * 2;
            float bb0 = bias[cc], bb1 = bias[cc + 1];
            float2 v0 = make_float2(acc[mt][nt][0] + bb0, acc[mt][nt][1] + bb1);
            float2 v1 = make_float2(acc[mt][nt][2] + bb0, acc[mt][nt][3] + bb1);
            *(float2*)(C + (size_t)r0 * CEMB + cc) = v0;
            *(float2*)(C + (size_t)(r0 + 8) * CEMB + cc) = v1;
        }
    }
}

// ---------------------------------------------------------------------------
// flash attention: QK 3-term bf16 (unchanged), PV 2-term fp16 (P hi/lo, V single)
// output: fp16 single g_oh
// ---------------------------------------------------------------------------
__global__ __launch_bounds__(128, 2) void attn_mma(
    const __nv_bfloat16* __restrict__ qhi, const __nv_bfloat16* __restrict__ qlo,
    const __nv_bfloat16* __restrict__ khi, const __nv_bfloat16* __restrict__ klo,
    const __half* __restrict__ vh_g, __half* __restrict__ oh)
{
    extern __shared__ char sm[];
    uint32_t sb = (cvta_s(sm) + 1023) & ~1023u;
    const uint32_t sQh = sb, sQl = sb + 16384;
    const uint32_t sKV = sb + 32768;   // per stage (24576): Kh 0, Kl 8192, Vh 16384

    const int tid = threadIdx.x, w = tid >> 5, lane = tid & 31;
    const int b = blockIdx.y >> 4, h = blockIdx.y & 15, g = h >> 2;
    const int qs = blockIdx.x * 64;

    {
        size_t qb = ((size_t)(b * NHEAD + h) * TSEQ + qs) * DHEAD;
#pragma unroll
        for (int p = 0; p < 8; p++) {
            int idx = tid + p * 128;
            int row = idx >> 4, ch = idx & 15;
            uint32_t d = adr128(row, ch);
            size_t s = qb + (size_t)row * DHEAD + ch * 8;
            cp16(sQh + d, qhi + s);
            cp16(sQl + d, qlo + s);
        }
    }
    CP_COMMIT();

    int t0 = qs - SWIN; if (t0 < 0) t0 = 0;
    const int sink = (t0 > 0) ? 1 : 0;
    const int ntiles = sink + (qs + 64 - t0) / 32;
    const size_t kvbase = (size_t)(b * NGROUP + g) * TSEQ * DHEAD;

    {
        int ts = sink ? 0 : t0;
        size_t kb = kvbase + (size_t)ts * DHEAD;
#pragma unroll
        for (int p = 0; p < 4; p++) {
            int idx = tid + p * 128;
            int row = idx >> 4, ch = idx & 15;
            uint32_t d = adr128(row, ch);
            size_t s = kb + (size_t)row * DHEAD + ch * 8;
            cp16(sKV +     0 + d, khi + s);
            cp16(sKV +  8192 + d, klo + s);
            cp16(sKV + 16384 + d, vh_g + s);
        }
    }
    CP_COMMIT();

    const int arow = (lane & 7) + ((lane >> 3) & 1) * 8;
    const int acb  = lane >> 4;
    const int brow = (lane & 7) + (lane >> 4) * 8;
    const int bcb  = (lane >> 3) & 1;
    const int vr_i = ((lane >> 3) & 1) * 8 + (lane & 7);
    const int vc_i = lane >> 4;
    const int i0 = qs + w * 16 + (lane >> 2);
    const int i1 = i0 + 8;
    const int iwmax = qs + w * 16 + 15;
    const int cbs = (lane & 3) * 2;

    CP_WAIT(1);
    __syncthreads();
    uint32_t qh[8][4], ql[8][4];
#pragma unroll
    for (int kc = 0; kc < 8; kc++) {
        uint32_t off = adr128(w * 16 + arow, 2 * kc + acb);
        LDSM4(qh[kc], sQh + off);
        LDSM4(ql[kc], sQl + off);
    }

    float o[16][4];
#pragma unroll
    for (int i = 0; i < 16; i++) { o[i][0] = 0.f; o[i][1] = 0.f; o[i][2] = 0.f; o[i][3] = 0.f; }
    float m0 = -1e30f, m1 = -1e30f, l0 = 0.f, l1 = 0.f;

    for (int it = 0; it < ntiles; it++) {
        const bool snk = (sink && it == 0);
        const int ts = snk ? 0 : t0 + (it - sink) * 32;
        const int n2max = snk ? 1 : 2;

        if (it + 1 < ntiles) {
            int tsn = t0 + (it + 1 - sink) * 32;
            uint32_t st = sKV + ((it + 1) & 1) * 24576;
            size_t kb = kvbase + (size_t)tsn * DHEAD;
#pragma unroll
            for (int p = 0; p < 4; p++) {
                int idx = tid + p * 128;
                int row = idx >> 4, ch = idx & 15;
                uint32_t d = adr128(row, ch);
                size_t s = kb + (size_t)row * DHEAD + ch * 8;
                cp16(st +     0 + d, khi + s);
                cp16(st +  8192 + d, klo + s);
                cp16(st + 16384 + d, vh_g + s);
            }
            CP_COMMIT();
            CP_WAIT(1);
        } else {
            CP_WAIT(0);
        }
        __syncthreads();

        uint32_t stg = sKV + (it & 1) * 24576;
        uint32_t sKh = stg, sKl = stg + 8192, sVh = stg + 16384;

        float sc[4][4];
#pragma unroll
        for (int i = 0; i < 4; i++) { sc[i][0] = 0.f; sc[i][1] = 0.f; sc[i][2] = 0.f; sc[i][3] = 0.f; }

        for (int n2 = 0; n2 < n2max; n2++) {
            if (ts + n2 * 16 > iwmax) break;
#pragma unroll
            for (int kc = 0; kc < 8; kc++) {
                uint32_t off = adr128(n2 * 16 + brow, 2 * kc + bcb);
                uint32_t kh_[4], kl_[4];
                LDSM4(kh_, sKh + off);
                LDSM4(kl_, sKl + off);
                MMA_BF(sc[2 * n2],     qh[kc], kh_[0], kh_[1]);
                MMA_BF(sc[2 * n2],     qh[kc], kl_[0], kl_[1]);
                MMA_BF(sc[2 * n2],     ql[kc], kh_[0], kh_[1]);
                MMA_BF(sc[2 * n2 + 1], qh[kc], kh_[2], kh_[3]);
                MMA_BF(sc[2 * n2 + 1], qh[kc], kl_[2], kl_[3]);
                MMA_BF(sc[2 * n2 + 1], ql[kc], kh_[2], kh_[3]);
            }
        }

        float rm0 = -1e30f, rm1 = -1e30f;
#pragma unroll
        for (int nt = 0; nt < 4; nt++) {
            int j0 = ts + nt * 8 + cbs, j1 = j0 + 1;
            sc[nt][0] = (j0 <= i0 && (j0 >= i0 - SWIN || j0 < SINK)) ? sc[nt][0] : -1e30f;
            sc[nt][1] = (j1 <= i0 && (j1 >= i0 - SWIN || j1 < SINK)) ? sc[nt][1] : -1e30f;
            sc[nt][2] = (j0 <= i1 && (j0 >= i1 - SWIN || j0 < SINK)) ? sc[nt][2] : -1e30f;
            sc[nt][3] = (j1 <= i1 && (j1 >= i1 - SWIN || j1 < SINK)) ? sc[nt][3] : -1e30f;
            rm0 = fmaxf(rm0, fmaxf(sc[nt][0], sc[nt][1]));
            rm1 = fmaxf(rm1, fmaxf(sc[nt][2], sc[nt][3]));
        }
        rm0 = fmaxf(rm0, __shfl_xor_sync(0xffffffffu, rm0, 1));
        rm0 = fmaxf(rm0, __shfl_xor_sync(0xffffffffu, rm0, 2));
        rm1 = fmaxf(rm1, __shfl_xor_sync(0xffffffffu, rm1, 1));
        rm1 = fmaxf(rm1, __shfl_xor_sync(0xffffffffu, rm1, 2));
        float mn0 = fmaxf(m0, rm0), mn1 = fmaxf(m1, rm1);
        float c0 = __expf(m0 - mn0), c1 = __expf(m1 - mn1);
        m0 = mn0; m1 = mn1;

#pragma unroll
        for (int nd = 0; nd < 16; nd++) {
            o[nd][0] *= c0; o[nd][1] *= c0; o[nd][2] *= c1; o[nd][3] *= c1;
        }

        float rs0 = 0.f, rs1 = 0.f;
        for (int k2 = 0; k2 < n2max; k2++) {
            if (ts + k2 * 16 > iwmax) break;
            uint32_t aP[4], aPl[4];
#pragma unroll
            for (int q2 = 0; q2 < 2; q2++) {
                int nt = 2 * k2 + q2;
                float p00 = __expf(sc[nt][0] - mn0), p01 = __expf(sc[nt][1] - mn0);
                float p10 = __expf(sc[nt][2] - mn1), p11 = __expf(sc[nt][3] - mn1);
                rs0 += p00 + p01; rs1 += p10 + p11;
                __half2 h0v = __floats2half2_rn(p00, p01);
                __half2 h1v = __floats2half2_rn(p10, p11);
                __half2 l0v = __floats2half2_rn(p00 - __half2float(h0v.x),
                                                p01 - __half2float(h0v.y));
                __half2 l1v = __floats2half2_rn(p10 - __half2float(h1v.x),
                                                p11 - __half2float(h1v.y));
                aP[2 * q2]      = *(uint32_t*)&h0v;
                aP[2 * q2 + 1]  = *(uint32_t*)&h1v;
                aPl[2 * q2]     = *(uint32_t*)&l0v;
                aPl[2 * q2 + 1] = *(uint32_t*)&l1v;
            }
#pragma unroll
            for (int ndp = 0; ndp < 8; ndp++) {
                uint32_t voff = adr128(k2 * 16 + vr_i, ndp * 2 + vc_i);
                uint32_t bv[4];
                LDSM4T(bv, sVh + voff);
                MMA_H(o[ndp * 2],     aP,  bv[0], bv[1]);
                MMA_H(o[ndp * 2],     aPl, bv[0], bv[1]);
                MMA_H(o[ndp * 2 + 1], aP,  bv[2], bv[3]);
                MMA_H(o[ndp * 2 + 1], aPl, bv[2], bv[3]);
            }
        }
        rs0 += __shfl_xor_sync(0xffffffffu, rs0, 1);
        rs0 += __shfl_xor_sync(0xffffffffu, rs0, 2);
        rs1 += __shfl_xor_sync(0xffffffffu, rs1, 1);
        rs1 += __shfl_xor_sync(0xffffffffu, rs1, 2);
        l0 = l0 * c0 + rs0;
        l1 = l1 * c1 + rs1;

        __syncthreads();
    }

    float il0 = 1.f / l0, il1 = 1.f / l1;
    size_t or0 = (size_t)(b * TSEQ + qs + w * 16 + (lane >> 2)) * CEMB + h * DHEAD;
    size_t or1 = or0 + (size_t)8 * CEMB;
#pragma unroll
    for (int nd = 0; nd < 16; nd++) {
        int col = nd * 8 + cbs;
        *(__half2*)(oh + or0 + col) = __floats2half2_rn(o[nd][0] * il0, o[nd][1] * il0);
        *(__half2*)(oh + or1 + col) = __floats2half2_rn(o[nd][2] * il1, o[nd][3] * il1);
    }
}

// ---------------------------------------------------------------------------
extern "C" void kernel_launch(void* const* d_in, const int* in_sizes, int n_in,
                              void* d_out, int out_size)
{
    const float* x  = (const float*)d_in[0];
    const float* Wq = (const float*)d_in[1];
    const float* bq = (const float*)d_in[2];
    const float* Wk = (const float*)d_in[3];
    const float* bk = (const float*)d_in[4];
    const float* Wv = (const float*)d_in[5];
    const float* bv = (const float*)d_in[6];
    const float* Wo = (const float*)d_in[7];
    const float* bo = (const float*)d_in[8];
    float* out = (float*)d_out;

    __nv_bfloat16 *xhi, *xlo, *qhi, *qlo, *khi, *klo, *wth, *wtl;
    __half *vh, *oh, *woh, *wol;
    float2* rope;
    cudaGetSymbolAddress((void**)&xhi, g_xhi);
    cudaGetSymbolAddress((void**)&xlo, g_xlo);
    cudaGetSymbolAddress((void**)&qhi, g_qhi);
    cudaGetSymbolAddress((void**)&qlo, g_qlo);
    cudaGetSymbolAddress((void**)&khi, g_khi);
    cudaGetSymbolAddress((void**)&klo, g_klo);
    cudaGetSymbolAddress((void**)&vh,  g_vh);
    cudaGetSymbolAddress((void**)&oh,  g_oh);
    cudaGetSymbolAddress((void**)&wth, g_WT_hi);
    cudaGetSymbolAddress((void**)&wtl, g_WT_lo);
    cudaGetSymbolAddress((void**)&woh, g_WoT_h);
    cudaGetSymbolAddress((void**)&wol, g_WoT_l);
    cudaGetSymbolAddress((void**)&rope, g_rope);

    const int QKV_SMEM = 99328;
    cudaFuncSetAttribute(gemm_qkv, cudaFuncAttributeMaxDynamicSharedMemorySize, QKV_SMEM);
    const int WO_SMEM = 74752;
    cudaFuncSetAttribute(gemm_wo, cudaFuncAttributeMaxDynamicSharedMemorySize, WO_SMEM);
    const int ATTN_SMEM = 82944;
    cudaFuncSetAttribute(attn_mma, cudaFuncAttributeMaxDynamicSharedMemorySize, ATTN_SMEM);

    // (0) rope table  (1) x split  (2) QKV weights  (3) Wo weights
    rope_table<<<(TSEQ * 64) / 256, 256>>>(rope);
    {
        int n4 = (MROWS * CEMB) / 4;
        split_f32<<<(n4 + 255) / 256, 256>>>(x, xhi, xlo, n4);
    }
    tsplit_qkv<<<dim3(96, 64), dim3(32, 8)>>>(Wq, Wk, Wv, wth, wtl);
    tsplit_wo<<<dim3(64, 64), dim3(32, 8)>>>(Wo, woh, wol);

    // (4) fused QKV projection + rope + pack
    gemm_qkv<<<dim3(NQKV / 128, MROWS / 128), 256, QKV_SMEM>>>(
        xhi, xlo, wth, wtl, bq, bk, bv,
        qhi, qlo, khi, klo, vh, rope);

    // (5) flash attention  ← ncu -s 5 captures this
    attn_mma<<<dim3(TSEQ / 64, 2 * NHEAD), 128, ATTN_SMEM>>>(
        qhi, qlo, khi, klo, vh, oh);

    // (6) output projection (2-term fp16)
    gemm_wo<<<dim3(CEMB / 128, MROWS / 128), 256, WO_SMEM>>>(
        oh, woh, wol, bo, out);
}

// round 8
// speedup vs baseline: 1.4963x; 1.2738x over previous
#include <cuda_runtime.h>
#include <cuda_bf16.h>
#include <cuda_fp16.h>
#include <math.h>
#include <stdint.h>

// Problem constants
#define MROWS 4096   // B*T
#define CEMB  2048
#define TSEQ  2048
#define NHEAD 16
#define NGROUP 4
#define DHEAD 128
#define KVC   512
#define SWIN  512
#define SINK  4
#define NQKV  3072

// scratch (all fp16 now)
__device__ __half g_xh [(size_t)MROWS * CEMB];          // x fp16 single
__device__ __half g_oh [(size_t)MROWS * CEMB];          // attention out
__device__ __half g_qh [(size_t)MROWS * CEMB];          // [b,h,t,d] pre-scaled
__device__ __half g_kh [(size_t)MROWS * KVC];           // [b,g,t,d]
__device__ __half g_vh [(size_t)MROWS * KVC];
__device__ __half g_WT_h[(size_t)NQKV * CEMB];          // packed Wq|Wk|Wv, [N,K] hi
__device__ __half g_WT_l[(size_t)NQKV * CEMB];          // lo
__device__ __half g_WoT_h[(size_t)CEMB * CEMB];
__device__ __half g_WoT_l[(size_t)CEMB * CEMB];
__device__ float2 g_rope[(size_t)TSEQ * 64];

// ---------------------------------------------------------------------------
// helpers
// ---------------------------------------------------------------------------
__device__ __forceinline__ uint32_t cvta_s(const void* p) {
    return (uint32_t)__cvta_generic_to_shared(p);
}
__device__ __forceinline__ void cp16(uint32_t dst, const void* src) {
    asm volatile("cp.async.cg.shared.global [%0], [%1], 16;\n" :: "r"(dst), "l"(src));
}
#define CP_COMMIT() asm volatile("cp.async.commit_group;\n" ::: "memory")
#define CP_WAIT(n)  asm volatile("cp.async.wait_group %0;\n" :: "n"(n) : "memory")

#define LDSM4(r, addr) \
    asm volatile("ldmatrix.sync.aligned.m8n8.x4.shared.b16 {%0,%1,%2,%3}, [%4];" \
        : "=r"((r)[0]), "=r"((r)[1]), "=r"((r)[2]), "=r"((r)[3]) : "r"(addr))

#define LDSM4T(r, addr) \
    asm volatile("ldmatrix.sync.aligned.m8n8.x4.trans.shared.b16 {%0,%1,%2,%3}, [%4];" \
        : "=r"((r)[0]), "=r"((r)[1]), "=r"((r)[2]), "=r"((r)[3]) : "r"(addr))

#define MMA_H(c, a, b0, b1) \
    asm volatile("mma.sync.aligned.m16n8k16.row.col.f32.f16.f16.f32 " \
        "{%0,%1,%2,%3},{%4,%5,%6,%7},{%8,%9},{%0,%1,%2,%3};" \
        : "+f"((c)[0]), "+f"((c)[1]), "+f"((c)[2]), "+f"((c)[3]) \
        : "r"((a)[0]), "r"((a)[1]), "r"((a)[2]), "r"((a)[3]), "r"(b0), "r"(b1))

__device__ __forceinline__ uint32_t adr32(int r, int c4) {
    return (uint32_t)((r >> 1) * 128 + (((((r & 1) << 2) | c4) ^ ((r >> 1) & 7)) << 4));
}
__device__ __forceinline__ uint32_t adr128(int r, int c) {
    return (uint32_t)(r * 256 + ((c ^ (r & 7)) << 4));
}

// ---------------------------------------------------------------------------
// rope table
// ---------------------------------------------------------------------------
__global__ void rope_table(float2* tab)
{
    int i = blockIdx.x * blockDim.x + threadIdx.x;
    if (i >= TSEQ * 64) return;
    int d = i & 63, t = i >> 6;
    float inv = powf(10000.f, -(float)d * (1.f / 64.f));
    float s, c;
    sincosf((float)t * inv, &s, &c);
    tab[i] = make_float2(c, s);
}

// ---------------------------------------------------------------------------
// convert fp32 -> fp16 single
// ---------------------------------------------------------------------------
__global__ void conv_x(const float* __restrict__ s, __half* __restrict__ d, int n4)
{
    int i = blockIdx.x * blockDim.x + threadIdx.x;
    if (i >= n4) return;
    float4 v = ((const float4*)s)[i];
    __half2* p = (__half2*)d;
    p[i * 2 + 0] = __floats2half2_rn(v.x, v.y);
    p[i * 2 + 1] = __floats2half2_rn(v.z, v.w);
}

// ---------------------------------------------------------------------------
// transpose+split QKV weights -> fp16 hi/lo (packed rows)
// ---------------------------------------------------------------------------
__global__ void tsplit_qkv(const float* __restrict__ Wq,
                           const float* __restrict__ Wk,
                           const float* __restrict__ Wv,
                           __half* __restrict__ hi, __half* __restrict__ lo)
{
    __shared__ float t[32][33];
    int bx = blockIdx.x, k0 = blockIdx.y * 32;
    const float* W; int N, n0, ro;
    if (bx < 64)      { W = Wq; N = 2048; n0 = bx * 32;        ro = 0; }
    else if (bx < 80) { W = Wk; N = 512;  n0 = (bx - 64) * 32; ro = 2048; }
    else              { W = Wv; N = 512;  n0 = (bx - 80) * 32; ro = 2560; }
    int tx = threadIdx.x, ty = threadIdx.y;
#pragma unroll
    for (int i = 0; i < 4; i++)
        t[ty + 8 * i][tx] = W[(size_t)(k0 + ty + 8 * i) * N + n0 + tx];
    __syncthreads();
#pragma unroll
    for (int i = 0; i < 4; i++) {
        float v = t[tx][ty + 8 * i];
        __half h = __float2half_rn(v);
        size_t off = (size_t)(ro + n0 + ty + 8 * i) * CEMB + k0 + tx;
        hi[off] = h;
        lo[off] = __float2half_rn(v - __half2float(h));
    }
}

// ---------------------------------------------------------------------------
// transpose+split Wo -> fp16 hi/lo
// ---------------------------------------------------------------------------
__global__ void tsplit_wo(const float* __restrict__ W,
                          __half* __restrict__ hi, __half* __restrict__ lo)
{
    __shared__ float t[32][33];
    int n0 = blockIdx.x * 32, k0 = blockIdx.y * 32;
    int tx = threadIdx.x, ty = threadIdx.y;
#pragma unroll
    for (int i = 0; i < 4; i++)
        t[ty + 8 * i][tx] = W[(size_t)(k0 + ty + 8 * i) * CEMB + n0 + tx];
    __syncthreads();
#pragma unroll
    for (int i = 0; i < 4; i++) {
        float v = t[tx][ty + 8 * i];
        __half h = __float2half_rn(v);
        size_t off = (size_t)(n0 + ty + 8 * i) * CEMB + k0 + tx;
        hi[off] = h;
        lo[off] = __float2half_rn(v - __half2float(h));
    }
}

// ---------------------------------------------------------------------------
// QKV GEMM: 2-term fp16. acc = x_fp16 @ (Whi + Wlo)^T, fp32 accum.
// Fused epilogue: bias + rope + pack to fp16 q/k/v.
// ---------------------------------------------------------------------------
__global__ __launch_bounds__(256, 2) void gemm_qkv(
    const __half* __restrict__ A,
    const __half* __restrict__ Bhi, const __half* __restrict__ Blo,
    const float* __restrict__ bq, const float* __restrict__ bk,
    const float* __restrict__ bv,
    __half* __restrict__ qh, __half* __restrict__ kh, __half* __restrict__ vh,
    const float2* __restrict__ rope)
{
    constexpr int KD = 2048, NCHUNK = 64, STG = 24576, PITCH = 132;
    extern __shared__ char dsm[];
    uint32_t sbase = (cvta_s(dsm) + 1023) & ~1023u;

    const int tid = threadIdx.x;
    const int wid = tid >> 5, lane = tid & 31;
    const int wm = wid >> 2, wn = wid & 3;
    const int m0 = blockIdx.y * 128, n0 = blockIdx.x * 128;

    uint32_t dsts[2];
    size_t gA[2], gB[2];
#pragma unroll
    for (int p = 0; p < 2; p++) {
        int idx = tid + p * 256;
        int r = idx >> 2, c = idx & 3;
        dsts[p] = adr32(r, c);
        gA[p] = (size_t)(m0 + r) * KD + c * 8;
        gB[p] = (size_t)(n0 + r) * KD + c * 8;
    }

    const int arow = (lane & 7) + ((lane >> 3) & 1) * 8;
    const int acb  = lane >> 4;
    const int brow = (lane & 7) + (lane >> 4) * 8;
    const int bcb  = (lane >> 3) & 1;
    const int cbs  = (lane & 3) * 2;

    float acc[4][4][4];
#pragma unroll
    for (int i = 0; i < 4; i++)
#pragma unroll
        for (int j = 0; j < 4; j++) {
            acc[i][j][0] = 0.f; acc[i][j][1] = 0.f;
            acc[i][j][2] = 0.f; acc[i][j][3] = 0.f;
        }

#pragma unroll
    for (int ch = 0; ch < 2; ch++) {
        uint32_t st = sbase + ch * STG;
        int k0 = ch * 32;
#pragma unroll
        for (int p = 0; p < 2; p++) {
            cp16(st +     0 + dsts[p], A   + gA[p] + k0);
            cp16(st +  8192 + dsts[p], Bhi + gB[p] + k0);
            cp16(st + 16384 + dsts[p], Blo + gB[p] + k0);
        }
        CP_COMMIT();
    }

    for (int c = 0; c < NCHUNK; c++) {
        if (c + 2 < NCHUNK) {
            int ch = c + 2;
            uint32_t st = sbase + (ch % 3) * STG;
            int k0 = ch * 32;
#pragma unroll
            for (int p = 0; p < 2; p++) {
                cp16(st +     0 + dsts[p], A   + gA[p] + k0);
                cp16(st +  8192 + dsts[p], Bhi + gB[p] + k0);
                cp16(st + 16384 + dsts[p], Blo + gB[p] + k0);
            }
            CP_COMMIT();
            CP_WAIT(2);
        } else if (c + 1 < NCHUNK) {
            CP_WAIT(1);
        } else {
            CP_WAIT(0);
        }
        __syncthreads();

        uint32_t st = sbase + (c % 3) * STG;
        uint32_t aB = st, bHiB = st + 8192, bLoB = st + 16384;

#pragma unroll
        for (int ks = 0; ks < 2; ks++) {
            uint32_t ah[4][4], bh[2][4], bl[2][4];
#pragma unroll
            for (int mt = 0; mt < 4; mt++)
                LDSM4(ah[mt], aB + adr32(wm * 64 + mt * 16 + arow, 2 * ks + acb));
#pragma unroll
            for (int np = 0; np < 2; np++)
                LDSM4(bh[np], bHiB + adr32(wn * 32 + np * 16 + brow, 2 * ks + bcb));
#pragma unroll
            for (int mt = 0; mt < 4; mt++)
#pragma unroll
                for (int nt = 0; nt < 4; nt++)
                    MMA_H(acc[mt][nt], ah[mt], bh[nt >> 1][(nt & 1) * 2],
                          bh[nt >> 1][(nt & 1) * 2 + 1]);
#pragma unroll
            for (int np = 0; np < 2; np++)
                LDSM4(bl[np], bLoB + adr32(wn * 32 + np * 16 + brow, 2 * ks + bcb));
#pragma unroll
            for (int mt = 0; mt < 4; mt++)
#pragma unroll
                for (int nt = 0; nt < 4; nt++)
                    MMA_H(acc[mt][nt], ah[mt], bl[nt >> 1][(nt & 1) * 2],
                          bl[nt >> 1][(nt & 1) * 2 + 1]);
        }
        __syncthreads();
    }

    // fused epilogue via smem fp32 staging
    const float* bias = (n0 < 2048) ? bq + n0
                      : (n0 < 2560) ? bk + (n0 - 2048)
                                    : bv + (n0 - 2560);
    float* s = (float*)((((uintptr_t)dsm) + 1023) & ~(uintptr_t)1023);

#pragma unroll
    for (int mt = 0; mt < 4; mt++) {
        int rl = wm * 64 + mt * 16 + (lane >> 2);
#pragma unroll
        for (int nt = 0; nt < 4; nt++) {
            int cl = wn * 32 + nt * 8 + cbs;
            float bb0 = bias[cl], bb1 = bias[cl + 1];
            s[rl * PITCH + cl]           = acc[mt][nt][0] + bb0;
            s[rl * PITCH + cl + 1]       = acc[mt][nt][1] + bb1;
            s[(rl + 8) * PITCH + cl]     = acc[mt][nt][2] + bb0;
            s[(rl + 8) * PITCH + cl + 1] = acc[mt][nt][3] + bb1;
        }
    }
    __syncthreads();

    if (n0 < 2560) {
        const bool isQ = (n0 < 2048);
        const float qsc = isQ ? 0.08838834764831845f : 1.0f;
        const int hh = isQ ? (n0 >> 7) : ((n0 - 2048) >> 7);
        const int nh = isQ ? NHEAD : NGROUP;
        __half* Out = isQ ? qh : kh;
#pragma unroll 4
        for (int idx = tid; idx < 128 * 32; idx += 256) {
            int r = idx >> 5, d2 = idx & 31;
            int m = m0 + r, t = m & (TSEQ - 1), b = m >> 11;
            int d0 = d2 * 2;
            float x1a = s[r * PITCH + d0],      x1b = s[r * PITCH + d0 + 1];
            float x2a = s[r * PITCH + d0 + 64], x2b = s[r * PITCH + d0 + 65];
            float2 ca = rope[t * 64 + d0], cb = rope[t * 64 + d0 + 1];
            float y1a = (x1a * ca.x - x2a * ca.y) * qsc;
            float y2a = (x1a * ca.y + x2a * ca.x) * qsc;
            float y1b = (x1b * cb.x - x2b * cb.y) * qsc;
            float y2b = (x1b * cb.y + x2b * cb.x) * qsc;
            size_t orow = ((size_t)(b * nh + hh) * TSEQ + t) * DHEAD;
            *(__half2*)(Out + orow + d0)      = __floats2half2_rn(y1a, y1b);
            *(__half2*)(Out + orow + 64 + d0) = __floats2half2_rn(y2a, y2b);
        }
    } else {
        const int g = (n0 - 2560) >> 7;
#pragma unroll 4
        for (int idx = tid; idx < 128 * 64; idx += 256) {
            int r = idx >> 6, c2 = idx & 63;
            int m = m0 + r, t = m & (TSEQ - 1), b = m >> 11;
            int c0 = c2 * 2;
            size_t o = ((size_t)(b * NGROUP + g) * TSEQ + t) * DHEAD + c0;
            *(__half2*)(vh + o) =
                __floats2half2_rn(s[r * PITCH + c0], s[r * PITCH + c0 + 1]);
        }
    }
}

// ---------------------------------------------------------------------------
// Wo GEMM: 2-term fp16 (unchanged from R7)
// ---------------------------------------------------------------------------
__global__ __launch_bounds__(256, 2) void gemm_wo(
    const __half* __restrict__ A,
    const __half* __restrict__ Bhi, const __half* __restrict__ Blo,
    const float* __restrict__ bias, float* __restrict__ C)
{
    constexpr int KD = 2048, NCHUNK = 64, STG = 24576;
    extern __shared__ char dsm[];
    uint32_t sbase = (cvta_s(dsm) + 1023) & ~1023u;

    const int tid = threadIdx.x;
    const int wid = tid >> 5, lane = tid & 31;
    const int wm = wid >> 2, wn = wid & 3;
    const int m0 = blockIdx.y * 128, n0 = blockIdx.x * 128;

    uint32_t dsts[2];
    size_t gA[2], gB[2];
#pragma unroll
    for (int p = 0; p < 2; p++) {
        int idx = tid + p * 256;
        int r = idx >> 2, c = idx & 3;
        dsts[p] = adr32(r, c);
        gA[p] = (size_t)(m0 + r) * KD + c * 8;
        gB[p] = (size_t)(n0 + r) * KD + c * 8;
    }

    const int arow = (lane & 7) + ((lane >> 3) & 1) * 8;
    const int acb  = lane >> 4;
    const int brow = (lane & 7) + (lane >> 4) * 8;
    const int bcb  = (lane >> 3) & 1;

    float acc[4][4][4];
#pragma unroll
    for (int i = 0; i < 4; i++)
#pragma unroll
        for (int j = 0; j < 4; j++) {
            acc[i][j][0] = 0.f; acc[i][j][1] = 0.f;
            acc[i][j][2] = 0.f; acc[i][j][3] = 0.f;
        }

#pragma unroll
    for (int ch = 0; ch < 2; ch++) {
        uint32_t st = sbase + ch * STG;
        int k0 = ch * 32;
#pragma unroll
        for (int p = 0; p < 2; p++) {
            cp16(st +     0 + dsts[p], A   + gA[p] + k0);
            cp16(st +  8192 + dsts[p], Bhi + gB[p] + k0);
            cp16(st + 16384 + dsts[p], Blo + gB[p] + k0);
        }
        CP_COMMIT();
    }

    for (int c = 0; c < NCHUNK; c++) {
        if (c + 2 < NCHUNK) {
            int ch = c + 2;
            uint32_t st = sbase + (ch % 3) * STG;
            int k0 = ch * 32;
#pragma unroll
            for (int p = 0; p < 2; p++) {
                cp16(st +     0 + dsts[p], A   + gA[p] + k0);
                cp16(st +  8192 + dsts[p], Bhi + gB[p] + k0);
                cp16(st + 16384 + dsts[p], Blo + gB[p] + k0);
            }
            CP_COMMIT();
            CP_WAIT(2);
        } else if (c + 1 < NCHUNK) {
            CP_WAIT(1);
        } else {
            CP_WAIT(0);
        }
        __syncthreads();

        uint32_t st = sbase + (c % 3) * STG;
        uint32_t aB = st, bHiB = st + 8192, bLoB = st + 16384;

#pragma unroll
        for (int ks = 0; ks < 2; ks++) {
            uint32_t ah[4][4], bh[2][4], bl[2][4];
#pragma unroll
            for (int mt = 0; mt < 4; mt++)
                LDSM4(ah[mt], aB + adr32(wm * 64 + mt * 16 + arow, 2 * ks + acb));
#pragma unroll
            for (int np = 0; np < 2; np++)
                LDSM4(bh[np], bHiB + adr32(wn * 32 + np * 16 + brow, 2 * ks + bcb));
#pragma unroll
            for (int mt = 0; mt < 4; mt++)
#pragma unroll
                for (int nt = 0; nt < 4; nt++)
                    MMA_H(acc[mt][nt], ah[mt], bh[nt >> 1][(nt & 1) * 2],
                          bh[nt >> 1][(nt & 1) * 2 + 1]);
#pragma unroll
            for (int np = 0; np < 2; np++)
                LDSM4(bl[np], bLoB + adr32(wn * 32 + np * 16 + brow, 2 * ks + bcb));
#pragma unroll
            for (int mt = 0; mt < 4; mt++)
#pragma unroll
                for (int nt = 0; nt < 4; nt++)
                    MMA_H(acc[mt][nt], ah[mt], bl[nt >> 1][(nt & 1) * 2],
                          bl[nt >> 1][(nt & 1) * 2 + 1]);
        }
        __syncthreads();
    }

#pragma unroll
    for (int mt = 0; mt < 4; mt++) {
        int r0 = m0 + wm * 64 + mt * 16 + (lane >> 2);
#pragma unroll
        for (int nt = 0; nt < 4; nt++) {
            int cc = n0 + wn * 32 + nt * 8 + (lane & 3) * 2;
            float bb0 = bias[cc], bb1 = bias[cc + 1];
            float2 v0 = make_float2(acc[mt][nt][0] + bb0, acc[mt][nt][1] + bb1);
            float2 v1 = make_float2(acc[mt][nt][2] + bb0, acc[mt][nt][3] + bb1);
            *(float2*)(C + (size_t)r0 * CEMB + cc) = v0;
            *(float2*)(C + (size_t)(r0 + 8) * CEMB + cc) = v1;
        }
    }
}

// ---------------------------------------------------------------------------
// flash attention: all fp16 single. QK 1 MMA, PV 1 MMA.
// ---------------------------------------------------------------------------
__global__ __launch_bounds__(128, 2) void attn_mma(
    const __half* __restrict__ qh_g, const __half* __restrict__ kh_g,
    const __half* __restrict__ vh_g, __half* __restrict__ oh)
{
    extern __shared__ char sm[];
    uint32_t sb = (cvta_s(sm) + 1023) & ~1023u;
    const uint32_t sQ  = sb;
    const uint32_t sKV = sb + 16384;   // per stage (16384): K 0, V 8192

    const int tid = threadIdx.x, w = tid >> 5, lane = tid & 31;
    const int b = blockIdx.y >> 4, h = blockIdx.y & 15, g = h >> 2;
    const int qs = blockIdx.x * 64;

    {
        size_t qb = ((size_t)(b * NHEAD + h) * TSEQ + qs) * DHEAD;
#pragma unroll
        for (int p = 0; p < 8; p++) {
            int idx = tid + p * 128;
            int row = idx >> 4, ch = idx & 15;
            cp16(sQ + adr128(row, ch), qh_g + qb + (size_t)row * DHEAD + ch * 8);
        }
    }
    CP_COMMIT();

    int t0 = qs - SWIN; if (t0 < 0) t0 = 0;
    const int sink = (t0 > 0) ? 1 : 0;
    const int ntiles = sink + (qs + 64 - t0) / 32;
    const size_t kvbase = (size_t)(b * NGROUP + g) * TSEQ * DHEAD;

    {
        int ts = sink ? 0 : t0;
        size_t kb = kvbase + (size_t)ts * DHEAD;
#pragma unroll
        for (int p = 0; p < 4; p++) {
            int idx = tid + p * 128;
            int row = idx >> 4, ch = idx & 15;
            uint32_t d = adr128(row, ch);
            size_t s = kb + (size_t)row * DHEAD + ch * 8;
            cp16(sKV +    0 + d, kh_g + s);
            cp16(sKV + 8192 + d, vh_g + s);
        }
    }
    CP_COMMIT();

    const int arow = (lane & 7) + ((lane >> 3) & 1) * 8;
    const int acb  = lane >> 4;
    const int brow = (lane & 7) + (lane >> 4) * 8;
    const int bcb  = (lane >> 3) & 1;
    const int vr_i = ((lane >> 3) & 1) * 8 + (lane & 7);
    const int vc_i = lane >> 4;
    const int i0 = qs + w * 16 + (lane >> 2);
    const int i1 = i0 + 8;
    const int iwmax = qs + w * 16 + 15;
    const int cbs = (lane & 3) * 2;

    CP_WAIT(1);
    __syncthreads();
    uint32_t qf[8][4];
#pragma unroll
    for (int kc = 0; kc < 8; kc++)
        LDSM4(qf[kc], sQ + adr128(w * 16 + arow, 2 * kc + acb));

    float o[16][4];
#pragma unroll
    for (int i = 0; i < 16; i++) { o[i][0] = 0.f; o[i][1] = 0.f; o[i][2] = 0.f; o[i][3] = 0.f; }
    float m0 = -1e30f, m1 = -1e30f, l0 = 0.f, l1 = 0.f;

    for (int it = 0; it < ntiles; it++) {
        const bool snk = (sink && it == 0);
        const int ts = snk ? 0 : t0 + (it - sink) * 32;
        const int n2max = snk ? 1 : 2;

        if (it + 1 < ntiles) {
            int tsn = t0 + (it + 1 - sink) * 32;
            uint32_t st = sKV + ((it + 1) & 1) * 16384;
            size_t kb = kvbase + (size_t)tsn * DHEAD;
#pragma unroll
            for (int p = 0; p < 4; p++) {
                int idx = tid + p * 128;
                int row = idx >> 4, ch = idx & 15;
                uint32_t d = adr128(row, ch);
                size_t s = kb + (size_t)row * DHEAD + ch * 8;
                cp16(st +    0 + d, kh_g + s);
                cp16(st + 8192 + d, vh_g + s);
            }
            CP_COMMIT();
            CP_WAIT(1);
        } else {
            CP_WAIT(0);
        }
        __syncthreads();

        uint32_t stg = sKV + (it & 1) * 16384;
        uint32_t sK = stg, sV = stg + 8192;

        float sc[4][4];
#pragma unroll
        for (int i = 0; i < 4; i++) { sc[i][0] = 0.f; sc[i][1] = 0.f; sc[i][2] = 0.f; sc[i][3] = 0.f; }

        for (int n2 = 0; n2 < n2max; n2++) {
            if (ts + n2 * 16 > iwmax) break;
#pragma unroll
            for (int kc = 0; kc < 8; kc++) {
                uint32_t kf[4];
                LDSM4(kf, sK + adr128(n2 * 16 + brow, 2 * kc + bcb));
                MMA_H(sc[2 * n2],     qf[kc], kf[0], kf[1]);
                MMA_H(sc[2 * n2 + 1], qf[kc], kf[2], kf[3]);
            }
        }

        float rm0 = -1e30f, rm1 = -1e30f;
#pragma unroll
        for (int nt = 0; nt < 4; nt++) {
            int j0 = ts + nt * 8 + cbs, j1 = j0 + 1;
            sc[nt][0] = (j0 <= i0 && (j0 >= i0 - SWIN || j0 < SINK)) ? sc[nt][0] : -1e30f;
            sc[nt][1] = (j1 <= i0 && (j1 >= i0 - SWIN || j1 < SINK)) ? sc[nt][1] : -1e30f;
            sc[nt][2] = (j0 <= i1 && (j0 >= i1 - SWIN || j0 < SINK)) ? sc[nt][2] : -1e30f;
            sc[nt][3] = (j1 <= i1 && (j1 >= i1 - SWIN || j1 < SINK)) ? sc[nt][3] : -1e30f;
            rm0 = fmaxf(rm0, fmaxf(sc[nt][0], sc[nt][1]));
            rm1 = fmaxf(rm1, fmaxf(sc[nt][2], sc[nt][3]));
        }
        rm0 = fmaxf(rm0, __shfl_xor_sync(0xffffffffu, rm0, 1));
        rm0 = fmaxf(rm0, __shfl_xor_sync(0xffffffffu, rm0, 2));
        rm1 = fmaxf(rm1, __shfl_xor_sync(0xffffffffu, rm1, 1));
        rm1 = fmaxf(rm1, __shfl_xor_sync(0xffffffffu, rm1, 2));
        float mn0 = fmaxf(m0, rm0), mn1 = fmaxf(m1, rm1);
        float c0 = __expf(m0 - mn0), c1 = __expf(m1 - mn1);
        m0 = mn0; m1 = mn1;

#pragma unroll
        for (int nd = 0; nd < 16; nd++) {
            o[nd][0] *= c0; o[nd][1] *= c0; o[nd][2] *= c1; o[nd][3] *= c1;
        }

        float rs0 = 0.f, rs1 = 0.f;
        for (int k2 = 0; k2 < n2max; k2++) {
            if (ts + k2 * 16 > iwmax) break;
            uint32_t aP[4];
#pragma unroll
            for (int q2 = 0; q2 < 2; q2++) {
                int nt = 2 * k2 + q2;
                float p00 = __expf(sc[nt][0] - mn0), p01 = __expf(sc[nt][1] - mn0);
                float p10 = __expf(sc[nt][2] - mn1), p11 = __expf(sc[nt][3] - mn1);
                rs0 += p00 + p01; rs1 += p10 + p11;
                __half2 h0v = __floats2half2_rn(p00, p01);
                __half2 h1v = __floats2half2_rn(p10, p11);
                aP[2 * q2]     = *(uint32_t*)&h0v;
                aP[2 * q2 + 1] = *(uint32_t*)&h1v;
            }
#pragma unroll
            for (int ndp = 0; ndp < 8; ndp++) {
                uint32_t bv[4];
                LDSM4T(bv, sV + adr128(k2 * 16 + vr_i, ndp * 2 + vc_i));
                MMA_H(o[ndp * 2],     aP, bv[0], bv[1]);
                MMA_H(o[ndp * 2 + 1], aP, bv[2], bv[3]);
            }
        }
        rs0 += __shfl_xor_sync(0xffffffffu, rs0, 1);
        rs0 += __shfl_xor_sync(0xffffffffu, rs0, 2);
        rs1 += __shfl_xor_sync(0xffffffffu, rs1, 1);
        rs1 += __shfl_xor_sync(0xffffffffu, rs1, 2);
        l0 = l0 * c0 + rs0;
        l1 = l1 * c1 + rs1;

        __syncthreads();
    }

    float il0 = 1.f / l0, il1 = 1.f / l1;
    size_t or0 = (size_t)(b * TSEQ + qs + w * 16 + (lane >> 2)) * CEMB + h * DHEAD;
    size_t or1 = or0 + (size_t)8 * CEMB;
#pragma unroll
    for (int nd = 0; nd < 16; nd++) {
        int col = nd * 8 + cbs;
        *(__half2*)(oh + or0 + col) = __floats2half2_rn(o[nd][0] * il0, o[nd][1] * il0);
        *(__half2*)(oh + or1 + col) = __floats2half2_rn(o[nd][2] * il1, o[nd][3] * il1);
    }
}

// ---------------------------------------------------------------------------
extern "C" void kernel_launch(void* const* d_in, const int* in_sizes, int n_in,
                              void* d_out, int out_size)
{
    const float* x  = (const float*)d_in[0];
    const float* Wq = (const float*)d_in[1];
    const float* bq = (const float*)d_in[2];
    const float* Wk = (const float*)d_in[3];
    const float* bk = (const float*)d_in[4];
    const float* Wv = (const float*)d_in[5];
    const float* bv = (const float*)d_in[6];
    const float* Wo = (const float*)d_in[7];
    const float* bo = (const float*)d_in[8];
    float* out = (float*)d_out;

    __half *xh, *qh, *kh, *vh, *oh, *wth, *wtl, *woh, *wol;
    float2* rope;
    cudaGetSymbolAddress((void**)&xh,  g_xh);
    cudaGetSymbolAddress((void**)&qh,  g_qh);
    cudaGetSymbolAddress((void**)&kh,  g_kh);
    cudaGetSymbolAddress((void**)&vh,  g_vh);
    cudaGetSymbolAddress((void**)&oh,  g_oh);
    cudaGetSymbolAddress((void**)&wth, g_WT_h);
    cudaGetSymbolAddress((void**)&wtl, g_WT_l);
    cudaGetSymbolAddress((void**)&woh, g_WoT_h);
    cudaGetSymbolAddress((void**)&wol, g_WoT_l);
    cudaGetSymbolAddress((void**)&rope, g_rope);

    const int QKV_SMEM = 74752;   // 3*24KB + align, reused as 128x132 fp32 staging
    cudaFuncSetAttribute(gemm_qkv, cudaFuncAttributeMaxDynamicSharedMemorySize, QKV_SMEM);
    const int WO_SMEM = 74752;
    cudaFuncSetAttribute(gemm_wo, cudaFuncAttributeMaxDynamicSharedMemorySize, WO_SMEM);
    const int ATTN_SMEM = 50176;  // 16KB Q + 2*16KB KV + align
    cudaFuncSetAttribute(attn_mma, cudaFuncAttributeMaxDynamicSharedMemorySize, ATTN_SMEM);

    // (0) rope table  (1) x convert  (2) QKV weights  (3) Wo weights
    rope_table<<<(TSEQ * 64) / 256, 256>>>(rope);
    {
        int n4 = (MROWS * CEMB) / 4;
        conv_x<<<(n4 + 255) / 256, 256>>>(x, xh, n4);
    }
    tsplit_qkv<<<dim3(96, 64), dim3(32, 8)>>>(Wq, Wk, Wv, wth, wtl);
    tsplit_wo<<<dim3(64, 64), dim3(32, 8)>>>(Wo, woh, wol);

    // (4) fused QKV projection + rope + pack (2-term fp16)
    gemm_qkv<<<dim3(NQKV / 128, MROWS / 128), 256, QKV_SMEM>>>(
        xh, wth, wtl, bq, bk, bv, qh, kh, vh, rope);

    // (5) flash attention (all fp16)  ← ncu -s 5 captures this
    attn_mma<<<dim3(TSEQ / 64, 2 * NHEAD), 128, ATTN_SMEM>>>(qh, kh, vh, oh);

    // (6) output projection (2-term fp16)
    gemm_wo<<<dim3(CEMB / 128, MROWS / 128), 256, WO_SMEM>>>(oh, woh, wol, bo, out);
}

// round 9
// speedup vs baseline: 2.2894x; 1.5300x over previous
#include <cuda_runtime.h>
#include <cuda_fp16.h>
#include <math.h>
#include <stdint.h>

// Problem constants
#define MROWS 4096   // B*T
#define CEMB  2048
#define TSEQ  2048
#define NHEAD 16
#define NGROUP 4
#define DHEAD 128
#define KVC   512
#define SWIN  512
#define SINK  4
#define NQKV  3072

// scratch (all fp16)
__device__ __half g_xh [(size_t)MROWS * CEMB];
__device__ __half g_oh [(size_t)MROWS * CEMB];
__device__ __half g_qh [(size_t)MROWS * CEMB];          // [b,h,t,d] pre-scaled
__device__ __half g_kh [(size_t)MROWS * KVC];           // [b,g,t,d]
__device__ __half g_vh [(size_t)MROWS * KVC];
__device__ __half g_WT [(size_t)NQKV * CEMB];           // packed Wq|Wk|Wv, [N,K]
__device__ __half g_WoT[(size_t)CEMB * CEMB];
__device__ float2 g_rope[(size_t)TSEQ * 64];

// ---------------------------------------------------------------------------
// helpers
// ---------------------------------------------------------------------------
__device__ __forceinline__ uint32_t cvta_s(const void* p) {
    return (uint32_t)__cvta_generic_to_shared(p);
}
__device__ __forceinline__ void cp16(uint32_t dst, const void* src) {
    asm volatile("cp.async.cg.shared.global [%0], [%1], 16;\n" :: "r"(dst), "l"(src));
}
#define CP_COMMIT() asm volatile("cp.async.commit_group;\n" ::: "memory")
#define CP_WAIT(n)  asm volatile("cp.async.wait_group %0;\n" :: "n"(n) : "memory")

#define LDSM4(r, addr) \
    asm volatile("ldmatrix.sync.aligned.m8n8.x4.shared.b16 {%0,%1,%2,%3}, [%4];" \
        : "=r"((r)[0]), "=r"((r)[1]), "=r"((r)[2]), "=r"((r)[3]) : "r"(addr))

#define LDSM4T(r, addr) \
    asm volatile("ldmatrix.sync.aligned.m8n8.x4.trans.shared.b16 {%0,%1,%2,%3}, [%4];" \
        : "=r"((r)[0]), "=r"((r)[1]), "=r"((r)[2]), "=r"((r)[3]) : "r"(addr))

#define MMA_H(c, a, b0, b1) \
    asm volatile("mma.sync.aligned.m16n8k16.row.col.f32.f16.f16.f32 " \
        "{%0,%1,%2,%3},{%4,%5,%6,%7},{%8,%9},{%0,%1,%2,%3};" \
        : "+f"((c)[0]), "+f"((c)[1]), "+f"((c)[2]), "+f"((c)[3]) \
        : "r"((a)[0]), "r"((a)[1]), "r"((a)[2]), "r"((a)[3]), "r"(b0), "r"(b1))

__device__ __forceinline__ uint32_t adr32(int r, int c4) {
    return (uint32_t)((r >> 1) * 128 + (((((r & 1) << 2) | c4) ^ ((r >> 1) & 7)) << 4));
}
__device__ __forceinline__ uint32_t adr128(int r, int c) {
    return (uint32_t)(r * 256 + ((c ^ (r & 7)) << 4));
}

// ---------------------------------------------------------------------------
// rope table
// ---------------------------------------------------------------------------
__global__ void rope_table(float2* tab)
{
    int i = blockIdx.x * blockDim.x + threadIdx.x;
    if (i >= TSEQ * 64) return;
    int d = i & 63, t = i >> 6;
    float inv = powf(10000.f, -(float)d * (1.f / 64.f));
    float s, c;
    sincosf((float)t * inv, &s, &c);
    tab[i] = make_float2(c, s);
}

// ---------------------------------------------------------------------------
// convert fp32 -> fp16 single
// ---------------------------------------------------------------------------
__global__ void conv_x(const float* __restrict__ s, __half* __restrict__ d, int n4)
{
    int i = blockIdx.x * blockDim.x + threadIdx.x;
    if (i >= n4) return;
    float4 v = ((const float4*)s)[i];
    __half2* p = (__half2*)d;
    p[i * 2 + 0] = __floats2half2_rn(v.x, v.y);
    p[i * 2 + 1] = __floats2half2_rn(v.z, v.w);
}

// ---------------------------------------------------------------------------
// transpose QKV weights -> fp16 single (packed rows)
// ---------------------------------------------------------------------------
__global__ void tsplit_qkv(const float* __restrict__ Wq,
                           const float* __restrict__ Wk,
                           const float* __restrict__ Wv,
                           __half* __restrict__ hi)
{
    __shared__ float t[32][33];
    int bx = blockIdx.x, k0 = blockIdx.y * 32;
    const float* W; int N, n0, ro;
    if (bx < 64)      { W = Wq; N = 2048; n0 = bx * 32;        ro = 0; }
    else if (bx < 80) { W = Wk; N = 512;  n0 = (bx - 64) * 32; ro = 2048; }
    else              { W = Wv; N = 512;  n0 = (bx - 80) * 32; ro = 2560; }
    int tx = threadIdx.x, ty = threadIdx.y;
#pragma unroll
    for (int i = 0; i < 4; i++)
        t[ty + 8 * i][tx] = W[(size_t)(k0 + ty + 8 * i) * N + n0 + tx];
    __syncthreads();
#pragma unroll
    for (int i = 0; i < 4; i++)
        hi[(size_t)(ro + n0 + ty + 8 * i) * CEMB + k0 + tx] =
            __float2half_rn(t[tx][ty + 8 * i]);
}

// ---------------------------------------------------------------------------
// transpose Wo -> fp16 single
// ---------------------------------------------------------------------------
__global__ void tsplit_wo(const float* __restrict__ W, __half* __restrict__ hi)
{
    __shared__ float t[32][33];
    int n0 = blockIdx.x * 32, k0 = blockIdx.y * 32;
    int tx = threadIdx.x, ty = threadIdx.y;
#pragma unroll
    for (int i = 0; i < 4; i++)
        t[ty + 8 * i][tx] = W[(size_t)(k0 + ty + 8 * i) * CEMB + n0 + tx];
    __syncthreads();
#pragma unroll
    for (int i = 0; i < 4; i++)
        hi[(size_t)(n0 + ty + 8 * i) * CEMB + k0 + tx] =
            __float2half_rn(t[tx][ty + 8 * i]);
}

// ---------------------------------------------------------------------------
// QKV GEMM: 1-term fp16, 4-stage pipeline. Fused bias+rope+pack epilogue.
// ---------------------------------------------------------------------------
__global__ __launch_bounds__(256, 2) void gemm_qkv(
    const __half* __restrict__ A, const __half* __restrict__ B,
    const float* __restrict__ bq, const float* __restrict__ bk,
    const float* __restrict__ bv,
    __half* __restrict__ qh, __half* __restrict__ kh, __half* __restrict__ vh,
    const float2* __restrict__ rope)
{
    constexpr int KD = 2048, NCHUNK = 64, STG = 16384, PITCH = 132;
    extern __shared__ char dsm[];
    uint32_t sbase = (cvta_s(dsm) + 1023) & ~1023u;

    const int tid = threadIdx.x;
    const int wid = tid >> 5, lane = tid & 31;
    const int wm = wid >> 2, wn = wid & 3;
    const int m0 = blockIdx.y * 128, n0 = blockIdx.x * 128;

    uint32_t dsts[2];
    size_t gA[2], gB[2];
#pragma unroll
    for (int p = 0; p < 2; p++) {
        int idx = tid + p * 256;
        int r = idx >> 2, c = idx & 3;
        dsts[p] = adr32(r, c);
        gA[p] = (size_t)(m0 + r) * KD + c * 8;
        gB[p] = (size_t)(n0 + r) * KD + c * 8;
    }

    const int arow = (lane & 7) + ((lane >> 3) & 1) * 8;
    const int acb  = lane >> 4;
    const int brow = (lane & 7) + (lane >> 4) * 8;
    const int bcb  = (lane >> 3) & 1;
    const int cbs  = (lane & 3) * 2;

    float acc[4][4][4];
#pragma unroll
    for (int i = 0; i < 4; i++)
#pragma unroll
        for (int j = 0; j < 4; j++) {
            acc[i][j][0] = 0.f; acc[i][j][1] = 0.f;
            acc[i][j][2] = 0.f; acc[i][j][3] = 0.f;
        }

#pragma unroll
    for (int ch = 0; ch < 3; ch++) {
        uint32_t st = sbase + ch * STG;
        int k0 = ch * 32;
#pragma unroll
        for (int p = 0; p < 2; p++) {
            cp16(st +    0 + dsts[p], A + gA[p] + k0);
            cp16(st + 8192 + dsts[p], B + gB[p] + k0);
        }
        CP_COMMIT();
    }

    for (int c = 0; c < NCHUNK; c++) {
        if (c + 3 < NCHUNK) {
            int ch = c + 3;
            uint32_t st = sbase + (ch & 3) * STG;
            int k0 = ch * 32;
#pragma unroll
            for (int p = 0; p < 2; p++) {
                cp16(st +    0 + dsts[p], A + gA[p] + k0);
                cp16(st + 8192 + dsts[p], B + gB[p] + k0);
            }
            CP_COMMIT();
            CP_WAIT(3);
        } else if (c + 2 < NCHUNK) {
            CP_WAIT(2);
        } else if (c + 1 < NCHUNK) {
            CP_WAIT(1);
        } else {
            CP_WAIT(0);
        }
        __syncthreads();

        uint32_t st = sbase + (c & 3) * STG;
        uint32_t aB = st, bB = st + 8192;

#pragma unroll
        for (int ks = 0; ks < 2; ks++) {
            uint32_t ah[4][4], bh[2][4];
#pragma unroll
            for (int mt = 0; mt < 4; mt++)
                LDSM4(ah[mt], aB + adr32(wm * 64 + mt * 16 + arow, 2 * ks + acb));
#pragma unroll
            for (int np = 0; np < 2; np++)
                LDSM4(bh[np], bB + adr32(wn * 32 + np * 16 + brow, 2 * ks + bcb));
#pragma unroll
            for (int mt = 0; mt < 4; mt++)
#pragma unroll
                for (int nt = 0; nt < 4; nt++)
                    MMA_H(acc[mt][nt], ah[mt], bh[nt >> 1][(nt & 1) * 2],
                          bh[nt >> 1][(nt & 1) * 2 + 1]);
        }
        __syncthreads();
    }

    // fused epilogue via smem fp32 staging
    const float* bias = (n0 < 2048) ? bq + n0
                      : (n0 < 2560) ? bk + (n0 - 2048)
                                    : bv + (n0 - 2560);
    float* s = (float*)((((uintptr_t)dsm) + 1023) & ~(uintptr_t)1023);

#pragma unroll
    for (int mt = 0; mt < 4; mt++) {
        int rl = wm * 64 + mt * 16 + (lane >> 2);
#pragma unroll
        for (int nt = 0; nt < 4; nt++) {
            int cl = wn * 32 + nt * 8 + cbs;
            float bb0 = bias[cl], bb1 = bias[cl + 1];
            s[rl * PITCH + cl]           = acc[mt][nt][0] + bb0;
            s[rl * PITCH + cl + 1]       = acc[mt][nt][1] + bb1;
            s[(rl + 8) * PITCH + cl]     = acc[mt][nt][2] + bb0;
            s[(rl + 8) * PITCH + cl + 1] = acc[mt][nt][3] + bb1;
        }
    }
    __syncthreads();

    if (n0 < 2560) {
        const bool isQ = (n0 < 2048);
        const float qsc = isQ ? 0.08838834764831845f : 1.0f;
        const int hh = isQ ? (n0 >> 7) : ((n0 - 2048) >> 7);
        const int nh = isQ ? NHEAD : NGROUP;
        __half* Out = isQ ? qh : kh;
#pragma unroll 4
        for (int idx = tid; idx < 128 * 32; idx += 256) {
            int r = idx >> 5, d2 = idx & 31;
            int m = m0 + r, t = m & (TSEQ - 1), b = m >> 11;
            int d0 = d2 * 2;
            float x1a = s[r * PITCH + d0],      x1b = s[r * PITCH + d0 + 1];
            float x2a = s[r * PITCH + d0 + 64], x2b = s[r * PITCH + d0 + 65];
            float2 ca = rope[t * 64 + d0], cb = rope[t * 64 + d0 + 1];
            float y1a = (x1a * ca.x - x2a * ca.y) * qsc;
            float y2a = (x1a * ca.y + x2a * ca.x) * qsc;
            float y1b = (x1b * cb.x - x2b * cb.y) * qsc;
            float y2b = (x1b * cb.y + x2b * cb.x) * qsc;
            size_t orow = ((size_t)(b * nh + hh) * TSEQ + t) * DHEAD;
            *(__half2*)(Out + orow + d0)      = __floats2half2_rn(y1a, y1b);
            *(__half2*)(Out + orow + 64 + d0) = __floats2half2_rn(y2a, y2b);
        }
    } else {
        const int g = (n0 - 2560) >> 7;
#pragma unroll 4
        for (int idx = tid; idx < 128 * 64; idx += 256) {
            int r = idx >> 6, c2 = idx & 63;
            int m = m0 + r, t = m & (TSEQ - 1), b = m >> 11;
            int c0 = c2 * 2;
            size_t o = ((size_t)(b * NGROUP + g) * TSEQ + t) * DHEAD + c0;
            *(__half2*)(vh + o) =
                __floats2half2_rn(s[r * PITCH + c0], s[r * PITCH + c0 + 1]);
        }
    }
}

// ---------------------------------------------------------------------------
// Wo GEMM: 1-term fp16, 4-stage pipeline, fp32 out.
// ---------------------------------------------------------------------------
__global__ __launch_bounds__(256, 2) void gemm_wo(
    const __half* __restrict__ A, const __half* __restrict__ B,
    const float* __restrict__ bias, float* __restrict__ C)
{
    constexpr int KD = 2048, NCHUNK = 64, STG = 16384;
    extern __shared__ char dsm[];
    uint32_t sbase = (cvta_s(dsm) + 1023) & ~1023u;

    const int tid = threadIdx.x;
    const int wid = tid >> 5, lane = tid & 31;
    const int wm = wid >> 2, wn = wid & 3;
    const int m0 = blockIdx.y * 128, n0 = blockIdx.x * 128;

    uint32_t dsts[2];
    size_t gA[2], gB[2];
#pragma unroll
    for (int p = 0; p < 2; p++) {
        int idx = tid + p * 256;
        int r = idx >> 2, c = idx & 3;
        dsts[p] = adr32(r, c);
        gA[p] = (size_t)(m0 + r) * KD + c * 8;
        gB[p] = (size_t)(n0 + r) * KD + c * 8;
    }

    const int arow = (lane & 7) + ((lane >> 3) & 1) * 8;
    const int acb  = lane >> 4;
    const int brow = (lane & 7) + (lane >> 4) * 8;
    const int bcb  = (lane >> 3) & 1;

    float acc[4][4][4];
#pragma unroll
    for (int i = 0; i < 4; i++)
#pragma unroll
        for (int j = 0; j < 4; j++) {
            acc[i][j][0] = 0.f; acc[i][j][1] = 0.f;
            acc[i][j][2] = 0.f; acc[i][j][3] = 0.f;
        }

#pragma unroll
    for (int ch = 0; ch < 3; ch++) {
        uint32_t st = sbase + ch * STG;
        int k0 = ch * 32;
#pragma unroll
        for (int p = 0; p < 2; p++) {
            cp16(st +    0 + dsts[p], A + gA[p] + k0);
            cp16(st + 8192 + dsts[p], B + gB[p] + k0);
        }
        CP_COMMIT();
    }

    for (int c = 0; c < NCHUNK; c++) {
        if (c + 3 < NCHUNK) {
            int ch = c + 3;
            uint32_t st = sbase + (ch & 3) * STG;
            int k0 = ch * 32;
#pragma unroll
            for (int p = 0; p < 2; p++) {
                cp16(st +    0 + dsts[p], A + gA[p] + k0);
                cp16(st + 8192 + dsts[p], B + gB[p] + k0);
            }
            CP_COMMIT();
            CP_WAIT(3);
        } else if (c + 2 < NCHUNK) {
            CP_WAIT(2);
        } else if (c + 1 < NCHUNK) {
            CP_WAIT(1);
        } else {
            CP_WAIT(0);
        }
        __syncthreads();

        uint32_t st = sbase + (c & 3) * STG;
        uint32_t aB = st, bB = st + 8192;

#pragma unroll
        for (int ks = 0; ks < 2; ks++) {
            uint32_t ah[4][4], bh[2][4];
#pragma unroll
            for (int mt = 0; mt < 4; mt++)
                LDSM4(ah[mt], aB + adr32(wm * 64 + mt * 16 + arow, 2 * ks + acb));
#pragma unroll
            for (int np = 0; np < 2; np++)
                LDSM4(bh[np], bB + adr32(wn * 32 + np * 16 + brow, 2 * ks + bcb));
#pragma unroll
            for (int mt = 0; mt < 4; mt++)
#pragma unroll
                for (int nt = 0; nt < 4; nt++)
                    MMA_H(acc[mt][nt], ah[mt], bh[nt >> 1][(nt & 1) * 2],
                          bh[nt >> 1][(nt & 1) * 2 + 1]);
        }
        __syncthreads();
    }

#pragma unroll
    for (int mt = 0; mt < 4; mt++) {
        int r0 = m0 + wm * 64 + mt * 16 + (lane >> 2);
#pragma unroll
        for (int nt = 0; nt < 4; nt++) {
            int cc = n0 + wn * 32 + nt * 8 + (lane & 3) * 2;
            float bb0 = bias[cc], bb1 = bias[cc + 1];
            float2 v0 = make_float2(acc[mt][nt][0] + bb0, acc[mt][nt][1] + bb1);
            float2 v1 = make_float2(acc[mt][nt][2] + bb0, acc[mt][nt][3] + bb1);
            *(float2*)(C + (size_t)r0 * CEMB + cc) = v0;
            *(float2*)(C + (size_t)(r0 + 8) * CEMB + cc) = v1;
        }
    }
}

// ---------------------------------------------------------------------------
// flash attention: all fp16 single (unchanged from R8)
// ---------------------------------------------------------------------------
__global__ __launch_bounds__(128, 2) void attn_mma(
    const __half* __restrict__ qh_g, const __half* __restrict__ kh_g,
    const __half* __restrict__ vh_g, __half* __restrict__ oh)
{
    extern __shared__ char sm[];
    uint32_t sb = (cvta_s(sm) + 1023) & ~1023u;
    const uint32_t sQ  = sb;
    const uint32_t sKV = sb + 16384;

    const int tid = threadIdx.x, w = tid >> 5, lane = tid & 31;
    const int b = blockIdx.y >> 4, h = blockIdx.y & 15, g = h >> 2;
    const int qs = blockIdx.x * 64;

    {
        size_t qb = ((size_t)(b * NHEAD + h) * TSEQ + qs) * DHEAD;
#pragma unroll
        for (int p = 0; p < 8; p++) {
            int idx = tid + p * 128;
            int row = idx >> 4, ch = idx & 15;
            cp16(sQ + adr128(row, ch), qh_g + qb + (size_t)row * DHEAD + ch * 8);
        }
    }
    CP_COMMIT();

    int t0 = qs - SWIN; if (t0 < 0) t0 = 0;
    const int sink = (t0 > 0) ? 1 : 0;
    const int ntiles = sink + (qs + 64 - t0) / 32;
    const size_t kvbase = (size_t)(b * NGROUP + g) * TSEQ * DHEAD;

    {
        int ts = sink ? 0 : t0;
        size_t kb = kvbase + (size_t)ts * DHEAD;
#pragma unroll
        for (int p = 0; p < 4; p++) {
            int idx = tid + p * 128;
            int row = idx >> 4, ch = idx & 15;
            uint32_t d = adr128(row, ch);
            size_t s = kb + (size_t)row * DHEAD + ch * 8;
            cp16(sKV +    0 + d, kh_g + s);
            cp16(sKV + 8192 + d, vh_g + s);
        }
    }
    CP_COMMIT();

    const int arow = (lane & 7) + ((lane >> 3) & 1) * 8;
    const int acb  = lane >> 4;
    const int brow = (lane & 7) + (lane >> 4) * 8;
    const int bcb  = (lane >> 3) & 1;
    const int vr_i = ((lane >> 3) & 1) * 8 + (lane & 7);
    const int vc_i = lane >> 4;
    const int i0 = qs + w * 16 + (lane >> 2);
    const int i1 = i0 + 8;
    const int iwmax = qs + w * 16 + 15;
    const int cbs = (lane & 3) * 2;

    CP_WAIT(1);
    __syncthreads();
    uint32_t qf[8][4];
#pragma unroll
    for (int kc = 0; kc < 8; kc++)
        LDSM4(qf[kc], sQ + adr128(w * 16 + arow, 2 * kc + acb));

    float o[16][4];
#pragma unroll
    for (int i = 0; i < 16; i++) { o[i][0] = 0.f; o[i][1] = 0.f; o[i][2] = 0.f; o[i][3] = 0.f; }
    float m0 = -1e30f, m1 = -1e30f, l0 = 0.f, l1 = 0.f;

    for (int it = 0; it < ntiles; it++) {
        const bool snk = (sink && it == 0);
        const int ts = snk ? 0 : t0 + (it - sink) * 32;
        const int n2max = snk ? 1 : 2;

        if (it + 1 < ntiles) {
            int tsn = t0 + (it + 1 - sink) * 32;
            uint32_t st = sKV + ((it + 1) & 1) * 16384;
            size_t kb = kvbase + (size_t)tsn * DHEAD;
#pragma unroll
            for (int p = 0; p < 4; p++) {
                int idx = tid + p * 128;
                int row = idx >> 4, ch = idx & 15;
                uint32_t d = adr128(row, ch);
                size_t s = kb + (size_t)row * DHEAD + ch * 8;
                cp16(st +    0 + d, kh_g + s);
                cp16(st + 8192 + d, vh_g + s);
            }
            CP_COMMIT();
            CP_WAIT(1);
        } else {
            CP_WAIT(0);
        }
        __syncthreads();

        uint32_t stg = sKV + (it & 1) * 16384;
        uint32_t sK = stg, sV = stg + 8192;

        float sc[4][4];
#pragma unroll
        for (int i = 0; i < 4; i++) { sc[i][0] = 0.f; sc[i][1] = 0.f; sc[i][2] = 0.f; sc[i][3] = 0.f; }

        for (int n2 = 0; n2 < n2max; n2++) {
            if (ts + n2 * 16 > iwmax) break;
#pragma unroll
            for (int kc = 0; kc < 8; kc++) {
                uint32_t kf[4];
                LDSM4(kf, sK + adr128(n2 * 16 + brow, 2 * kc + bcb));
                MMA_H(sc[2 * n2],     qf[kc], kf[0], kf[1]);
                MMA_H(sc[2 * n2 + 1], qf[kc], kf[2], kf[3]);
            }
        }

        float rm0 = -1e30f, rm1 = -1e30f;
#pragma unroll
        for (int nt = 0; nt < 4; nt++) {
            int j0 = ts + nt * 8 + cbs, j1 = j0 + 1;
            sc[nt][0] = (j0 <= i0 && (j0 >= i0 - SWIN || j0 < SINK)) ? sc[nt][0] : -1e30f;
            sc[nt][1] = (j1 <= i0 && (j1 >= i0 - SWIN || j1 < SINK)) ? sc[nt][1] : -1e30f;
            sc[nt][2] = (j0 <= i1 && (j0 >= i1 - SWIN || j0 < SINK)) ? sc[nt][2] : -1e30f;
            sc[nt][3] = (j1 <= i1 && (j1 >= i1 - SWIN || j1 < SINK)) ? sc[nt][3] : -1e30f;
            rm0 = fmaxf(rm0, fmaxf(sc[nt][0], sc[nt][1]));
            rm1 = fmaxf(rm1, fmaxf(sc[nt][2], sc[nt][3]));
        }
        rm0 = fmaxf(rm0, __shfl_xor_sync(0xffffffffu, rm0, 1));
        rm0 = fmaxf(rm0, __shfl_xor_sync(0xffffffffu, rm0, 2));
        rm1 = fmaxf(rm1, __shfl_xor_sync(0xffffffffu, rm1, 1));
        rm1 = fmaxf(rm1, __shfl_xor_sync(0xffffffffu, rm1, 2));
        float mn0 = fmaxf(m0, rm0), mn1 = fmaxf(m1, rm1);
        float c0 = __expf(m0 - mn0), c1 = __expf(m1 - mn1);
        m0 = mn0; m1 = mn1;

#pragma unroll
        for (int nd = 0; nd < 16; nd++) {
            o[nd][0] *= c0; o[nd][1] *= c0; o[nd][2] *= c1; o[nd][3] *= c1;
        }

        float rs0 = 0.f, rs1 = 0.f;
        for (int k2 = 0; k2 < n2max; k2++) {
            if (ts + k2 * 16 > iwmax) break;
            uint32_t aP[4];
#pragma unroll
            for (int q2 = 0; q2 < 2; q2++) {
                int nt = 2 * k2 + q2;
                float p00 = __expf(sc[nt][0] - mn0), p01 = __expf(sc[nt][1] - mn0);
                float p10 = __expf(sc[nt][2] - mn1), p11 = __expf(sc[nt][3] - mn1);
                rs0 += p00 + p01; rs1 += p10 + p11;
                __half2 h0v = __floats2half2_rn(p00, p01);
                __half2 h1v = __floats2half2_rn(p10, p11);
                aP[2 * q2]     = *(uint32_t*)&h0v;
                aP[2 * q2 + 1] = *(uint32_t*)&h1v;
            }
#pragma unroll
            for (int ndp = 0; ndp < 8; ndp++) {
                uint32_t bv[4];
                LDSM4T(bv, sV + adr128(k2 * 16 + vr_i, ndp * 2 + vc_i));
                MMA_H(o[ndp * 2],     aP, bv[0], bv[1]);
                MMA_H(o[ndp * 2 + 1], aP, bv[2], bv[3]);
            }
        }
        rs0 += __shfl_xor_sync(0xffffffffu, rs0, 1);
        rs0 += __shfl_xor_sync(0xffffffffu, rs0, 2);
        rs1 += __shfl_xor_sync(0xffffffffu, rs1, 1);
        rs1 += __shfl_xor_sync(0xffffffffu, rs1, 2);
        l0 = l0 * c0 + rs0;
        l1 = l1 * c1 + rs1;

        __syncthreads();
    }

    float il0 = 1.f / l0, il1 = 1.f / l1;
    size_t or0 = (size_t)(b * TSEQ + qs + w * 16 + (lane >> 2)) * CEMB + h * DHEAD;
    size_t or1 = or0 + (size_t)8 * CEMB;
#pragma unroll
    for (int nd = 0; nd < 16; nd++) {
        int col = nd * 8 + cbs;
        *(__half2*)(oh + or0 + col) = __floats2half2_rn(o[nd][0] * il0, o[nd][1] * il0);
        *(__half2*)(oh + or1 + col) = __floats2half2_rn(o[nd][2] * il1, o[nd][3] * il1);
    }
}

// ---------------------------------------------------------------------------
extern "C" void kernel_launch(void* const* d_in, const int* in_sizes, int n_in,
                              void* d_out, int out_size)
{
    const float* x  = (const float*)d_in[0];
    const float* Wq = (const float*)d_in[1];
    const float* bq = (const float*)d_in[2];
    const float* Wk = (const float*)d_in[3];
    const float* bk = (const float*)d_in[4];
    const float* Wv = (const float*)d_in[5];
    const float* bv = (const float*)d_in[6];
    const float* Wo = (const float*)d_in[7];
    const float* bo = (const float*)d_in[8];
    float* out = (float*)d_out;

    __half *xh, *qh, *kh, *vh, *oh, *wt, *wot;
    float2* rope;
    cudaGetSymbolAddress((void**)&xh,  g_xh);
    cudaGetSymbolAddress((void**)&qh,  g_qh);
    cudaGetSymbolAddress((void**)&kh,  g_kh);
    cudaGetSymbolAddress((void**)&vh,  g_vh);
    cudaGetSymbolAddress((void**)&oh,  g_oh);
    cudaGetSymbolAddress((void**)&wt,  g_WT);
    cudaGetSymbolAddress((void**)&wot, g_WoT);
    cudaGetSymbolAddress((void**)&rope, g_rope);

    const int QKV_SMEM = 68608;   // max(4*16KB, 128*132*4 staging) + align
    cudaFuncSetAttribute(gemm_qkv, cudaFuncAttributeMaxDynamicSharedMemorySize, QKV_SMEM);
    const int WO_SMEM = 66560;    // 4*16KB + align
    cudaFuncSetAttribute(gemm_wo, cudaFuncAttributeMaxDynamicSharedMemorySize, WO_SMEM);
    const int ATTN_SMEM = 50176;
    cudaFuncSetAttribute(attn_mma, cudaFuncAttributeMaxDynamicSharedMemorySize, ATTN_SMEM);

    // (0) rope table  (1) x convert  (2) QKV weights  (3) Wo weights
    rope_table<<<(TSEQ * 64) / 256, 256>>>(rope);
    {
        int n4 = (MROWS * CEMB) / 4;
        conv_x<<<(n4 + 255) / 256, 256>>>(x, xh, n4);
    }
    tsplit_qkv<<<dim3(96, 64), dim3(32, 8)>>>(Wq, Wk, Wv, wt);
    tsplit_wo<<<dim3(64, 64), dim3(32, 8)>>>(Wo, wot);

    // (4) fused QKV projection + rope + pack (1-term fp16)
    gemm_qkv<<<dim3(NQKV / 128, MROWS / 128), 256, QKV_SMEM>>>(
        xh, wt, bq, bk, bv, qh, kh, vh, rope);

    // (5) flash attention  ← ncu -s 5 captures this
    attn_mma<<<dim3(TSEQ / 64, 2 * NHEAD), 128, ATTN_SMEM>>>(qh, kh, vh, oh);

    // (6) output projection (1-term fp16)
    gemm_wo<<<dim3(CEMB / 128, MROWS / 128), 256, WO_SMEM>>>(oh, wot, bo, out);
}

// round 10
// speedup vs baseline: 2.3005x; 1.0048x over previous
#include <cuda_runtime.h>
#include <cuda_fp16.h>
#include <math.h>
#include <stdint.h>

// Problem constants
#define MROWS 4096   // B*T
#define CEMB  2048
#define TSEQ  2048
#define NHEAD 16
#define NGROUP 4
#define DHEAD 128
#define KVC   512
#define SWIN  512
#define SINK  4
#define NQKV  3072

// scratch (all fp16)
__device__ __half g_xh [(size_t)MROWS * CEMB];
__device__ __half g_oh [(size_t)MROWS * CEMB];
__device__ __half g_qh [(size_t)MROWS * CEMB];          // [b,h,t,d] pre-scaled
__device__ __half g_kh [(size_t)MROWS * KVC];           // [b,g,t,d]
__device__ __half g_vh [(size_t)MROWS * KVC];
__device__ __half g_WT [(size_t)NQKV * CEMB];           // packed Wq|Wk|Wv, [N,K]
__device__ __half g_WoT[(size_t)CEMB * CEMB];
__device__ float2 g_rope[(size_t)TSEQ * 64];

// ---------------------------------------------------------------------------
// helpers
// ---------------------------------------------------------------------------
__device__ __forceinline__ uint32_t cvta_s(const void* p) {
    return (uint32_t)__cvta_generic_to_shared(p);
}
__device__ __forceinline__ void cp16(uint32_t dst, const void* src) {
    asm volatile("cp.async.cg.shared.global [%0], [%1], 16;\n" :: "r"(dst), "l"(src));
}
#define CP_COMMIT() asm volatile("cp.async.commit_group;\n" ::: "memory")
#define CP_WAIT(n)  asm volatile("cp.async.wait_group %0;\n" :: "n"(n) : "memory")

#define LDSM4(r, addr) \
    asm volatile("ldmatrix.sync.aligned.m8n8.x4.shared.b16 {%0,%1,%2,%3}, [%4];" \
        : "=r"((r)[0]), "=r"((r)[1]), "=r"((r)[2]), "=r"((r)[3]) : "r"(addr))

#define LDSM4T(r, addr) \
    asm volatile("ldmatrix.sync.aligned.m8n8.x4.trans.shared.b16 {%0,%1,%2,%3}, [%4];" \
        : "=r"((r)[0]), "=r"((r)[1]), "=r"((r)[2]), "=r"((r)[3]) : "r"(addr))

#define MMA_H(c, a, b0, b1) \
    asm volatile("mma.sync.aligned.m16n8k16.row.col.f32.f16.f16.f32 " \
        "{%0,%1,%2,%3},{%4,%5,%6,%7},{%8,%9},{%0,%1,%2,%3};" \
        : "+f"((c)[0]), "+f"((c)[1]), "+f"((c)[2]), "+f"((c)[3]) \
        : "r"((a)[0]), "r"((a)[1]), "r"((a)[2]), "r"((a)[3]), "r"(b0), "r"(b1))

__device__ __forceinline__ uint32_t adr32(int r, int c4) {
    return (uint32_t)((r >> 1) * 128 + (((((r & 1) << 2) | c4) ^ ((r >> 1) & 7)) << 4));
}
__device__ __forceinline__ uint32_t adr128(int r, int c) {
    return (uint32_t)(r * 256 + ((c ^ (r & 7)) << 4));
}

// ---------------------------------------------------------------------------
// rope table
// ---------------------------------------------------------------------------
__global__ void rope_table(float2* tab)
{
    int i = blockIdx.x * blockDim.x + threadIdx.x;
    if (i >= TSEQ * 64) return;
    int d = i & 63, t = i >> 6;
    float inv = powf(10000.f, -(float)d * (1.f / 64.f));
    float s, c;
    sincosf((float)t * inv, &s, &c);
    tab[i] = make_float2(c, s);
}

// ---------------------------------------------------------------------------
// convert fp32 -> fp16 single
// ---------------------------------------------------------------------------
__global__ void conv_x(const float* __restrict__ s, __half* __restrict__ d, int n4)
{
    int i = blockIdx.x * blockDim.x + threadIdx.x;
    if (i >= n4) return;
    float4 v = ((const float4*)s)[i];
    __half2* p = (__half2*)d;
    p[i * 2 + 0] = __floats2half2_rn(v.x, v.y);
    p[i * 2 + 1] = __floats2half2_rn(v.z, v.w);
}

// ---------------------------------------------------------------------------
// transpose QKV weights -> fp16 single (packed rows)
// ---------------------------------------------------------------------------
__global__ void tsplit_qkv(const float* __restrict__ Wq,
                           const float* __restrict__ Wk,
                           const float* __restrict__ Wv,
                           __half* __restrict__ hi)
{
    __shared__ float t[32][33];
    int bx = blockIdx.x, k0 = blockIdx.y * 32;
    const float* W; int N, n0, ro;
    if (bx < 64)      { W = Wq; N = 2048; n0 = bx * 32;        ro = 0; }
    else if (bx < 80) { W = Wk; N = 512;  n0 = (bx - 64) * 32; ro = 2048; }
    else              { W = Wv; N = 512;  n0 = (bx - 80) * 32; ro = 2560; }
    int tx = threadIdx.x, ty = threadIdx.y;
#pragma unroll
    for (int i = 0; i < 4; i++)
        t[ty + 8 * i][tx] = W[(size_t)(k0 + ty + 8 * i) * N + n0 + tx];
    __syncthreads();
#pragma unroll
    for (int i = 0; i < 4; i++)
        hi[(size_t)(ro + n0 + ty + 8 * i) * CEMB + k0 + tx] =
            __float2half_rn(t[tx][ty + 8 * i]);
}

// ---------------------------------------------------------------------------
// transpose Wo -> fp16 single
// ---------------------------------------------------------------------------
__global__ void tsplit_wo(const float* __restrict__ W, __half* __restrict__ hi)
{
    __shared__ float t[32][33];
    int n0 = blockIdx.x * 32, k0 = blockIdx.y * 32;
    int tx = threadIdx.x, ty = threadIdx.y;
#pragma unroll
    for (int i = 0; i < 4; i++)
        t[ty + 8 * i][tx] = W[(size_t)(k0 + ty + 8 * i) * CEMB + n0 + tx];
    __syncthreads();
#pragma unroll
    for (int i = 0; i < 4; i++)
        hi[(size_t)(n0 + ty + 8 * i) * CEMB + k0 + tx] =
            __float2half_rn(t[tx][ty + 8 * i]);
}

// ---------------------------------------------------------------------------
// QKV GEMM: 1-term fp16, 4-stage pipeline. Fused bias+rope+pack epilogue.
// (unchanged from R9)
// ---------------------------------------------------------------------------
__global__ __launch_bounds__(256, 2) void gemm_qkv(
    const __half* __restrict__ A, const __half* __restrict__ B,
    const float* __restrict__ bq, const float* __restrict__ bk,
    const float* __restrict__ bv,
    __half* __restrict__ qh, __half* __restrict__ kh, __half* __restrict__ vh,
    const float2* __restrict__ rope)
{
    constexpr int KD = 2048, NCHUNK = 64, STG = 16384, PITCH = 132;
    extern __shared__ char dsm[];
    uint32_t sbase = (cvta_s(dsm) + 1023) & ~1023u;

    const int tid = threadIdx.x;
    const int wid = tid >> 5, lane = tid & 31;
    const int wm = wid >> 2, wn = wid & 3;
    const int m0 = blockIdx.y * 128, n0 = blockIdx.x * 128;

    uint32_t dsts[2];
    size_t gA[2], gB[2];
#pragma unroll
    for (int p = 0; p < 2; p++) {
        int idx = tid + p * 256;
        int r = idx >> 2, c = idx & 3;
        dsts[p] = adr32(r, c);
        gA[p] = (size_t)(m0 + r) * KD + c * 8;
        gB[p] = (size_t)(n0 + r) * KD + c * 8;
    }

    const int arow = (lane & 7) + ((lane >> 3) & 1) * 8;
    const int acb  = lane >> 4;
    const int brow = (lane & 7) + (lane >> 4) * 8;
    const int bcb  = (lane >> 3) & 1;
    const int cbs  = (lane & 3) * 2;

    float acc[4][4][4];
#pragma unroll
    for (int i = 0; i < 4; i++)
#pragma unroll
        for (int j = 0; j < 4; j++) {
            acc[i][j][0] = 0.f; acc[i][j][1] = 0.f;
            acc[i][j][2] = 0.f; acc[i][j][3] = 0.f;
        }

#pragma unroll
    for (int ch = 0; ch < 3; ch++) {
        uint32_t st = sbase + ch * STG;
        int k0 = ch * 32;
#pragma unroll
        for (int p = 0; p < 2; p++) {
            cp16(st +    0 + dsts[p], A + gA[p] + k0);
            cp16(st + 8192 + dsts[p], B + gB[p] + k0);
        }
        CP_COMMIT();
    }

    for (int c = 0; c < NCHUNK; c++) {
        if (c + 3 < NCHUNK) {
            int ch = c + 3;
            uint32_t st = sbase + (ch & 3) * STG;
            int k0 = ch * 32;
#pragma unroll
            for (int p = 0; p < 2; p++) {
                cp16(st +    0 + dsts[p], A + gA[p] + k0);
                cp16(st + 8192 + dsts[p], B + gB[p] + k0);
            }
            CP_COMMIT();
            CP_WAIT(3);
        } else if (c + 2 < NCHUNK) {
            CP_WAIT(2);
        } else if (c + 1 < NCHUNK) {
            CP_WAIT(1);
        } else {
            CP_WAIT(0);
        }
        __syncthreads();

        uint32_t st = sbase + (c & 3) * STG;
        uint32_t aB = st, bB = st + 8192;

#pragma unroll
        for (int ks = 0; ks < 2; ks++) {
            uint32_t ah[4][4], bh[2][4];
#pragma unroll
            for (int mt = 0; mt < 4; mt++)
                LDSM4(ah[mt], aB + adr32(wm * 64 + mt * 16 + arow, 2 * ks + acb));
#pragma unroll
            for (int np = 0; np < 2; np++)
                LDSM4(bh[np], bB + adr32(wn * 32 + np * 16 + brow, 2 * ks + bcb));
#pragma unroll
            for (int mt = 0; mt < 4; mt++)
#pragma unroll
                for (int nt = 0; nt < 4; nt++)
                    MMA_H(acc[mt][nt], ah[mt], bh[nt >> 1][(nt & 1) * 2],
                          bh[nt >> 1][(nt & 1) * 2 + 1]);
        }
        __syncthreads();
    }

    // fused epilogue via smem fp32 staging
    const float* bias = (n0 < 2048) ? bq + n0
                      : (n0 < 2560) ? bk + (n0 - 2048)
                                    : bv + (n0 - 2560);
    float* s = (float*)((((uintptr_t)dsm) + 1023) & ~(uintptr_t)1023);

#pragma unroll
    for (int mt = 0; mt < 4; mt++) {
        int rl = wm * 64 + mt * 16 + (lane >> 2);
#pragma unroll
        for (int nt = 0; nt < 4; nt++) {
            int cl = wn * 32 + nt * 8 + cbs;
            float bb0 = bias[cl], bb1 = bias[cl + 1];
            s[rl * PITCH + cl]           = acc[mt][nt][0] + bb0;
            s[rl * PITCH + cl + 1]       = acc[mt][nt][1] + bb1;
            s[(rl + 8) * PITCH + cl]     = acc[mt][nt][2] + bb0;
            s[(rl + 8) * PITCH + cl + 1] = acc[mt][nt][3] + bb1;
        }
    }
    __syncthreads();

    if (n0 < 2560) {
        const bool isQ = (n0 < 2048);
        const float qsc = isQ ? 0.08838834764831845f : 1.0f;
        const int hh = isQ ? (n0 >> 7) : ((n0 - 2048) >> 7);
        const int nh = isQ ? NHEAD : NGROUP;
        __half* Out = isQ ? qh : kh;
#pragma unroll 4
        for (int idx = tid; idx < 128 * 32; idx += 256) {
            int r = idx >> 5, d2 = idx & 31;
            int m = m0 + r, t = m & (TSEQ - 1), b = m >> 11;
            int d0 = d2 * 2;
            float x1a = s[r * PITCH + d0],      x1b = s[r * PITCH + d0 + 1];
            float x2a = s[r * PITCH + d0 + 64], x2b = s[r * PITCH + d0 + 65];
            float2 ca = rope[t * 64 + d0], cb = rope[t * 64 + d0 + 1];
            float y1a = (x1a * ca.x - x2a * ca.y) * qsc;
            float y2a = (x1a * ca.y + x2a * ca.x) * qsc;
            float y1b = (x1b * cb.x - x2b * cb.y) * qsc;
            float y2b = (x1b * cb.y + x2b * cb.x) * qsc;
            size_t orow = ((size_t)(b * nh + hh) * TSEQ + t) * DHEAD;
            *(__half2*)(Out + orow + d0)      = __floats2half2_rn(y1a, y1b);
            *(__half2*)(Out + orow + 64 + d0) = __floats2half2_rn(y2a, y2b);
        }
    } else {
        const int g = (n0 - 2560) >> 7;
#pragma unroll 4
        for (int idx = tid; idx < 128 * 64; idx += 256) {
            int r = idx >> 6, c2 = idx & 63;
            int m = m0 + r, t = m & (TSEQ - 1), b = m >> 11;
            int c0 = c2 * 2;
            size_t o = ((size_t)(b * NGROUP + g) * TSEQ + t) * DHEAD + c0;
            *(__half2*)(vh + o) =
                __floats2half2_rn(s[r * PITCH + c0], s[r * PITCH + c0 + 1]);
        }
    }
}

// ---------------------------------------------------------------------------
// Wo GEMM: 1-term fp16, 4-stage pipeline, fp32 out. (unchanged from R9)
// ---------------------------------------------------------------------------
__global__ __launch_bounds__(256, 2) void gemm_wo(
    const __half* __restrict__ A, const __half* __restrict__ B,
    const float* __restrict__ bias, float* __restrict__ C)
{
    constexpr int KD = 2048, NCHUNK = 64, STG = 16384;
    extern __shared__ char dsm[];
    uint32_t sbase = (cvta_s(dsm) + 1023) & ~1023u;

    const int tid = threadIdx.x;
    const int wid = tid >> 5, lane = tid & 31;
    const int wm = wid >> 2, wn = wid & 3;
    const int m0 = blockIdx.y * 128, n0 = blockIdx.x * 128;

    uint32_t dsts[2];
    size_t gA[2], gB[2];
#pragma unroll
    for (int p = 0; p < 2; p++) {
        int idx = tid + p * 256;
        int r = idx >> 2, c = idx & 3;
        dsts[p] = adr32(r, c);
        gA[p] = (size_t)(m0 + r) * KD + c * 8;
        gB[p] = (size_t)(n0 + r) * KD + c * 8;
    }

    const int arow = (lane & 7) + ((lane >> 3) & 1) * 8;
    const int acb  = lane >> 4;
    const int brow = (lane & 7) + (lane >> 4) * 8;
    const int bcb  = (lane >> 3) & 1;

    float acc[4][4][4];
#pragma unroll
    for (int i = 0; i < 4; i++)
#pragma unroll
        for (int j = 0; j < 4; j++) {
            acc[i][j][0] = 0.f; acc[i][j][1] = 0.f;
            acc[i][j][2] = 0.f; acc[i][j][3] = 0.f;
        }

#pragma unroll
    for (int ch = 0; ch < 3; ch++) {
        uint32_t st = sbase + ch * STG;
        int k0 = ch * 32;
#pragma unroll
        for (int p = 0; p < 2; p++) {
            cp16(st +    0 + dsts[p], A + gA[p] + k0);
            cp16(st + 8192 + dsts[p], B + gB[p] + k0);
        }
        CP_COMMIT();
    }

    for (int c = 0; c < NCHUNK; c++) {
        if (c + 3 < NCHUNK) {
            int ch = c + 3;
            uint32_t st = sbase + (ch & 3) * STG;
            int k0 = ch * 32;
#pragma unroll
            for (int p = 0; p < 2; p++) {
                cp16(st +    0 + dsts[p], A + gA[p] + k0);
                cp16(st + 8192 + dsts[p], B + gB[p] + k0);
            }
            CP_COMMIT();
            CP_WAIT(3);
        } else if (c + 2 < NCHUNK) {
            CP_WAIT(2);
        } else if (c + 1 < NCHUNK) {
            CP_WAIT(1);
        } else {
            CP_WAIT(0);
        }
        __syncthreads();

        uint32_t st = sbase + (c & 3) * STG;
        uint32_t aB = st, bB = st + 8192;

#pragma unroll
        for (int ks = 0; ks < 2; ks++) {
            uint32_t ah[4][4], bh[2][4];
#pragma unroll
            for (int mt = 0; mt < 4; mt++)
                LDSM4(ah[mt], aB + adr32(wm * 64 + mt * 16 + arow, 2 * ks + acb));
#pragma unroll
            for (int np = 0; np < 2; np++)
                LDSM4(bh[np], bB + adr32(wn * 32 + np * 16 + brow, 2 * ks + bcb));
#pragma unroll
            for (int mt = 0; mt < 4; mt++)
#pragma unroll
                for (int nt = 0; nt < 4; nt++)
                    MMA_H(acc[mt][nt], ah[mt], bh[nt >> 1][(nt & 1) * 2],
                          bh[nt >> 1][(nt & 1) * 2 + 1]);
        }
        __syncthreads();
    }

#pragma unroll
    for (int mt = 0; mt < 4; mt++) {
        int r0 = m0 + wm * 64 + mt * 16 + (lane >> 2);
#pragma unroll
        for (int nt = 0; nt < 4; nt++) {
            int cc = n0 + wn * 32 + nt * 8 + (lane & 3) * 2;
            float bb0 = bias[cc], bb1 = bias[cc + 1];
            float2 v0 = make_float2(acc[mt][nt][0] + bb0, acc[mt][nt][1] + bb1);
            float2 v1 = make_float2(acc[mt][nt][2] + bb0, acc[mt][nt][3] + bb1);
            *(float2*)(C + (size_t)r0 * CEMB + cc) = v0;
            *(float2*)(C + (size_t)(r0 + 8) * CEMB + cc) = v1;
        }
    }
}

// ---------------------------------------------------------------------------
// flash attention: QT=128 (256 threads, 8 warps x 16 rows), KT=64,
// double-buffered KV, mask-free fast path, conditional rescale.
// ---------------------------------------------------------------------------
__global__ __launch_bounds__(256, 1) void attn_mma(
    const __half* __restrict__ qh_g, const __half* __restrict__ kh_g,
    const __half* __restrict__ vh_g, __half* __restrict__ oh)
{
    extern __shared__ char sm[];
    uint32_t sb = (cvta_s(sm) + 1023) & ~1023u;
    const uint32_t sQ  = sb;            // 32KB (128 rows x 256B)
    const uint32_t sKV = sb + 32768;    // per stage 32768: K 16KB, V 16KB

    const int tid = threadIdx.x, w = tid >> 5, lane = tid & 31;
    const int b = blockIdx.y >> 4, h = blockIdx.y & 15, g = h >> 2;
    const int qs = blockIdx.x * 128;

    // Q tile: 128 rows x 128 dims fp16 = 32KB
    {
        size_t qb = ((size_t)(b * NHEAD + h) * TSEQ + qs) * DHEAD;
#pragma unroll
        for (int p = 0; p < 8; p++) {
            int idx = tid + p * 256;
            int row = idx >> 4, ch = idx & 15;
            cp16(sQ + adr128(row, ch), qh_g + qb + (size_t)row * DHEAD + ch * 8);
        }
    }
    CP_COMMIT();

    int t0 = qs - SWIN; if (t0 < 0) t0 = 0;
    const int sink = (t0 > 0) ? 1 : 0;
    const int ntiles = sink + (qs + 128 - t0) / 64;
    const size_t kvbase = (size_t)(b * NGROUP + g) * TSEQ * DHEAD;

    // KV tile 0 (64 rows K + 64 rows V)
    {
        int ts = sink ? 0 : t0;
        size_t kb = kvbase + (size_t)ts * DHEAD;
#pragma unroll
        for (int p = 0; p < 4; p++) {
            int idx = tid + p * 256;
            int row = idx >> 4, ch = idx & 15;
            uint32_t d = adr128(row, ch);
            size_t s = kb + (size_t)row * DHEAD + ch * 8;
            cp16(sKV +     0 + d, kh_g + s);
            cp16(sKV + 16384 + d, vh_g + s);
        }
    }
    CP_COMMIT();

    const int arow = (lane & 7) + ((lane >> 3) & 1) * 8;
    const int acb  = lane >> 4;
    const int brow = (lane & 7) + (lane >> 4) * 8;
    const int bcb  = (lane >> 3) & 1;
    const int vr_i = ((lane >> 3) & 1) * 8 + (lane & 7);
    const int vc_i = lane >> 4;
    const int i0 = qs + w * 16 + (lane >> 2);
    const int i1 = i0 + 8;
    const int iwmin = qs + w * 16;         // warp's min query row
    const int iwmax = qs + w * 16 + 15;    // warp's max query row
    const int cbs = (lane & 3) * 2;

    CP_WAIT(1);
    __syncthreads();
    uint32_t qf[8][4];
#pragma unroll
    for (int kc = 0; kc < 8; kc++)
        LDSM4(qf[kc], sQ + adr128(w * 16 + arow, 2 * kc + acb));

    float o[16][4];
#pragma unroll
    for (int i = 0; i < 16; i++) { o[i][0] = 0.f; o[i][1] = 0.f; o[i][2] = 0.f; o[i][3] = 0.f; }
    float m0 = -1e30f, m1 = -1e30f, l0 = 0.f, l1 = 0.f;

    for (int it = 0; it < ntiles; it++) {
        const bool snk = (sink && it == 0);
        const int ts = snk ? 0 : t0 + (it - sink) * 64;
        const int n2max = snk ? 1 : 4;

        if (it + 1 < ntiles) {
            int tsn = t0 + (it + 1 - sink) * 64;
            uint32_t st = sKV + ((it + 1) & 1) * 32768;
            size_t kb = kvbase + (size_t)tsn * DHEAD;
#pragma unroll
            for (int p = 0; p < 4; p++) {
                int idx = tid + p * 256;
                int row = idx >> 4, ch = idx & 15;
                uint32_t d = adr128(row, ch);
                size_t s = kb + (size_t)row * DHEAD + ch * 8;
                cp16(st +     0 + d, kh_g + s);
                cp16(st + 16384 + d, vh_g + s);
            }
            CP_COMMIT();
            CP_WAIT(1);
        } else {
            CP_WAIT(0);
        }
        __syncthreads();

        uint32_t stg = sKV + (it & 1) * 32768;
        uint32_t sK = stg, sV = stg + 16384;

        // S = Q @ K^T
        float sc[8][4];
#pragma unroll
        for (int i = 0; i < 8; i++) { sc[i][0] = 0.f; sc[i][1] = 0.f; sc[i][2] = 0.f; sc[i][3] = 0.f; }

        for (int n2 = 0; n2 < n2max; n2++) {
            if (ts + n2 * 16 > iwmax) break;   // fully causal-masked for this warp
#pragma unroll
            for (int kc = 0; kc < 8; kc++) {
                uint32_t kf[4];
                LDSM4(kf, sK + adr128(n2 * 16 + brow, 2 * kc + bcb));
                MMA_H(sc[2 * n2],     qf[kc], kf[0], kf[1]);
                MMA_H(sc[2 * n2 + 1], qf[kc], kf[2], kf[3]);
            }
        }

        // mask + row max. Fast path: tile fully valid for this warp.
        float rm0 = -1e30f, rm1 = -1e30f;
        const bool full = (!snk) && (ts + 63 <= iwmin) && (ts >= iwmax - SWIN);
        if (full) {
#pragma unroll
            for (int nt = 0; nt < 8; nt++) {
                rm0 = fmaxf(rm0, fmaxf(sc[nt][0], sc[nt][1]));
                rm1 = fmaxf(rm1, fmaxf(sc[nt][2], sc[nt][3]));
            }
        } else {
#pragma unroll
            for (int nt = 0; nt < 8; nt++) {
                int j0 = ts + nt * 8 + cbs, j1 = j0 + 1;
                sc[nt][0] = (j0 <= i0 && (j0 >= i0 - SWIN || j0 < SINK)) ? sc[nt][0] : -1e30f;
                sc[nt][1] = (j1 <= i0 && (j1 >= i0 - SWIN || j1 < SINK)) ? sc[nt][1] : -1e30f;
                sc[nt][2] = (j0 <= i1 && (j0 >= i1 - SWIN || j0 < SINK)) ? sc[nt][2] : -1e30f;
                sc[nt][3] = (j1 <= i1 && (j1 >= i1 - SWIN || j1 < SINK)) ? sc[nt][3] : -1e30f;
                rm0 = fmaxf(rm0, fmaxf(sc[nt][0], sc[nt][1]));
                rm1 = fmaxf(rm1, fmaxf(sc[nt][2], sc[nt][3]));
            }
        }
        rm0 = fmaxf(rm0, __shfl_xor_sync(0xffffffffu, rm0, 1));
        rm0 = fmaxf(rm0, __shfl_xor_sync(0xffffffffu, rm0, 2));
        rm1 = fmaxf(rm1, __shfl_xor_sync(0xffffffffu, rm1, 1));
        rm1 = fmaxf(rm1, __shfl_xor_sync(0xffffffffu, rm1, 2));
        float mn0 = fmaxf(m0, rm0), mn1 = fmaxf(m1, rm1);
        float c0 = __expf(m0 - mn0), c1 = __expf(m1 - mn1);
        m0 = mn0; m1 = mn1;

        if (c0 != 1.f || c1 != 1.f) {
#pragma unroll
            for (int nd = 0; nd < 16; nd++) {
                o[nd][0] *= c0; o[nd][1] *= c0; o[nd][2] *= c1; o[nd][3] *= c1;
            }
        }

        float rs0 = 0.f, rs1 = 0.f;
        for (int k2 = 0; k2 < n2max; k2++) {
            if (ts + k2 * 16 > iwmax) break;
            uint32_t aP[4];
#pragma unroll
            for (int q2 = 0; q2 < 2; q2++) {
                int nt = 2 * k2 + q2;
                float p00 = __expf(sc[nt][0] - mn0), p01 = __expf(sc[nt][1] - mn0);
                float p10 = __expf(sc[nt][2] - mn1), p11 = __expf(sc[nt][3] - mn1);
                rs0 += p00 + p01; rs1 += p10 + p11;
                __half2 h0v = __floats2half2_rn(p00, p01);
                __half2 h1v = __floats2half2_rn(p10, p11);
                aP[2 * q2]     = *(uint32_t*)&h0v;
                aP[2 * q2 + 1] = *(uint32_t*)&h1v;
            }
#pragma unroll
            for (int ndp = 0; ndp < 8; ndp++) {
                uint32_t bv[4];
                LDSM4T(bv, sV + adr128(k2 * 16 + vr_i, ndp * 2 + vc_i));
                MMA_H(o[ndp * 2],     aP, bv[0], bv[1]);
                MMA_H(o[ndp * 2 + 1], aP, bv[2], bv[3]);
            }
        }
        rs0 += __shfl_xor_sync(0xffffffffu, rs0, 1);
        rs0 += __shfl_xor_sync(0xffffffffu, rs0, 2);
        rs1 += __shfl_xor_sync(0xffffffffu, rs1, 1);
        rs1 += __shfl_xor_sync(0xffffffffu, rs1, 2);
        l0 = l0 * c0 + rs0;
        l1 = l1 * c1 + rs1;

        __syncthreads();
    }

    float il0 = 1.f / l0, il1 = 1.f / l1;
    size_t or0 = (size_t)(b * TSEQ + qs + w * 16 + (lane >> 2)) * CEMB + h * DHEAD;
    size_t or1 = or0 + (size_t)8 * CEMB;
#pragma unroll
    for (int nd = 0; nd < 16; nd++) {
        int col = nd * 8 + cbs;
        *(__half2*)(oh + or0 + col) = __floats2half2_rn(o[nd][0] * il0, o[nd][1] * il0);
        *(__half2*)(oh + or1 + col) = __floats2half2_rn(o[nd][2] * il1, o[nd][3] * il1);
    }
}

// ---------------------------------------------------------------------------
extern "C" void kernel_launch(void* const* d_in, const int* in_sizes, int n_in,
                              void* d_out, int out_size)
{
    const float* x  = (const float*)d_in[0];
    const float* Wq = (const float*)d_in[1];
    const float* bq = (const float*)d_in[2];
    const float* Wk = (const float*)d_in[3];
    const float* bk = (const float*)d_in[4];
    const float* Wv = (const float*)d_in[5];
    const float* bv = (const float*)d_in[6];
    const float* Wo = (const float*)d_in[7];
    const float* bo = (const float*)d_in[8];
    float* out = (float*)d_out;

    __half *xh, *qh, *kh, *vh, *oh, *wt, *wot;
    float2* rope;
    cudaGetSymbolAddress((void**)&xh,  g_xh);
    cudaGetSymbolAddress((void**)&qh,  g_qh);
    cudaGetSymbolAddress((void**)&kh,  g_kh);
    cudaGetSymbolAddress((void**)&vh,  g_vh);
    cudaGetSymbolAddress((void**)&oh,  g_oh);
    cudaGetSymbolAddress((void**)&wt,  g_WT);
    cudaGetSymbolAddress((void**)&wot, g_WoT);
    cudaGetSymbolAddress((void**)&rope, g_rope);

    const int QKV_SMEM = 68608;
    cudaFuncSetAttribute(gemm_qkv, cudaFuncAttributeMaxDynamicSharedMemorySize, QKV_SMEM);
    const int WO_SMEM = 66560;
    cudaFuncSetAttribute(gemm_wo, cudaFuncAttributeMaxDynamicSharedMemorySize, WO_SMEM);
    const int ATTN_SMEM = 99328;  // 32KB Q + 2*32KB KV + align
    cudaFuncSetAttribute(attn_mma, cudaFuncAttributeMaxDynamicSharedMemorySize, ATTN_SMEM);

    rope_table<<<(TSEQ * 64) / 256, 256>>>(rope);
    {
        int n4 = (MROWS * CEMB) / 4;
        conv_x<<<(n4 + 255) / 256, 256>>>(x, xh, n4);
    }
    tsplit_qkv<<<dim3(96, 64), dim3(32, 8)>>>(Wq, Wk, Wv, wt);
    tsplit_wo<<<dim3(64, 64), dim3(32, 8)>>>(Wo, wot);

    // fused QKV projection + rope + pack (1-term fp16)
    gemm_qkv<<<dim3(NQKV / 128, MROWS / 128), 256, QKV_SMEM>>>(
        xh, wt, bq, bk, bv, qh, kh, vh, rope);

    // flash attention (QT=128, KT=64)
    attn_mma<<<dim3(TSEQ / 128, 2 * NHEAD), 256, ATTN_SMEM>>>(qh, kh, vh, oh);

    // output projection (1-term fp16)
    gemm_wo<<<dim3(CEMB / 128, MROWS / 128), 256, WO_SMEM>>>(oh, wot, bo, out);
}

// round 11
// speedup vs baseline: 2.4733x; 1.0751x over previous
#include <cuda_runtime.h>
#include <cuda_fp16.h>
#include <math.h>
#include <stdint.h>

// Problem constants
#define MROWS 4096   // B*T
#define CEMB  2048
#define TSEQ  2048
#define NHEAD 16
#define NGROUP 4
#define DHEAD 128
#define KVC   512
#define SWIN  512
#define SINK  4
#define NQKV  3072

// scratch (all fp16)
__device__ __half g_xh [(size_t)MROWS * CEMB];
__device__ __half g_oh [(size_t)MROWS * CEMB];
__device__ __half g_qh [(size_t)MROWS * CEMB];          // [b,h,t,d] pre-scaled
__device__ __half g_kh [(size_t)MROWS * KVC];           // [b,g,t,d]
__device__ __half g_vh [(size_t)MROWS * KVC];
__device__ __half g_WT [(size_t)NQKV * CEMB];           // packed Wq|Wk|Wv, [N,K]
__device__ __half g_WoT[(size_t)CEMB * CEMB];
__device__ float2 g_rope[(size_t)TSEQ * 64];

// ---------------------------------------------------------------------------
// helpers
// ---------------------------------------------------------------------------
__device__ __forceinline__ uint32_t cvta_s(const void* p) {
    return (uint32_t)__cvta_generic_to_shared(p);
}
__device__ __forceinline__ void cp16(uint32_t dst, const void* src) {
    asm volatile("cp.async.cg.shared.global [%0], [%1], 16;\n" :: "r"(dst), "l"(src));
}
#define CP_COMMIT() asm volatile("cp.async.commit_group;\n" ::: "memory")
#define CP_WAIT(n)  asm volatile("cp.async.wait_group %0;\n" :: "n"(n) : "memory")

#define LDSM4(r, addr) \
    asm volatile("ldmatrix.sync.aligned.m8n8.x4.shared.b16 {%0,%1,%2,%3}, [%4];" \
        : "=r"((r)[0]), "=r"((r)[1]), "=r"((r)[2]), "=r"((r)[3]) : "r"(addr))

#define LDSM4T(r, addr) \
    asm volatile("ldmatrix.sync.aligned.m8n8.x4.trans.shared.b16 {%0,%1,%2,%3}, [%4];" \
        : "=r"((r)[0]), "=r"((r)[1]), "=r"((r)[2]), "=r"((r)[3]) : "r"(addr))

#define MMA_H(c, a, b0, b1) \
    asm volatile("mma.sync.aligned.m16n8k16.row.col.f32.f16.f16.f32 " \
        "{%0,%1,%2,%3},{%4,%5,%6,%7},{%8,%9},{%0,%1,%2,%3};" \
        : "+f"((c)[0]), "+f"((c)[1]), "+f"((c)[2]), "+f"((c)[3]) \
        : "r"((a)[0]), "r"((a)[1]), "r"((a)[2]), "r"((a)[3]), "r"(b0), "r"(b1))

// 128B-row swizzled address (BK=64 GEMM tiles): row r (0..127), 16B chunk c (0..7)
__device__ __forceinline__ uint32_t adrK(int r, int c) {
    return (uint32_t)(r * 128 + ((c ^ (r & 7)) << 4));
}
// 256B-row swizzled address (attention tiles): row r, 16B chunk c (0..15)
__device__ __forceinline__ uint32_t adr128(int r, int c) {
    return (uint32_t)(r * 256 + ((c ^ (r & 7)) << 4));
}

// ---------------------------------------------------------------------------
// prep: rope table (blocks [0,512)) + x fp32->fp16 (blocks [512, 512+8192))
// ---------------------------------------------------------------------------
__global__ void prep(const float* __restrict__ x, __half* __restrict__ xh,
                     float2* __restrict__ tab)
{
    int bid = blockIdx.x;
    if (bid < 512) {
        int i = bid * 256 + threadIdx.x;   // < 2048*64
        int d = i & 63, t = i >> 6;
        float inv = powf(10000.f, -(float)d * (1.f / 64.f));
        float s, c;
        sincosf((float)t * inv, &s, &c);
        tab[i] = make_float2(c, s);
    } else {
        int i = (bid - 512) * 256 + threadIdx.x;  // < MROWS*CEMB/4
        float4 v = ((const float4*)x)[i];
        __half2* p = (__half2*)xh;
        p[i * 2 + 0] = __floats2half2_rn(v.x, v.y);
        p[i * 2 + 1] = __floats2half2_rn(v.z, v.w);
    }
}

// ---------------------------------------------------------------------------
// transpose QKV weights -> fp16 single (packed rows)
// ---------------------------------------------------------------------------
__global__ void tsplit_qkv(const float* __restrict__ Wq,
                           const float* __restrict__ Wk,
                           const float* __restrict__ Wv,
                           __half* __restrict__ hi)
{
    __shared__ float t[32][33];
    int bx = blockIdx.x, k0 = blockIdx.y * 32;
    const float* W; int N, n0, ro;
    if (bx < 64)      { W = Wq; N = 2048; n0 = bx * 32;        ro = 0; }
    else if (bx < 80) { W = Wk; N = 512;  n0 = (bx - 64) * 32; ro = 2048; }
    else              { W = Wv; N = 512;  n0 = (bx - 80) * 32; ro = 2560; }
    int tx = threadIdx.x, ty = threadIdx.y;
#pragma unroll
    for (int i = 0; i < 4; i++)
        t[ty + 8 * i][tx] = W[(size_t)(k0 + ty + 8 * i) * N + n0 + tx];
    __syncthreads();
#pragma unroll
    for (int i = 0; i < 4; i++)
        hi[(size_t)(ro + n0 + ty + 8 * i) * CEMB + k0 + tx] =
            __float2half_rn(t[tx][ty + 8 * i]);
}

// ---------------------------------------------------------------------------
// transpose Wo -> fp16 single
// ---------------------------------------------------------------------------
__global__ void tsplit_wo(const float* __restrict__ W, __half* __restrict__ hi)
{
    __shared__ float t[32][33];
    int n0 = blockIdx.x * 32, k0 = blockIdx.y * 32;
    int tx = threadIdx.x, ty = threadIdx.y;
#pragma unroll
    for (int i = 0; i < 4; i++)
        t[ty + 8 * i][tx] = W[(size_t)(k0 + ty + 8 * i) * CEMB + n0 + tx];
    __syncthreads();
#pragma unroll
    for (int i = 0; i < 4; i++)
        hi[(size_t)(n0 + ty + 8 * i) * CEMB + k0 + tx] =
            __float2half_rn(t[tx][ty + 8 * i]);
}

// ---------------------------------------------------------------------------
// QKV GEMM: 1-term fp16, BK=64, 3-stage pipeline. Fused bias+rope+pack.
// ---------------------------------------------------------------------------
__global__ __launch_bounds__(256, 2) void gemm_qkv(
    const __half* __restrict__ A, const __half* __restrict__ B,
    const float* __restrict__ bq, const float* __restrict__ bk,
    const float* __restrict__ bv,
    __half* __restrict__ qh, __half* __restrict__ kh, __half* __restrict__ vh,
    const float2* __restrict__ rope)
{
    constexpr int KD = 2048, NCHUNK = 32, STG = 32768, PITCH = 132;
    extern __shared__ char dsm[];
    uint32_t sbase = (cvta_s(dsm) + 1023) & ~1023u;

    const int tid = threadIdx.x;
    const int wid = tid >> 5, lane = tid & 31;
    const int wm = wid >> 2, wn = wid & 3;
    const int m0 = blockIdx.y * 128, n0 = blockIdx.x * 128;

    // per-thread cp.async slots: 4 A + 4 B 16B chunks per stage
    uint32_t dsts[4];
    size_t gA[4], gB[4];
#pragma unroll
    for (int p = 0; p < 4; p++) {
        int idx = tid + p * 256;
        int r = idx >> 3, c = idx & 7;
        dsts[p] = adrK(r, c);
        gA[p] = (size_t)(m0 + r) * KD + c * 8;
        gB[p] = (size_t)(n0 + r) * KD + c * 8;
    }

    const int arow = (lane & 7) + ((lane >> 3) & 1) * 8;
    const int acb  = lane >> 4;
    const int brow = (lane & 7) + (lane >> 4) * 8;
    const int bcb  = (lane >> 3) & 1;
    const int cbs  = (lane & 3) * 2;

    float acc[4][4][4];
#pragma unroll
    for (int i = 0; i < 4; i++)
#pragma unroll
        for (int j = 0; j < 4; j++) {
            acc[i][j][0] = 0.f; acc[i][j][1] = 0.f;
            acc[i][j][2] = 0.f; acc[i][j][3] = 0.f;
        }

#pragma unroll
    for (int ch = 0; ch < 2; ch++) {
        uint32_t st = sbase + ch * STG;
        int k0 = ch * 64;
#pragma unroll
        for (int p = 0; p < 4; p++) {
            cp16(st +     0 + dsts[p], A + gA[p] + k0);
            cp16(st + 16384 + dsts[p], B + gB[p] + k0);
        }
        CP_COMMIT();
    }

    for (int c = 0; c < NCHUNK; c++) {
        if (c + 2 < NCHUNK) {
            int ch = c + 2;
            uint32_t st = sbase + (ch % 3) * STG;
            int k0 = ch * 64;
#pragma unroll
            for (int p = 0; p < 4; p++) {
                cp16(st +     0 + dsts[p], A + gA[p] + k0);
                cp16(st + 16384 + dsts[p], B + gB[p] + k0);
            }
            CP_COMMIT();
            CP_WAIT(2);
        } else if (c + 1 < NCHUNK) {
            CP_WAIT(1);
        } else {
            CP_WAIT(0);
        }
        __syncthreads();

        uint32_t st = sbase + (c % 3) * STG;
        uint32_t aB = st, bB = st + 16384;

#pragma unroll
        for (int ks = 0; ks < 4; ks++) {
            uint32_t ah[4][4], bh[2][4];
#pragma unroll
            for (int mt = 0; mt < 4; mt++)
                LDSM4(ah[mt], aB + adrK(wm * 64 + mt * 16 + arow, 2 * ks + acb));
#pragma unroll
            for (int np = 0; np < 2; np++)
                LDSM4(bh[np], bB + adrK(wn * 32 + np * 16 + brow, 2 * ks + bcb));
#pragma unroll
            for (int mt = 0; mt < 4; mt++)
#pragma unroll
                for (int nt = 0; nt < 4; nt++)
                    MMA_H(acc[mt][nt], ah[mt], bh[nt >> 1][(nt & 1) * 2],
                          bh[nt >> 1][(nt & 1) * 2 + 1]);
        }
        __syncthreads();
    }

    // fused epilogue via smem fp32 staging
    const float* bias = (n0 < 2048) ? bq + n0
                      : (n0 < 2560) ? bk + (n0 - 2048)
                                    : bv + (n0 - 2560);
    float* s = (float*)((((uintptr_t)dsm) + 1023) & ~(uintptr_t)1023);

#pragma unroll
    for (int mt = 0; mt < 4; mt++) {
        int rl = wm * 64 + mt * 16 + (lane >> 2);
#pragma unroll
        for (int nt = 0; nt < 4; nt++) {
            int cl = wn * 32 + nt * 8 + cbs;
            float bb0 = bias[cl], bb1 = bias[cl + 1];
            s[rl * PITCH + cl]           = acc[mt][nt][0] + bb0;
            s[rl * PITCH + cl + 1]       = acc[mt][nt][1] + bb1;
            s[(rl + 8) * PITCH + cl]     = acc[mt][nt][2] + bb0;
            s[(rl + 8) * PITCH + cl + 1] = acc[mt][nt][3] + bb1;
        }
    }
    __syncthreads();

    if (n0 < 2560) {
        const bool isQ = (n0 < 2048);
        const float qsc = isQ ? 0.08838834764831845f : 1.0f;
        const int hh = isQ ? (n0 >> 7) : ((n0 - 2048) >> 7);
        const int nh = isQ ? NHEAD : NGROUP;
        __half* Out = isQ ? qh : kh;
#pragma unroll 4
        for (int idx = tid; idx < 128 * 32; idx += 256) {
            int r = idx >> 5, d2 = idx & 31;
            int m = m0 + r, t = m & (TSEQ - 1), b = m >> 11;
            int d0 = d2 * 2;
            float x1a = s[r * PITCH + d0],      x1b = s[r * PITCH + d0 + 1];
            float x2a = s[r * PITCH + d0 + 64], x2b = s[r * PITCH + d0 + 65];
            float2 ca = rope[t * 64 + d0], cb = rope[t * 64 + d0 + 1];
            float y1a = (x1a * ca.x - x2a * ca.y) * qsc;
            float y2a = (x1a * ca.y + x2a * ca.x) * qsc;
            float y1b = (x1b * cb.x - x2b * cb.y) * qsc;
            float y2b = (x1b * cb.y + x2b * cb.x) * qsc;
            size_t orow = ((size_t)(b * nh + hh) * TSEQ + t) * DHEAD;
            *(__half2*)(Out + orow + d0)      = __floats2half2_rn(y1a, y1b);
            *(__half2*)(Out + orow + 64 + d0) = __floats2half2_rn(y2a, y2b);
        }
    } else {
        const int g = (n0 - 2560) >> 7;
#pragma unroll 4
        for (int idx = tid; idx < 128 * 64; idx += 256) {
            int r = idx >> 6, c2 = idx & 63;
            int m = m0 + r, t = m & (TSEQ - 1), b = m >> 11;
            int c0 = c2 * 2;
            size_t o = ((size_t)(b * NGROUP + g) * TSEQ + t) * DHEAD + c0;
            *(__half2*)(vh + o) =
                __floats2half2_rn(s[r * PITCH + c0], s[r * PITCH + c0 + 1]);
        }
    }
}

// ---------------------------------------------------------------------------
// Wo GEMM: 1-term fp16, BK=64, 3-stage, fp32 out.
// ---------------------------------------------------------------------------
__global__ __launch_bounds__(256, 2) void gemm_wo(
    const __half* __restrict__ A, const __half* __restrict__ B,
    const float* __restrict__ bias, float* __restrict__ C)
{
    constexpr int KD = 2048, NCHUNK = 32, STG = 32768;
    extern __shared__ char dsm[];
    uint32_t sbase = (cvta_s(dsm) + 1023) & ~1023u;

    const int tid = threadIdx.x;
    const int wid = tid >> 5, lane = tid & 31;
    const int wm = wid >> 2, wn = wid & 3;
    const int m0 = blockIdx.y * 128, n0 = blockIdx.x * 128;

    uint32_t dsts[4];
    size_t gA[4], gB[4];
#pragma unroll
    for (int p = 0; p < 4; p++) {
        int idx = tid + p * 256;
        int r = idx >> 3, c = idx & 7;
        dsts[p] = adrK(r, c);
        gA[p] = (size_t)(m0 + r) * KD + c * 8;
        gB[p] = (size_t)(n0 + r) * KD + c * 8;
    }

    const int arow = (lane & 7) + ((lane >> 3) & 1) * 8;
    const int acb  = lane >> 4;
    const int brow = (lane & 7) + (lane >> 4) * 8;
    const int bcb  = (lane >> 3) & 1;

    float acc[4][4][4];
#pragma unroll
    for (int i = 0; i < 4; i++)
#pragma unroll
        for (int j = 0; j < 4; j++) {
            acc[i][j][0] = 0.f; acc[i][j][1] = 0.f;
            acc[i][j][2] = 0.f; acc[i][j][3] = 0.f;
        }

#pragma unroll
    for (int ch = 0; ch < 2; ch++) {
        uint32_t st = sbase + ch * STG;
        int k0 = ch * 64;
#pragma unroll
        for (int p = 0; p < 4; p++) {
            cp16(st +     0 + dsts[p], A + gA[p] + k0);
            cp16(st + 16384 + dsts[p], B + gB[p] + k0);
        }
        CP_COMMIT();
    }

    for (int c = 0; c < NCHUNK; c++) {
        if (c + 2 < NCHUNK) {
            int ch = c + 2;
            uint32_t st = sbase + (ch % 3) * STG;
            int k0 = ch * 64;
#pragma unroll
            for (int p = 0; p < 4; p++) {
                cp16(st +     0 + dsts[p], A + gA[p] + k0);
                cp16(st + 16384 + dsts[p], B + gB[p] + k0);
            }
            CP_COMMIT();
            CP_WAIT(2);
        } else if (c + 1 < NCHUNK) {
            CP_WAIT(1);
        } else {
            CP_WAIT(0);
        }
        __syncthreads();

        uint32_t st = sbase + (c % 3) * STG;
        uint32_t aB = st, bB = st + 16384;

#pragma unroll
        for (int ks = 0; ks < 4; ks++) {
            uint32_t ah[4][4], bh[2][4];
#pragma unroll
            for (int mt = 0; mt < 4; mt++)
                LDSM4(ah[mt], aB + adrK(wm * 64 + mt * 16 + arow, 2 * ks + acb));
#pragma unroll
            for (int np = 0; np < 2; np++)
                LDSM4(bh[np], bB + adrK(wn * 32 + np * 16 + brow, 2 * ks + bcb));
#pragma unroll
            for (int mt = 0; mt < 4; mt++)
#pragma unroll
                for (int nt = 0; nt < 4; nt++)
                    MMA_H(acc[mt][nt], ah[mt], bh[nt >> 1][(nt & 1) * 2],
                          bh[nt >> 1][(nt & 1) * 2 + 1]);
        }
        __syncthreads();
    }

#pragma unroll
    for (int mt = 0; mt < 4; mt++) {
        int r0 = m0 + wm * 64 + mt * 16 + (lane >> 2);
#pragma unroll
        for (int nt = 0; nt < 4; nt++) {
            int cc = n0 + wn * 32 + nt * 8 + (lane & 3) * 2;
            float bb0 = bias[cc], bb1 = bias[cc + 1];
            float2 v0 = make_float2(acc[mt][nt][0] + bb0, acc[mt][nt][1] + bb1);
            float2 v1 = make_float2(acc[mt][nt][2] + bb0, acc[mt][nt][3] + bb1);
            *(float2*)(C + (size_t)r0 * CEMB + cc) = v0;
            *(float2*)(C + (size_t)(r0 + 8) * CEMB + cc) = v1;
        }
    }
}

// ---------------------------------------------------------------------------
// flash attention: QT=128, KT=64, double-buffered KV (unchanged from R10)
// ---------------------------------------------------------------------------
__global__ __launch_bounds__(256, 1) void attn_mma(
    const __half* __restrict__ qh_g, const __half* __restrict__ kh_g,
    const __half* __restrict__ vh_g, __half* __restrict__ oh)
{
    extern __shared__ char sm[];
    uint32_t sb = (cvta_s(sm) + 1023) & ~1023u;
    const uint32_t sQ  = sb;
    const uint32_t sKV = sb + 32768;

    const int tid = threadIdx.x, w = tid >> 5, lane = tid & 31;
    const int b = blockIdx.y >> 4, h = blockIdx.y & 15, g = h >> 2;
    const int qs = blockIdx.x * 128;

    {
        size_t qb = ((size_t)(b * NHEAD + h) * TSEQ + qs) * DHEAD;
#pragma unroll
        for (int p = 0; p < 8; p++) {
            int idx = tid + p * 256;
            int row = idx >> 4, ch = idx & 15;
            cp16(sQ + adr128(row, ch), qh_g + qb + (size_t)row * DHEAD + ch * 8);
        }
    }
    CP_COMMIT();

    int t0 = qs - SWIN; if (t0 < 0) t0 = 0;
    const int sink = (t0 > 0) ? 1 : 0;
    const int ntiles = sink + (qs + 128 - t0) / 64;
    const size_t kvbase = (size_t)(b * NGROUP + g) * TSEQ * DHEAD;

    {
        int ts = sink ? 0 : t0;
        size_t kb = kvbase + (size_t)ts * DHEAD;
#pragma unroll
        for (int p = 0; p < 4; p++) {
            int idx = tid + p * 256;
            int row = idx >> 4, ch = idx & 15;
            uint32_t d = adr128(row, ch);
            size_t s = kb + (size_t)row * DHEAD + ch * 8;
            cp16(sKV +     0 + d, kh_g + s);
            cp16(sKV + 16384 + d, vh_g + s);
        }
    }
    CP_COMMIT();

    const int arow = (lane & 7) + ((lane >> 3) & 1) * 8;
    const int acb  = lane >> 4;
    const int brow = (lane & 7) + (lane >> 4) * 8;
    const int bcb  = (lane >> 3) & 1;
    const int vr_i = ((lane >> 3) & 1) * 8 + (lane & 7);
    const int vc_i = lane >> 4;
    const int i0 = qs + w * 16 + (lane >> 2);
    const int i1 = i0 + 8;
    const int iwmin = qs + w * 16;
    const int iwmax = qs + w * 16 + 15;
    const int cbs = (lane & 3) * 2;

    CP_WAIT(1);
    __syncthreads();
    uint32_t qf[8][4];
#pragma unroll
    for (int kc = 0; kc < 8; kc++)
        LDSM4(qf[kc], sQ + adr128(w * 16 + arow, 2 * kc + acb));

    float o[16][4];
#pragma unroll
    for (int i = 0; i < 16; i++) { o[i][0] = 0.f; o[i][1] = 0.f; o[i][2] = 0.f; o[i][3] = 0.f; }
    float m0 = -1e30f, m1 = -1e30f, l0 = 0.f, l1 = 0.f;

    for (int it = 0; it < ntiles; it++) {
        const bool snk = (sink && it == 0);
        const int ts = snk ? 0 : t0 + (it - sink) * 64;
        const int n2max = snk ? 1 : 4;

        if (it + 1 < ntiles) {
            int tsn = t0 + (it + 1 - sink) * 64;
            uint32_t st = sKV + ((it + 1) & 1) * 32768;
            size_t kb = kvbase + (size_t)tsn * DHEAD;
#pragma unroll
            for (int p = 0; p < 4; p++) {
                int idx = tid + p * 256;
                int row = idx >> 4, ch = idx & 15;
                uint32_t d = adr128(row, ch);
                size_t s = kb + (size_t)row * DHEAD + ch * 8;
                cp16(st +     0 + d, kh_g + s);
                cp16(st + 16384 + d, vh_g + s);
            }
            CP_COMMIT();
            CP_WAIT(1);
        } else {
            CP_WAIT(0);
        }
        __syncthreads();

        uint32_t stg = sKV + (it & 1) * 32768;
        uint32_t sK = stg, sV = stg + 16384;

        float sc[8][4];
#pragma unroll
        for (int i = 0; i < 8; i++) { sc[i][0] = 0.f; sc[i][1] = 0.f; sc[i][2] = 0.f; sc[i][3] = 0.f; }

        for (int n2 = 0; n2 < n2max; n2++) {
            if (ts + n2 * 16 > iwmax) break;
#pragma unroll
            for (int kc = 0; kc < 8; kc++) {
                uint32_t kf[4];
                LDSM4(kf, sK + adr128(n2 * 16 + brow, 2 * kc + bcb));
                MMA_H(sc[2 * n2],     qf[kc], kf[0], kf[1]);
                MMA_H(sc[2 * n2 + 1], qf[kc], kf[2], kf[3]);
            }
        }

        float rm0 = -1e30f, rm1 = -1e30f;
        const bool full = (!snk) && (ts + 63 <= iwmin) && (ts >= iwmax - SWIN);
        if (full) {
#pragma unroll
            for (int nt = 0; nt < 8; nt++) {
                rm0 = fmaxf(rm0, fmaxf(sc[nt][0], sc[nt][1]));
                rm1 = fmaxf(rm1, fmaxf(sc[nt][2], sc[nt][3]));
            }
        } else {
#pragma unroll
            for (int nt = 0; nt < 8; nt++) {
                int j0 = ts + nt * 8 + cbs, j1 = j0 + 1;
                sc[nt][0] = (j0 <= i0 && (j0 >= i0 - SWIN || j0 < SINK)) ? sc[nt][0] : -1e30f;
                sc[nt][1] = (j1 <= i0 && (j1 >= i0 - SWIN || j1 < SINK)) ? sc[nt][1] : -1e30f;
                sc[nt][2] = (j0 <= i1 && (j0 >= i1 - SWIN || j0 < SINK)) ? sc[nt][2] : -1e30f;
                sc[nt][3] = (j1 <= i1 && (j1 >= i1 - SWIN || j1 < SINK)) ? sc[nt][3] : -1e30f;
                rm0 = fmaxf(rm0, fmaxf(sc[nt][0], sc[nt][1]));
                rm1 = fmaxf(rm1, fmaxf(sc[nt][2], sc[nt][3]));
            }
        }
        rm0 = fmaxf(rm0, __shfl_xor_sync(0xffffffffu, rm0, 1));
        rm0 = fmaxf(rm0, __shfl_xor_sync(0xffffffffu, rm0, 2));
        rm1 = fmaxf(rm1, __shfl_xor_sync(0xffffffffu, rm1, 1));
        rm1 = fmaxf(rm1, __shfl_xor_sync(0xffffffffu, rm1, 2));
        float mn0 = fmaxf(m0, rm0), mn1 = fmaxf(m1, rm1);
        float c0 = __expf(m0 - mn0), c1 = __expf(m1 - mn1);
        m0 = mn0; m1 = mn1;

        if (c0 != 1.f || c1 != 1.f) {
#pragma unroll
            for (int nd = 0; nd < 16; nd++) {
                o[nd][0] *= c0; o[nd][1] *= c0; o[nd][2] *= c1; o[nd][3] *= c1;
            }
        }

        float rs0 = 0.f, rs1 = 0.f;
        for (int k2 = 0; k2 < n2max; k2++) {
            if (ts + k2 * 16 > iwmax) break;
            uint32_t aP[4];
#pragma unroll
            for (int q2 = 0; q2 < 2; q2++) {
                int nt = 2 * k2 + q2;
                float p00 = __expf(sc[nt][0] - mn0), p01 = __expf(sc[nt][1] - mn0);
                float p10 = __expf(sc[nt][2] - mn1), p11 = __expf(sc[nt][3] - mn1);
                rs0 += p00 + p01; rs1 += p10 + p11;
                __half2 h0v = __floats2half2_rn(p00, p01);
                __half2 h1v = __floats2half2_rn(p10, p11);
                aP[2 * q2]     = *(uint32_t*)&h0v;
                aP[2 * q2 + 1] = *(uint32_t*)&h1v;
            }
#pragma unroll
            for (int ndp = 0; ndp < 8; ndp++) {
                uint32_t bv[4];
                LDSM4T(bv, sV + adr128(k2 * 16 + vr_i, ndp * 2 + vc_i));
                MMA_H(o[ndp * 2],     aP, bv[0], bv[1]);
                MMA_H(o[ndp * 2 + 1], aP, bv[2], bv[3]);
            }
        }
        rs0 += __shfl_xor_sync(0xffffffffu, rs0, 1);
        rs0 += __shfl_xor_sync(0xffffffffu, rs0, 2);
        rs1 += __shfl_xor_sync(0xffffffffu, rs1, 1);
        rs1 += __shfl_xor_sync(0xffffffffu, rs1, 2);
        l0 = l0 * c0 + rs0;
        l1 = l1 * c1 + rs1;

        __syncthreads();
    }

    float il0 = 1.f / l0, il1 = 1.f / l1;
    size_t or0 = (size_t)(b * TSEQ + qs + w * 16 + (lane >> 2)) * CEMB + h * DHEAD;
    size_t or1 = or0 + (size_t)8 * CEMB;
#pragma unroll
    for (int nd = 0; nd < 16; nd++) {
        int col = nd * 8 + cbs;
        *(__half2*)(oh + or0 + col) = __floats2half2_rn(o[nd][0] * il0, o[nd][1] * il0);
        *(__half2*)(oh + or1 + col) = __floats2half2_rn(o[nd][2] * il1, o[nd][3] * il1);
    }
}

// ---------------------------------------------------------------------------
extern "C" void kernel_launch(void* const* d_in, const int* in_sizes, int n_in,
                              void* d_out, int out_size)
{
    const float* x  = (const float*)d_in[0];
    const float* Wq = (const float*)d_in[1];
    const float* bq = (const float*)d_in[2];
    const float* Wk = (const float*)d_in[3];
    const float* bk = (const float*)d_in[4];
    const float* Wv = (const float*)d_in[5];
    const float* bv = (const float*)d_in[6];
    const float* Wo = (const float*)d_in[7];
    const float* bo = (const float*)d_in[8];
    float* out = (float*)d_out;

    __half *xh, *qh, *kh, *vh, *oh, *wt, *wot;
    float2* rope;
    cudaGetSymbolAddress((void**)&xh,  g_xh);
    cudaGetSymbolAddress((void**)&qh,  g_qh);
    cudaGetSymbolAddress((void**)&kh,  g_kh);
    cudaGetSymbolAddress((void**)&vh,  g_vh);
    cudaGetSymbolAddress((void**)&oh,  g_oh);
    cudaGetSymbolAddress((void**)&wt,  g_WT);
    cudaGetSymbolAddress((void**)&wot, g_WoT);
    cudaGetSymbolAddress((void**)&rope, g_rope);

    const int GEMM_SMEM = 99328;   // 3*32KB + align (staging 67.6KB fits)
    cudaFuncSetAttribute(gemm_qkv, cudaFuncAttributeMaxDynamicSharedMemorySize, GEMM_SMEM);
    cudaFuncSetAttribute(gemm_wo,  cudaFuncAttributeMaxDynamicSharedMemorySize, GEMM_SMEM);
    const int ATTN_SMEM = 99328;   // 32KB Q + 2*32KB KV + align
    cudaFuncSetAttribute(attn_mma, cudaFuncAttributeMaxDynamicSharedMemorySize, ATTN_SMEM);

    // (0) prep: rope table + x convert
    prep<<<512 + (MROWS * CEMB / 4) / 256, 256>>>(x, xh, rope);
    // (1) QKV weights  (2) Wo weights
    tsplit_qkv<<<dim3(96, 64), dim3(32, 8)>>>(Wq, Wk, Wv, wt);
    tsplit_wo<<<dim3(64, 64), dim3(32, 8)>>>(Wo, wot);

    // (3) fused QKV projection + rope + pack  ← ncu capture slot
    gemm_qkv<<<dim3(NQKV / 128, MROWS / 128), 256, GEMM_SMEM>>>(
        xh, wt, bq, bk, bv, qh, kh, vh, rope);

    // (4) flash attention
    attn_mma<<<dim3(TSEQ / 128, 2 * NHEAD), 256, ATTN_SMEM>>>(qh, kh, vh, oh);

    // (5) output projection
    gemm_wo<<<dim3(CEMB / 128, MROWS / 128), 256, GEMM_SMEM>>>(oh, wot, bo, out);
}

// round 12
// speedup vs baseline: 2.5549x; 1.0330x over previous
#include <cuda_runtime.h>
#include <cuda_fp16.h>
#include <math.h>
#include <stdint.h>

// Problem constants
#define MROWS 4096   // B*T
#define CEMB  2048
#define TSEQ  2048
#define NHEAD 16
#define NGROUP 4
#define DHEAD 128
#define KVC   512
#define SWIN  512
#define SINK  4
#define NQKV  3072

// scratch (all fp16)
__device__ __half g_xh [(size_t)MROWS * CEMB];
__device__ __half g_oh [(size_t)MROWS * CEMB];
__device__ __half g_qh [(size_t)MROWS * CEMB];          // [b,h,t,d] pre-scaled
__device__ __half g_kh [(size_t)MROWS * KVC];           // [b,g,t,d]
__device__ __half g_vh [(size_t)MROWS * KVC];
__device__ __half g_WT [(size_t)NQKV * CEMB];           // packed Wq|Wk|Wv, [N,K]
__device__ __half g_WoT[(size_t)CEMB * CEMB];
__device__ float2 g_rope[(size_t)TSEQ * 64];

// ---------------------------------------------------------------------------
// helpers
// ---------------------------------------------------------------------------
__device__ __forceinline__ uint32_t cvta_s(const void* p) {
    return (uint32_t)__cvta_generic_to_shared(p);
}
__device__ __forceinline__ void cp16(uint32_t dst, const void* src) {
    asm volatile("cp.async.cg.shared.global [%0], [%1], 16;\n" :: "r"(dst), "l"(src));
}
#define CP_COMMIT() asm volatile("cp.async.commit_group;\n" ::: "memory")
#define CP_WAIT(n)  asm volatile("cp.async.wait_group %0;\n" :: "n"(n) : "memory")

#define LDSM4(r, addr) \
    asm volatile("ldmatrix.sync.aligned.m8n8.x4.shared.b16 {%0,%1,%2,%3}, [%4];" \
        : "=r"((r)[0]), "=r"((r)[1]), "=r"((r)[2]), "=r"((r)[3]) : "r"(addr))

#define LDSM4T(r, addr) \
    asm volatile("ldmatrix.sync.aligned.m8n8.x4.trans.shared.b16 {%0,%1,%2,%3}, [%4];" \
        : "=r"((r)[0]), "=r"((r)[1]), "=r"((r)[2]), "=r"((r)[3]) : "r"(addr))

#define MMA_H(c, a, b0, b1) \
    asm volatile("mma.sync.aligned.m16n8k16.row.col.f32.f16.f16.f32 " \
        "{%0,%1,%2,%3},{%4,%5,%6,%7},{%8,%9},{%0,%1,%2,%3};" \
        : "+f"((c)[0]), "+f"((c)[1]), "+f"((c)[2]), "+f"((c)[3]) \
        : "r"((a)[0]), "r"((a)[1]), "r"((a)[2]), "r"((a)[3]), "r"(b0), "r"(b1))

// 128B-row swizzled address (BK=64 GEMM tiles): row r (0..127), 16B chunk c (0..7)
__device__ __forceinline__ uint32_t adrK(int r, int c) {
    return (uint32_t)(r * 128 + ((c ^ (r & 7)) << 4));
}
// 256B-row swizzled address (attention tiles): row r, 16B chunk c (0..15)
__device__ __forceinline__ uint32_t adr128(int r, int c) {
    return (uint32_t)(r * 256 + ((c ^ (r & 7)) << 4));
}

// ---------------------------------------------------------------------------
// prep: rope table (blocks [0,512)) + x fp32->fp16 (blocks [512, 512+4096))
// ---------------------------------------------------------------------------
__global__ void prep(const float* __restrict__ x, __half* __restrict__ xh,
                     float2* __restrict__ tab)
{
    int bid = blockIdx.x;
    if (bid < 512) {
        int i = bid * 256 + threadIdx.x;
        int d = i & 63, t = i >> 6;
        float inv = powf(10000.f, -(float)d * (1.f / 64.f));
        float s, c;
        sincosf((float)t * inv, &s, &c);
        tab[i] = make_float2(c, s);
    } else {
        int i = (bid - 512) * 256 + threadIdx.x;
        float4 v = ((const float4*)x)[i];
        __half2* p = (__half2*)xh;
        p[i * 2 + 0] = __floats2half2_rn(v.x, v.y);
        p[i * 2 + 1] = __floats2half2_rn(v.z, v.w);
    }
}

// ---------------------------------------------------------------------------
// transpose QKV weights -> fp16 single (packed rows)
// ---------------------------------------------------------------------------
__global__ void tsplit_qkv(const float* __restrict__ Wq,
                           const float* __restrict__ Wk,
                           const float* __restrict__ Wv,
                           __half* __restrict__ hi)
{
    __shared__ float t[32][33];
    int bx = blockIdx.x, k0 = blockIdx.y * 32;
    const float* W; int N, n0, ro;
    if (bx < 64)      { W = Wq; N = 2048; n0 = bx * 32;        ro = 0; }
    else if (bx < 80) { W = Wk; N = 512;  n0 = (bx - 64) * 32; ro = 2048; }
    else              { W = Wv; N = 512;  n0 = (bx - 80) * 32; ro = 2560; }
    int tx = threadIdx.x, ty = threadIdx.y;
#pragma unroll
    for (int i = 0; i < 4; i++)
        t[ty + 8 * i][tx] = W[(size_t)(k0 + ty + 8 * i) * N + n0 + tx];
    __syncthreads();
#pragma unroll
    for (int i = 0; i < 4; i++)
        hi[(size_t)(ro + n0 + ty + 8 * i) * CEMB + k0 + tx] =
            __float2half_rn(t[tx][ty + 8 * i]);
}

// ---------------------------------------------------------------------------
// transpose Wo -> fp16 single
// ---------------------------------------------------------------------------
__global__ void tsplit_wo(const float* __restrict__ W, __half* __restrict__ hi)
{
    __shared__ float t[32][33];
    int n0 = blockIdx.x * 32, k0 = blockIdx.y * 32;
    int tx = threadIdx.x, ty = threadIdx.y;
#pragma unroll
    for (int i = 0; i < 4; i++)
        t[ty + 8 * i][tx] = W[(size_t)(k0 + ty + 8 * i) * CEMB + n0 + tx];
    __syncthreads();
#pragma unroll
    for (int i = 0; i < 4; i++)
        hi[(size_t)(n0 + ty + 8 * i) * CEMB + k0 + tx] =
            __float2half_rn(t[tx][ty + 8 * i]);
}

// ---------------------------------------------------------------------------
// QKV GEMM: 1-term fp16, BK=64, 3-stage, single barrier per chunk.
// Permuted B mapping: warp wn owns cols {wn*16..+16} u {64+wn*16..+16}
// so rope pairs (d, d+64) live in one thread -> register-direct epilogue.
// ---------------------------------------------------------------------------
__global__ __launch_bounds__(256, 2) void gemm_qkv(
    const __half* __restrict__ A, const __half* __restrict__ B,
    const float* __restrict__ bq, const float* __restrict__ bk,
    const float* __restrict__ bv,
    __half* __restrict__ qh, __half* __restrict__ kh, __half* __restrict__ vh,
    const float2* __restrict__ rope)
{
    constexpr int KD = 2048, NCHUNK = 32, STG = 32768;
    extern __shared__ char dsm[];
    uint32_t sbase = (cvta_s(dsm) + 1023) & ~1023u;

    const int tid = threadIdx.x;
    const int wid = tid >> 5, lane = tid & 31;
    const int wm = wid >> 2, wn = wid & 3;
    const int m0 = blockIdx.y * 128, n0 = blockIdx.x * 128;

    uint32_t dsts[4];
    size_t gA[4], gB[4];
#pragma unroll
    for (int p = 0; p < 4; p++) {
        int idx = tid + p * 256;
        int r = idx >> 3, c = idx & 7;
        dsts[p] = adrK(r, c);
        gA[p] = (size_t)(m0 + r) * KD + c * 8;
        gB[p] = (size_t)(n0 + r) * KD + c * 8;
    }

    const int arow = (lane & 7) + ((lane >> 3) & 1) * 8;
    const int acb  = lane >> 4;
    const int brow = (lane & 7) + (lane >> 4) * 8;
    const int bcb  = (lane >> 3) & 1;
    const int cbs  = (lane & 3) * 2;

    float acc[4][4][4];
#pragma unroll
    for (int i = 0; i < 4; i++)
#pragma unroll
        for (int j = 0; j < 4; j++) {
            acc[i][j][0] = 0.f; acc[i][j][1] = 0.f;
            acc[i][j][2] = 0.f; acc[i][j][3] = 0.f;
        }

#pragma unroll
    for (int ch = 0; ch < 2; ch++) {
        uint32_t st = sbase + ch * STG;
        int k0 = ch * 64;
#pragma unroll
        for (int p = 0; p < 4; p++) {
            cp16(st +     0 + dsts[p], A + gA[p] + k0);
            cp16(st + 16384 + dsts[p], B + gB[p] + k0);
        }
        CP_COMMIT();
    }

    for (int c = 0; c < NCHUNK; c++) {
        if (c + 1 < NCHUNK) { CP_WAIT(1); } else { CP_WAIT(0); }
        __syncthreads();
        if (c + 2 < NCHUNK) {
            int ch = c + 2;
            uint32_t st = sbase + (ch % 3) * STG;
            int k0 = ch * 64;
#pragma unroll
            for (int p = 0; p < 4; p++) {
                cp16(st +     0 + dsts[p], A + gA[p] + k0);
                cp16(st + 16384 + dsts[p], B + gB[p] + k0);
            }
            CP_COMMIT();
        }

        uint32_t st = sbase + (c % 3) * STG;
        uint32_t aB = st, bB = st + 16384;

#pragma unroll
        for (int ks = 0; ks < 4; ks++) {
            uint32_t ah[4][4], bh[2][4];
#pragma unroll
            for (int mt = 0; mt < 4; mt++)
                LDSM4(ah[mt], aB + adrK(wm * 64 + mt * 16 + arow, 2 * ks + acb));
            // permuted B rows: np=0 -> cols wn*16.., np=1 -> cols 64+wn*16..
#pragma unroll
            for (int np = 0; np < 2; np++)
                LDSM4(bh[np], bB + adrK(wn * 16 + np * 64 + brow, 2 * ks + bcb));
#pragma unroll
            for (int mt = 0; mt < 4; mt++)
#pragma unroll
                for (int nt = 0; nt < 4; nt++)
                    MMA_H(acc[mt][nt], ah[mt], bh[nt >> 1][(nt & 1) * 2],
                          bh[nt >> 1][(nt & 1) * 2 + 1]);
        }
    }

    // register-direct epilogue
    const float* bias = (n0 < 2048) ? bq + n0
                      : (n0 < 2560) ? bk + (n0 - 2048)
                                    : bv + (n0 - 2560);

    if (n0 < 2560) {
        const bool isQ = (n0 < 2048);
        const float qsc = isQ ? 0.08838834764831845f : 1.0f;
        const int hh = isQ ? (n0 >> 7) : ((n0 - 2048) >> 7);
        const int nh = isQ ? NHEAD : NGROUP;
        __half* Out = isQ ? qh : kh;
#pragma unroll
        for (int mt = 0; mt < 4; mt++) {
            int rg = m0 + wm * 64 + mt * 16 + (lane >> 2);
            int tr = rg & (TSEQ - 1);
            int bb = rg >> 11;
            size_t orow0 = ((size_t)(bb * nh + hh) * TSEQ + tr) * DHEAD;
            size_t orow1 = orow0 + 8 * DHEAD;   // row +8 same batch
#pragma unroll
            for (int nt = 0; nt < 2; nt++) {
                int d0 = wn * 16 + nt * 8 + cbs;   // in [0,64)
                float bb1 = bias[d0],     bb2 = bias[d0 + 1];
                float bb3 = bias[d0 + 64], bb4 = bias[d0 + 65];
                float2 ca = rope[tr * 64 + d0], cb = rope[tr * 64 + d0 + 1];
                // row rg
                {
                    float x1a = acc[mt][nt][0] + bb1, x1b = acc[mt][nt][1] + bb2;
                    float x2a = acc[mt][nt + 2][0] + bb3, x2b = acc[mt][nt + 2][1] + bb4;
                    float y1a = (x1a * ca.x - x2a * ca.y) * qsc;
                    float y2a = (x1a * ca.y + x2a * ca.x) * qsc;
                    float y1b = (x1b * cb.x - x2b * cb.y) * qsc;
                    float y2b = (x1b * cb.y + x2b * cb.x) * qsc;
                    *(__half2*)(Out + orow0 + d0)      = __floats2half2_rn(y1a, y1b);
                    *(__half2*)(Out + orow0 + 64 + d0) = __floats2half2_rn(y2a, y2b);
                }
                // row rg + 8
                {
                    float2 ca8 = rope[(tr + 8) * 64 + d0];
                    float2 cb8 = rope[(tr + 8) * 64 + d0 + 1];
                    float x1a = acc[mt][nt][2] + bb1, x1b = acc[mt][nt][3] + bb2;
                    float x2a = acc[mt][nt + 2][2] + bb3, x2b = acc[mt][nt + 2][3] + bb4;
                    float y1a = (x1a * ca8.x - x2a * ca8.y) * qsc;
                    float y2a = (x1a * ca8.y + x2a * ca8.x) * qsc;
                    float y1b = (x1b * cb8.x - x2b * cb8.y) * qsc;
                    float y2b = (x1b * cb8.y + x2b * cb8.x) * qsc;
                    *(__half2*)(Out + orow1 + d0)      = __floats2half2_rn(y1a, y1b);
                    *(__half2*)(Out + orow1 + 64 + d0) = __floats2half2_rn(y2a, y2b);
                }
            }
        }
    } else {
        const int g = (n0 - 2560) >> 7;
#pragma unroll
        for (int mt = 0; mt < 4; mt++) {
            int rg = m0 + wm * 64 + mt * 16 + (lane >> 2);
            int tr = rg & (TSEQ - 1);
            int bb = rg >> 11;
            size_t orow0 = ((size_t)(bb * NGROUP + g) * TSEQ + tr) * DHEAD;
            size_t orow1 = orow0 + 8 * DHEAD;
#pragma unroll
            for (int nt = 0; nt < 4; nt++) {
                int d0 = wn * 16 + (nt >> 1) * 64 + (nt & 1) * 8 + cbs;
                float bb1 = bias[d0], bb2 = bias[d0 + 1];
                *(__half2*)(vh + orow0 + d0) =
                    __floats2half2_rn(acc[mt][nt][0] + bb1, acc[mt][nt][1] + bb2);
                *(__half2*)(vh + orow1 + d0) =
                    __floats2half2_rn(acc[mt][nt][2] + bb1, acc[mt][nt][3] + bb2);
            }
        }
    }
}

// ---------------------------------------------------------------------------
// Wo GEMM: 1-term fp16, BK=64, 3-stage, single barrier per chunk, fp32 out.
// ---------------------------------------------------------------------------
__global__ __launch_bounds__(256, 2) void gemm_wo(
    const __half* __restrict__ A, const __half* __restrict__ B,
    const float* __restrict__ bias, float* __restrict__ C)
{
    constexpr int KD = 2048, NCHUNK = 32, STG = 32768;
    extern __shared__ char dsm[];
    uint32_t sbase = (cvta_s(dsm) + 1023) & ~1023u;

    const int tid = threadIdx.x;
    const int wid = tid >> 5, lane = tid & 31;
    const int wm = wid >> 2, wn = wid & 3;
    const int m0 = blockIdx.y * 128, n0 = blockIdx.x * 128;

    uint32_t dsts[4];
    size_t gA[4], gB[4];
#pragma unroll
    for (int p = 0; p < 4; p++) {
        int idx = tid + p * 256;
        int r = idx >> 3, c = idx & 7;
        dsts[p] = adrK(r, c);
        gA[p] = (size_t)(m0 + r) * KD + c * 8;
        gB[p] = (size_t)(n0 + r) * KD + c * 8;
    }

    const int arow = (lane & 7) + ((lane >> 3) & 1) * 8;
    const int acb  = lane >> 4;
    const int brow = (lane & 7) + (lane >> 4) * 8;
    const int bcb  = (lane >> 3) & 1;

    float acc[4][4][4];
#pragma unroll
    for (int i = 0; i < 4; i++)
#pragma unroll
        for (int j = 0; j < 4; j++) {
            acc[i][j][0] = 0.f; acc[i][j][1] = 0.f;
            acc[i][j][2] = 0.f; acc[i][j][3] = 0.f;
        }

#pragma unroll
    for (int ch = 0; ch < 2; ch++) {
        uint32_t st = sbase + ch * STG;
        int k0 = ch * 64;
#pragma unroll
        for (int p = 0; p < 4; p++) {
            cp16(st +     0 + dsts[p], A + gA[p] + k0);
            cp16(st + 16384 + dsts[p], B + gB[p] + k0);
        }
        CP_COMMIT();
    }

    for (int c = 0; c < NCHUNK; c++) {
        if (c + 1 < NCHUNK) { CP_WAIT(1); } else { CP_WAIT(0); }
        __syncthreads();
        if (c + 2 < NCHUNK) {
            int ch = c + 2;
            uint32_t st = sbase + (ch % 3) * STG;
            int k0 = ch * 64;
#pragma unroll
            for (int p = 0; p < 4; p++) {
                cp16(st +     0 + dsts[p], A + gA[p] + k0);
                cp16(st + 16384 + dsts[p], B + gB[p] + k0);
            }
            CP_COMMIT();
        }

        uint32_t st = sbase + (c % 3) * STG;
        uint32_t aB = st, bB = st + 16384;

#pragma unroll
        for (int ks = 0; ks < 4; ks++) {
            uint32_t ah[4][4], bh[2][4];
#pragma unroll
            for (int mt = 0; mt < 4; mt++)
                LDSM4(ah[mt], aB + adrK(wm * 64 + mt * 16 + arow, 2 * ks + acb));
#pragma unroll
            for (int np = 0; np < 2; np++)
                LDSM4(bh[np], bB + adrK(wn * 32 + np * 16 + brow, 2 * ks + bcb));
#pragma unroll
            for (int mt = 0; mt < 4; mt++)
#pragma unroll
                for (int nt = 0; nt < 4; nt++)
                    MMA_H(acc[mt][nt], ah[mt], bh[nt >> 1][(nt & 1) * 2],
                          bh[nt >> 1][(nt & 1) * 2 + 1]);
        }
    }

#pragma unroll
    for (int mt = 0; mt < 4; mt++) {
        int r0 = m0 + wm * 64 + mt * 16 + (lane >> 2);
#pragma unroll
        for (int nt = 0; nt < 4; nt++) {
            int cc = n0 + wn * 32 + nt * 8 + (lane & 3) * 2;
            float bb0 = bias[cc], bb1 = bias[cc + 1];
            float2 v0 = make_float2(acc[mt][nt][0] + bb0, acc[mt][nt][1] + bb1);
            float2 v1 = make_float2(acc[mt][nt][2] + bb0, acc[mt][nt][3] + bb1);
            *(float2*)(C + (size_t)r0 * CEMB + cc) = v0;
            *(float2*)(C + (size_t)(r0 + 8) * CEMB + cc) = v1;
        }
    }
}

// ---------------------------------------------------------------------------
// flash attention: QT=128, KT=64, 3-stage KV, single barrier per tile.
// ---------------------------------------------------------------------------
__global__ __launch_bounds__(256, 1) void attn_mma(
    const __half* __restrict__ qh_g, const __half* __restrict__ kh_g,
    const __half* __restrict__ vh_g, __half* __restrict__ oh)
{
    extern __shared__ char sm[];
    uint32_t sb = (cvta_s(sm) + 1023) & ~1023u;
    const uint32_t sQ  = sb;            // 32KB
    const uint32_t sKV = sb + 32768;    // 3 stages x 32KB: K 16KB, V 16KB each

    const int tid = threadIdx.x, w = tid >> 5, lane = tid & 31;
    const int b = blockIdx.y >> 4, h = blockIdx.y & 15, g = h >> 2;
    const int qs = blockIdx.x * 128;

    int t0 = qs - SWIN; if (t0 < 0) t0 = 0;
    const int sink = (t0 > 0) ? 1 : 0;
    const int ntiles = sink + (qs + 128 - t0) / 64;   // >= 2 always
    const size_t kvbase = (size_t)(b * NGROUP + g) * TSEQ * DHEAD;

    // Q load (group 1)
    {
        size_t qb = ((size_t)(b * NHEAD + h) * TSEQ + qs) * DHEAD;
#pragma unroll
        for (int p = 0; p < 8; p++) {
            int idx = tid + p * 256;
            int row = idx >> 4, ch = idx & 15;
            cp16(sQ + adr128(row, ch), qh_g + qb + (size_t)row * DHEAD + ch * 8);
        }
    }
    CP_COMMIT();

    // KV tiles 0 and 1 (groups 2, 3)
#pragma unroll
    for (int j = 0; j < 2; j++) {
        int ts = (sink && j == 0) ? 0 : t0 + (j - sink) * 64;
        uint32_t st = sKV + j * 32768;
        size_t kb = kvbase + (size_t)ts * DHEAD;
#pragma unroll
        for (int p = 0; p < 4; p++) {
            int idx = tid + p * 256;
            int row = idx >> 4, ch = idx & 15;
            uint32_t d = adr128(row, ch);
            size_t s = kb + (size_t)row * DHEAD + ch * 8;
            cp16(st +     0 + d, kh_g + s);
            cp16(st + 16384 + d, vh_g + s);
        }
        CP_COMMIT();
    }

    const int arow = (lane & 7) + ((lane >> 3) & 1) * 8;
    const int acb  = lane >> 4;
    const int brow = (lane & 7) + (lane >> 4) * 8;
    const int bcb  = (lane >> 3) & 1;
    const int vr_i = ((lane >> 3) & 1) * 8 + (lane & 7);
    const int vc_i = lane >> 4;
    const int i0 = qs + w * 16 + (lane >> 2);
    const int i1 = i0 + 8;
    const int iwmin = qs + w * 16;
    const int iwmax = qs + w * 16 + 15;
    const int cbs = (lane & 3) * 2;

    // wait for Q (leaves KV0, KV1 outstanding)
    CP_WAIT(2);
    __syncthreads();
    uint32_t qf[8][4];
#pragma unroll
    for (int kc = 0; kc < 8; kc++)
        LDSM4(qf[kc], sQ + adr128(w * 16 + arow, 2 * kc + acb));

    float o[16][4];
#pragma unroll
    for (int i = 0; i < 16; i++) { o[i][0] = 0.f; o[i][1] = 0.f; o[i][2] = 0.f; o[i][3] = 0.f; }
    float m0 = -1e30f, m1 = -1e30f, l0 = 0.f, l1 = 0.f;

    for (int it = 0; it < ntiles; it++) {
        const bool snk = (sink && it == 0);
        const int ts = snk ? 0 : t0 + (it - sink) * 64;
        const int n2max = snk ? 1 : 4;

        if (it + 1 < ntiles) { CP_WAIT(1); } else { CP_WAIT(0); }
        __syncthreads();

        if (it + 2 < ntiles) {
            int tsn = t0 + (it + 2 - sink) * 64;
            uint32_t st = sKV + ((it + 2) % 3) * 32768;
            size_t kb = kvbase + (size_t)tsn * DHEAD;
#pragma unroll
            for (int p = 0; p < 4; p++) {
                int idx = tid + p * 256;
                int row = idx >> 4, ch = idx & 15;
                uint32_t d = adr128(row, ch);
                size_t s = kb + (size_t)row * DHEAD + ch * 8;
                cp16(st +     0 + d, kh_g + s);
                cp16(st + 16384 + d, vh_g + s);
            }
            CP_COMMIT();
        }

        uint32_t stg = sKV + (it % 3) * 32768;
        uint32_t sK = stg, sV = stg + 16384;

        float sc[8][4];
#pragma unroll
        for (int i = 0; i < 8; i++) { sc[i][0] = 0.f; sc[i][1] = 0.f; sc[i][2] = 0.f; sc[i][3] = 0.f; }

        for (int n2 = 0; n2 < n2max; n2++) {
            if (ts + n2 * 16 > iwmax) break;
#pragma unroll
            for (int kc = 0; kc < 8; kc++) {
                uint32_t kf[4];
                LDSM4(kf, sK + adr128(n2 * 16 + brow, 2 * kc + bcb));
                MMA_H(sc[2 * n2],     qf[kc], kf[0], kf[1]);
                MMA_H(sc[2 * n2 + 1], qf[kc], kf[2], kf[3]);
            }
        }

        float rm0 = -1e30f, rm1 = -1e30f;
        const bool full = (!snk) && (ts + 63 <= iwmin) && (ts >= iwmax - SWIN);
        if (full) {
#pragma unroll
            for (int nt = 0; nt < 8; nt++) {
                rm0 = fmaxf(rm0, fmaxf(sc[nt][0], sc[nt][1]));
                rm1 = fmaxf(rm1, fmaxf(sc[nt][2], sc[nt][3]));
            }
        } else {
#pragma unroll
            for (int nt = 0; nt < 8; nt++) {
                int j0 = ts + nt * 8 + cbs, j1 = j0 + 1;
                sc[nt][0] = (j0 <= i0 && (j0 >= i0 - SWIN || j0 < SINK)) ? sc[nt][0] : -1e30f;
                sc[nt][1] = (j1 <= i0 && (j1 >= i0 - SWIN || j1 < SINK)) ? sc[nt][1] : -1e30f;
                sc[nt][2] = (j0 <= i1 && (j0 >= i1 - SWIN || j0 < SINK)) ? sc[nt][2] : -1e30f;
                sc[nt][3] = (j1 <= i1 && (j1 >= i1 - SWIN || j1 < SINK)) ? sc[nt][3] : -1e30f;
                rm0 = fmaxf(rm0, fmaxf(sc[nt][0], sc[nt][1]));
                rm1 = fmaxf(rm1, fmaxf(sc[nt][2], sc[nt][3]));
            }
        }
        rm0 = fmaxf(rm0, __shfl_xor_sync(0xffffffffu, rm0, 1));
        rm0 = fmaxf(rm0, __shfl_xor_sync(0xffffffffu, rm0, 2));
        rm1 = fmaxf(rm1, __shfl_xor_sync(0xffffffffu, rm1, 1));
        rm1 = fmaxf(rm1, __shfl_xor_sync(0xffffffffu, rm1, 2));
        float mn0 = fmaxf(m0, rm0), mn1 = fmaxf(m1, rm1);
        float c0 = __expf(m0 - mn0), c1 = __expf(m1 - mn1);
        m0 = mn0; m1 = mn1;

        if (c0 != 1.f || c1 != 1.f) {
#pragma unroll
            for (int nd = 0; nd < 16; nd++) {
                o[nd][0] *= c0; o[nd][1] *= c0; o[nd][2] *= c1; o[nd][3] *= c1;
            }
        }

        float rs0 = 0.f, rs1 = 0.f;
        for (int k2 = 0; k2 < n2max; k2++) {
            if (ts + k2 * 16 > iwmax) break;
            uint32_t aP[4];
#pragma unroll
            for (int q2 = 0; q2 < 2; q2++) {
                int nt = 2 * k2 + q2;
                float p00 = __expf(sc[nt][0] - mn0), p01 = __expf(sc[nt][1] - mn0);
                float p10 = __expf(sc[nt][2] - mn1), p11 = __expf(sc[nt][3] - mn1);
                rs0 += p00 + p01; rs1 += p10 + p11;
                __half2 h0v = __floats2half2_rn(p00, p01);
                __half2 h1v = __floats2half2_rn(p10, p11);
                aP[2 * q2]     = *(uint32_t*)&h0v;
                aP[2 * q2 + 1] = *(uint32_t*)&h1v;
            }
#pragma unroll
            for (int ndp = 0; ndp < 8; ndp++) {
                uint32_t bv[4];
                LDSM4T(bv, sV + adr128(k2 * 16 + vr_i, ndp * 2 + vc_i));
                MMA_H(o[ndp * 2],     aP, bv[0], bv[1]);
                MMA_H(o[ndp * 2 + 1], aP, bv[2], bv[3]);
            }
        }
        rs0 += __shfl_xor_sync(0xffffffffu, rs0, 1);
        rs0 += __shfl_xor_sync(0xffffffffu, rs0, 2);
        rs1 += __shfl_xor_sync(0xffffffffu, rs1, 1);
        rs1 += __shfl_xor_sync(0xffffffffu, rs1, 2);
        l0 = l0 * c0 + rs0;
        l1 = l1 * c1 + rs1;
    }

    float il0 = 1.f / l0, il1 = 1.f / l1;
    size_t or0 = (size_t)(b * TSEQ + qs + w * 16 + (lane >> 2)) * CEMB + h * DHEAD;
    size_t or1 = or0 + (size_t)8 * CEMB;
#pragma unroll
    for (int nd = 0; nd < 16; nd++) {
        int col = nd * 8 + cbs;
        *(__half2*)(oh + or0 + col) = __floats2half2_rn(o[nd][0] * il0, o[nd][1] * il0);
        *(__half2*)(oh + or1 + col) = __floats2half2_rn(o[nd][2] * il1, o[nd][3] * il1);
    }
}

// ---------------------------------------------------------------------------
extern "C" void kernel_launch(void* const* d_in, const int* in_sizes, int n_in,
                              void* d_out, int out_size)
{
    const float* x  = (const float*)d_in[0];
    const float* Wq = (const float*)d_in[1];
    const float* bq = (const float*)d_in[2];
    const float* Wk = (const float*)d_in[3];
    const float* bk = (const float*)d_in[4];
    const float* Wv = (const float*)d_in[5];
    const float* bv = (const float*)d_in[6];
    const float* Wo = (const float*)d_in[7];
    const float* bo = (const float*)d_in[8];
    float* out = (float*)d_out;

    __half *xh, *qh, *kh, *vh, *oh, *wt, *wot;
    float2* rope;
    cudaGetSymbolAddress((void**)&xh,  g_xh);
    cudaGetSymbolAddress((void**)&qh,  g_qh);
    cudaGetSymbolAddress((void**)&kh,  g_kh);
    cudaGetSymbolAddress((void**)&vh,  g_vh);
    cudaGetSymbolAddress((void**)&oh,  g_oh);
    cudaGetSymbolAddress((void**)&wt,  g_WT);
    cudaGetSymbolAddress((void**)&wot, g_WoT);
    cudaGetSymbolAddress((void**)&rope, g_rope);

    const int GEMM_SMEM = 99328;    // 3*32KB + align
    cudaFuncSetAttribute(gemm_qkv, cudaFuncAttributeMaxDynamicSharedMemorySize, GEMM_SMEM);
    cudaFuncSetAttribute(gemm_wo,  cudaFuncAttributeMaxDynamicSharedMemorySize, GEMM_SMEM);
    const int ATTN_SMEM = 132096;   // 32KB Q + 3*32KB KV + align
    cudaFuncSetAttribute(attn_mma, cudaFuncAttributeMaxDynamicSharedMemorySize, ATTN_SMEM);

    // (0) prep  (1) QKV weights  (2) Wo weights
    prep<<<512 + (MROWS * CEMB / 4) / 256, 256>>>(x, xh, rope);
    tsplit_qkv<<<dim3(96, 64), dim3(32, 8)>>>(Wq, Wk, Wv, wt);
    tsplit_wo<<<dim3(64, 64), dim3(32, 8)>>>(Wo, wot);

    // (3) fused QKV projection + rope + pack  ← ncu capture slot
    gemm_qkv<<<dim3(NQKV / 128, MROWS / 128), 256, GEMM_SMEM>>>(
        xh, wt, bq, bk, bv, qh, kh, vh, rope);

    // (4) flash attention
    attn_mma<<<dim3(TSEQ / 128, 2 * NHEAD), 256, ATTN_SMEM>>>(qh, kh, vh, oh);

    // (5) output projection
    gemm_wo<<<dim3(CEMB / 128, MROWS / 128), 256, GEMM_SMEM>>>(oh, wot, bo, out);
}

// round 13
// speedup vs baseline: 2.5782x; 1.0091x over previous
#include <cuda_runtime.h>
#include <cuda_fp16.h>
#include <math.h>
#include <stdint.h>

// Problem constants
#define MROWS 4096   // B*T
#define CEMB  2048
#define TSEQ  2048
#define NHEAD 16
#define NGROUP 4
#define DHEAD 128
#define KVC   512
#define SWIN  512
#define SINK  4
#define NQKV  3072

// scratch (all fp16)
__device__ __half g_xh [(size_t)MROWS * CEMB];
__device__ __half g_oh [(size_t)MROWS * CEMB];
__device__ __half g_qh [(size_t)MROWS * CEMB];          // [b,h,t,d] pre-scaled
__device__ __half g_kh [(size_t)MROWS * KVC];           // [b,g,t,d]
__device__ __half g_vh [(size_t)MROWS * KVC];
__device__ __half g_WT [(size_t)NQKV * CEMB];           // packed Wq|Wk|Wv, [N,K]
__device__ __half g_WoT[(size_t)CEMB * CEMB];
__device__ float2 g_rope[(size_t)TSEQ * 64];

// ---------------------------------------------------------------------------
// helpers
// ---------------------------------------------------------------------------
__device__ __forceinline__ uint32_t cvta_s(const void* p) {
    return (uint32_t)__cvta_generic_to_shared(p);
}
__device__ __forceinline__ void cp16(uint32_t dst, const void* src) {
    asm volatile("cp.async.cg.shared.global [%0], [%1], 16;\n" :: "r"(dst), "l"(src));
}
#define CP_COMMIT() asm volatile("cp.async.commit_group;\n" ::: "memory")
#define CP_WAIT(n)  asm volatile("cp.async.wait_group %0;\n" :: "n"(n) : "memory")

#define LDSM4(r, addr) \
    asm volatile("ldmatrix.sync.aligned.m8n8.x4.shared.b16 {%0,%1,%2,%3}, [%4];" \
        : "=r"((r)[0]), "=r"((r)[1]), "=r"((r)[2]), "=r"((r)[3]) : "r"(addr))

#define LDSM4T(r, addr) \
    asm volatile("ldmatrix.sync.aligned.m8n8.x4.trans.shared.b16 {%0,%1,%2,%3}, [%4];" \
        : "=r"((r)[0]), "=r"((r)[1]), "=r"((r)[2]), "=r"((r)[3]) : "r"(addr))

#define MMA_H(c, a, b0, b1) \
    asm volatile("mma.sync.aligned.m16n8k16.row.col.f32.f16.f16.f32 " \
        "{%0,%1,%2,%3},{%4,%5,%6,%7},{%8,%9},{%0,%1,%2,%3};" \
        : "+f"((c)[0]), "+f"((c)[1]), "+f"((c)[2]), "+f"((c)[3]) \
        : "r"((a)[0]), "r"((a)[1]), "r"((a)[2]), "r"((a)[3]), "r"(b0), "r"(b1))

// 128B-row swizzled address (BK=64 GEMM tiles): row r (0..127), 16B chunk c (0..7)
__device__ __forceinline__ uint32_t adrK(int r, int c) {
    return (uint32_t)(r * 128 + ((c ^ (r & 7)) << 4));
}
// 256B-row swizzled address (attention tiles): row r, 16B chunk c (0..15)
__device__ __forceinline__ uint32_t adr128(int r, int c) {
    return (uint32_t)(r * 256 + ((c ^ (r & 7)) << 4));
}

// ---------------------------------------------------------------------------
// prep: rope table (blocks [0,512)) + x fp32->fp16 (blocks [512, 512+4096))
// ---------------------------------------------------------------------------
__global__ void prep(const float* __restrict__ x, __half* __restrict__ xh,
                     float2* __restrict__ tab)
{
    int bid = blockIdx.x;
    if (bid < 512) {
        int i = bid * 256 + threadIdx.x;
        int d = i & 63, t = i >> 6;
        float inv = powf(10000.f, -(float)d * (1.f / 64.f));
        float s, c;
        sincosf((float)t * inv, &s, &c);
        tab[i] = make_float2(c, s);
    } else {
        int i = (bid - 512) * 256 + threadIdx.x;
        float4 v = ((const float4*)x)[i];
        __half2* p = (__half2*)xh;
        p[i * 2 + 0] = __floats2half2_rn(v.x, v.y);
        p[i * 2 + 1] = __floats2half2_rn(v.z, v.w);
    }
}

// ---------------------------------------------------------------------------
// transpose QKV weights -> fp16 single (packed rows)
// ---------------------------------------------------------------------------
__global__ void tsplit_qkv(const float* __restrict__ Wq,
                           const float* __restrict__ Wk,
                           const float* __restrict__ Wv,
                           __half* __restrict__ hi)
{
    __shared__ float t[32][33];
    int bx = blockIdx.x, k0 = blockIdx.y * 32;
    const float* W; int N, n0, ro;
    if (bx < 64)      { W = Wq; N = 2048; n0 = bx * 32;        ro = 0; }
    else if (bx < 80) { W = Wk; N = 512;  n0 = (bx - 64) * 32; ro = 2048; }
    else              { W = Wv; N = 512;  n0 = (bx - 80) * 32; ro = 2560; }
    int tx = threadIdx.x, ty = threadIdx.y;
#pragma unroll
    for (int i = 0; i < 4; i++)
        t[ty + 8 * i][tx] = W[(size_t)(k0 + ty + 8 * i) * N + n0 + tx];
    __syncthreads();
#pragma unroll
    for (int i = 0; i < 4; i++)
        hi[(size_t)(ro + n0 + ty + 8 * i) * CEMB + k0 + tx] =
            __float2half_rn(t[tx][ty + 8 * i]);
}

// ---------------------------------------------------------------------------
// transpose Wo -> fp16 single
// ---------------------------------------------------------------------------
__global__ void tsplit_wo(const float* __restrict__ W, __half* __restrict__ hi)
{
    __shared__ float t[32][33];
    int n0 = blockIdx.x * 32, k0 = blockIdx.y * 32;
    int tx = threadIdx.x, ty = threadIdx.y;
#pragma unroll
    for (int i = 0; i < 4; i++)
        t[ty + 8 * i][tx] = W[(size_t)(k0 + ty + 8 * i) * CEMB + n0 + tx];
    __syncthreads();
#pragma unroll
    for (int i = 0; i < 4; i++)
        hi[(size_t)(n0 + ty + 8 * i) * CEMB + k0 + tx] =
            __float2half_rn(t[tx][ty + 8 * i]);
}

// ---------------------------------------------------------------------------
// QKV GEMM: 1-term fp16, BK=64, 3-stage, constant-offset addressing.
// Permuted B mapping for register-direct rope epilogue.
// ---------------------------------------------------------------------------
__global__ __launch_bounds__(256, 2) void gemm_qkv(
    const __half* __restrict__ A, const __half* __restrict__ B,
    const float* __restrict__ bq, const float* __restrict__ bk,
    const float* __restrict__ bv,
    __half* __restrict__ qh, __half* __restrict__ kh, __half* __restrict__ vh,
    const float2* __restrict__ rope)
{
    constexpr int KD = 2048, NCHUNK = 32, STG = 32768;
    constexpr size_t GSTRIDE = (size_t)32 * KD;   // +32 rows
    extern __shared__ char dsm[];
    uint32_t sbase = (cvta_s(dsm) + 1023) & ~1023u;

    const int tid = threadIdx.x;
    const int wid = tid >> 5, lane = tid & 31;
    const int wm = wid >> 2, wn = wid & 3;
    const int m0 = blockIdx.y * 128, n0 = blockIdx.x * 128;

    // single base slot; others at constant offsets (+p*4096 smem, +p*GSTRIDE gmem)
    const int r0_ = tid >> 3, c0_ = tid & 7;
    const uint32_t dst0 = adrK(r0_, c0_);
    const __half* pA = A + (size_t)(m0 + r0_) * KD + c0_ * 8;
    const __half* pB = B + (size_t)(n0 + r0_) * KD + c0_ * 8;

    const int arow = (lane & 7) + ((lane >> 3) & 1) * 8;
    const int acb  = lane >> 4;
    const int brow = (lane & 7) + (lane >> 4) * 8;
    const int bcb  = (lane >> 3) & 1;
    const int cbs  = (lane & 3) * 2;

    float acc[4][4][4];
#pragma unroll
    for (int i = 0; i < 4; i++)
#pragma unroll
        for (int j = 0; j < 4; j++) {
            acc[i][j][0] = 0.f; acc[i][j][1] = 0.f;
            acc[i][j][2] = 0.f; acc[i][j][3] = 0.f;
        }

#pragma unroll
    for (int ch = 0; ch < 2; ch++) {
        uint32_t st = sbase + ch * STG;
        int k0 = ch * 64;
#pragma unroll
        for (int p = 0; p < 4; p++) {
            cp16(st +     0 + dst0 + p * 4096, pA + p * GSTRIDE + k0);
            cp16(st + 16384 + dst0 + p * 4096, pB + p * GSTRIDE + k0);
        }
        CP_COMMIT();
    }

    for (int c = 0; c < NCHUNK; c++) {
        if (c + 1 < NCHUNK) { CP_WAIT(1); } else { CP_WAIT(0); }
        __syncthreads();
        if (c + 2 < NCHUNK) {
            int ch = c + 2;
            uint32_t st = sbase + (ch % 3) * STG;
            int k0 = ch * 64;
#pragma unroll
            for (int p = 0; p < 4; p++) {
                cp16(st +     0 + dst0 + p * 4096, pA + p * GSTRIDE + k0);
                cp16(st + 16384 + dst0 + p * 4096, pB + p * GSTRIDE + k0);
            }
            CP_COMMIT();
        }

        uint32_t st = sbase + (c % 3) * STG;
        uint32_t aB = st, bB = st + 16384;

#pragma unroll
        for (int ks = 0; ks < 4; ks++) {
            uint32_t ah[4][4], bh[2][4];
#pragma unroll
            for (int mt = 0; mt < 4; mt++)
                LDSM4(ah[mt], aB + adrK(wm * 64 + mt * 16 + arow, 2 * ks + acb));
#pragma unroll
            for (int np = 0; np < 2; np++)
                LDSM4(bh[np], bB + adrK(wn * 16 + np * 64 + brow, 2 * ks + bcb));
#pragma unroll
            for (int mt = 0; mt < 4; mt++)
#pragma unroll
                for (int nt = 0; nt < 4; nt++)
                    MMA_H(acc[mt][nt], ah[mt], bh[nt >> 1][(nt & 1) * 2],
                          bh[nt >> 1][(nt & 1) * 2 + 1]);
        }
    }

    // register-direct epilogue
    const float* bias = (n0 < 2048) ? bq + n0
                      : (n0 < 2560) ? bk + (n0 - 2048)
                                    : bv + (n0 - 2560);

    if (n0 < 2560) {
        const bool isQ = (n0 < 2048);
        const float qsc = isQ ? 0.08838834764831845f : 1.0f;
        const int hh = isQ ? (n0 >> 7) : ((n0 - 2048) >> 7);
        const int nh = isQ ? NHEAD : NGROUP;
        __half* Out = isQ ? qh : kh;
#pragma unroll
        for (int mt = 0; mt < 4; mt++) {
            int rg = m0 + wm * 64 + mt * 16 + (lane >> 2);
            int tr = rg & (TSEQ - 1);
            int bb = rg >> 11;
            size_t orow0 = ((size_t)(bb * nh + hh) * TSEQ + tr) * DHEAD;
            size_t orow1 = orow0 + 8 * DHEAD;
#pragma unroll
            for (int nt = 0; nt < 2; nt++) {
                int d0 = wn * 16 + nt * 8 + cbs;
                float bb1 = bias[d0],      bb2 = bias[d0 + 1];
                float bb3 = bias[d0 + 64], bb4 = bias[d0 + 65];
                float2 ca = rope[tr * 64 + d0], cb = rope[tr * 64 + d0 + 1];
                {
                    float x1a = acc[mt][nt][0] + bb1, x1b = acc[mt][nt][1] + bb2;
                    float x2a = acc[mt][nt + 2][0] + bb3, x2b = acc[mt][nt + 2][1] + bb4;
                    float y1a = (x1a * ca.x - x2a * ca.y) * qsc;
                    float y2a = (x1a * ca.y + x2a * ca.x) * qsc;
                    float y1b = (x1b * cb.x - x2b * cb.y) * qsc;
                    float y2b = (x1b * cb.y + x2b * cb.x) * qsc;
                    *(__half2*)(Out + orow0 + d0)      = __floats2half2_rn(y1a, y1b);
                    *(__half2*)(Out + orow0 + 64 + d0) = __floats2half2_rn(y2a, y2b);
                }
                {
                    float2 ca8 = rope[(tr + 8) * 64 + d0];
                    float2 cb8 = rope[(tr + 8) * 64 + d0 + 1];
                    float x1a = acc[mt][nt][2] + bb1, x1b = acc[mt][nt][3] + bb2;
                    float x2a = acc[mt][nt + 2][2] + bb3, x2b = acc[mt][nt + 2][3] + bb4;
                    float y1a = (x1a * ca8.x - x2a * ca8.y) * qsc;
                    float y2a = (x1a * ca8.y + x2a * ca8.x) * qsc;
                    float y1b = (x1b * cb8.x - x2b * cb8.y) * qsc;
                    float y2b = (x1b * cb8.y + x2b * cb8.x) * qsc;
                    *(__half2*)(Out + orow1 + d0)      = __floats2half2_rn(y1a, y1b);
                    *(__half2*)(Out + orow1 + 64 + d0) = __floats2half2_rn(y2a, y2b);
                }
            }
        }
    } else {
        const int g = (n0 - 2560) >> 7;
#pragma unroll
        for (int mt = 0; mt < 4; mt++) {
            int rg = m0 + wm * 64 + mt * 16 + (lane >> 2);
            int tr = rg & (TSEQ - 1);
            int bb = rg >> 11;
            size_t orow0 = ((size_t)(bb * NGROUP + g) * TSEQ + tr) * DHEAD;
            size_t orow1 = orow0 + 8 * DHEAD;
#pragma unroll
            for (int nt = 0; nt < 4; nt++) {
                int d0 = wn * 16 + (nt >> 1) * 64 + (nt & 1) * 8 + cbs;
                float bb1 = bias[d0], bb2 = bias[d0 + 1];
                *(__half2*)(vh + orow0 + d0) =
                    __floats2half2_rn(acc[mt][nt][0] + bb1, acc[mt][nt][1] + bb2);
                *(__half2*)(vh + orow1 + d0) =
                    __floats2half2_rn(acc[mt][nt][2] + bb1, acc[mt][nt][3] + bb2);
            }
        }
    }
}

// ---------------------------------------------------------------------------
// Wo GEMM: 1-term fp16, BK=64, 3-stage, constant-offset addressing, fp32 out.
// ---------------------------------------------------------------------------
__global__ __launch_bounds__(256, 2) void gemm_wo(
    const __half* __restrict__ A, const __half* __restrict__ B,
    const float* __restrict__ bias, float* __restrict__ C)
{
    constexpr int KD = 2048, NCHUNK = 32, STG = 32768;
    constexpr size_t GSTRIDE = (size_t)32 * KD;
    extern __shared__ char dsm[];
    uint32_t sbase = (cvta_s(dsm) + 1023) & ~1023u;

    const int tid = threadIdx.x;
    const int wid = tid >> 5, lane = tid & 31;
    const int wm = wid >> 2, wn = wid & 3;
    const int m0 = blockIdx.y * 128, n0 = blockIdx.x * 128;

    const int r0_ = tid >> 3, c0_ = tid & 7;
    const uint32_t dst0 = adrK(r0_, c0_);
    const __half* pA = A + (size_t)(m0 + r0_) * KD + c0_ * 8;
    const __half* pB = B + (size_t)(n0 + r0_) * KD + c0_ * 8;

    const int arow = (lane & 7) + ((lane >> 3) & 1) * 8;
    const int acb  = lane >> 4;
    const int brow = (lane & 7) + (lane >> 4) * 8;
    const int bcb  = (lane >> 3) & 1;

    float acc[4][4][4];
#pragma unroll
    for (int i = 0; i < 4; i++)
#pragma unroll
        for (int j = 0; j < 4; j++) {
            acc[i][j][0] = 0.f; acc[i][j][1] = 0.f;
            acc[i][j][2] = 0.f; acc[i][j][3] = 0.f;
        }

#pragma unroll
    for (int ch = 0; ch < 2; ch++) {
        uint32_t st = sbase + ch * STG;
        int k0 = ch * 64;
#pragma unroll
        for (int p = 0; p < 4; p++) {
            cp16(st +     0 + dst0 + p * 4096, pA + p * GSTRIDE + k0);
            cp16(st + 16384 + dst0 + p * 4096, pB + p * GSTRIDE + k0);
        }
        CP_COMMIT();
    }

    for (int c = 0; c < NCHUNK; c++) {
        if (c + 1 < NCHUNK) { CP_WAIT(1); } else { CP_WAIT(0); }
        __syncthreads();
        if (c + 2 < NCHUNK) {
            int ch = c + 2;
            uint32_t st = sbase + (ch % 3) * STG;
            int k0 = ch * 64;
#pragma unroll
            for (int p = 0; p < 4; p++) {
                cp16(st +     0 + dst0 + p * 4096, pA + p * GSTRIDE + k0);
                cp16(st + 16384 + dst0 + p * 4096, pB + p * GSTRIDE + k0);
            }
            CP_COMMIT();
        }

        uint32_t st = sbase + (c % 3) * STG;
        uint32_t aB = st, bB = st + 16384;

#pragma unroll
        for (int ks = 0; ks < 4; ks++) {
            uint32_t ah[4][4], bh[2][4];
#pragma unroll
            for (int mt = 0; mt < 4; mt++)
                LDSM4(ah[mt], aB + adrK(wm * 64 + mt * 16 + arow, 2 * ks + acb));
#pragma unroll
            for (int np = 0; np < 2; np++)
                LDSM4(bh[np], bB + adrK(wn * 32 + np * 16 + brow, 2 * ks + bcb));
#pragma unroll
            for (int mt = 0; mt < 4; mt++)
#pragma unroll
                for (int nt = 0; nt < 4; nt++)
                    MMA_H(acc[mt][nt], ah[mt], bh[nt >> 1][(nt & 1) * 2],
                          bh[nt >> 1][(nt & 1) * 2 + 1]);
        }
    }

#pragma unroll
    for (int mt = 0; mt < 4; mt++) {
        int r0 = m0 + wm * 64 + mt * 16 + (lane >> 2);
#pragma unroll
        for (int nt = 0; nt < 4; nt++) {
            int cc = n0 + wn * 32 + nt * 8 + (lane & 3) * 2;
            float bb0 = bias[cc], bb1 = bias[cc + 1];
            float2 v0 = make_float2(acc[mt][nt][0] + bb0, acc[mt][nt][1] + bb1);
            float2 v1 = make_float2(acc[mt][nt][2] + bb0, acc[mt][nt][3] + bb1);
            *(float2*)(C + (size_t)r0 * CEMB + cc) = v0;
            *(float2*)(C + (size_t)(r0 + 8) * CEMB + cc) = v1;
        }
    }
}

// ---------------------------------------------------------------------------
// flash attention: QT=128, KT=64, 3-stage KV, single barrier per tile.
// ---------------------------------------------------------------------------
__global__ __launch_bounds__(256, 1) void attn_mma(
    const __half* __restrict__ qh_g, const __half* __restrict__ kh_g,
    const __half* __restrict__ vh_g, __half* __restrict__ oh)
{
    extern __shared__ char sm[];
    uint32_t sb = (cvta_s(sm) + 1023) & ~1023u;
    const uint32_t sQ  = sb;
    const uint32_t sKV = sb + 32768;

    const int tid = threadIdx.x, w = tid >> 5, lane = tid & 31;
    const int b = blockIdx.y >> 4, h = blockIdx.y & 15, g = h >> 2;
    const int qs = blockIdx.x * 128;

    int t0 = qs - SWIN; if (t0 < 0) t0 = 0;
    const int sink = (t0 > 0) ? 1 : 0;
    const int ntiles = sink + (qs + 128 - t0) / 64;
    const size_t kvbase = (size_t)(b * NGROUP + g) * TSEQ * DHEAD;

    const int lr0 = tid >> 4, lc0 = tid & 15;
    const uint32_t ldst0 = adr128(lr0, lc0);
    const size_t goff0 = (size_t)lr0 * DHEAD + lc0 * 8;

    // Q load
    {
        size_t qb = ((size_t)(b * NHEAD + h) * TSEQ + qs) * DHEAD + goff0;
#pragma unroll
        for (int p = 0; p < 8; p++)
            cp16(sQ + ldst0 + p * 4096, qh_g + qb + p * (16 * DHEAD));
    }
    CP_COMMIT();

    // KV tiles 0 and 1
#pragma unroll
    for (int j = 0; j < 2; j++) {
        int ts = (sink && j == 0) ? 0 : t0 + (j - sink) * 64;
        uint32_t st = sKV + j * 32768;
        const __half* pk = kh_g + kvbase + (size_t)ts * DHEAD + goff0;
        const __half* pv = vh_g + kvbase + (size_t)ts * DHEAD + goff0;
#pragma unroll
        for (int p = 0; p < 4; p++) {
            cp16(st +     0 + ldst0 + p * 4096, pk + p * (16 * DHEAD));
            cp16(st + 16384 + ldst0 + p * 4096, pv + p * (16 * DHEAD));
        }
        CP_COMMIT();
    }

    const int arow = (lane & 7) + ((lane >> 3) & 1) * 8;
    const int acb  = lane >> 4;
    const int brow = (lane & 7) + (lane >> 4) * 8;
    const int bcb  = (lane >> 3) & 1;
    const int vr_i = ((lane >> 3) & 1) * 8 + (lane & 7);
    const int vc_i = lane >> 4;
    const int i0 = qs + w * 16 + (lane >> 2);
    const int i1 = i0 + 8;
    const int iwmin = qs + w * 16;
    const int iwmax = qs + w * 16 + 15;
    const int cbs = (lane & 3) * 2;

    CP_WAIT(2);
    __syncthreads();
    uint32_t qf[8][4];
#pragma unroll
    for (int kc = 0; kc < 8; kc++)
        LDSM4(qf[kc], sQ + adr128(w * 16 + arow, 2 * kc + acb));

    float o[16][4];
#pragma unroll
    for (int i = 0; i < 16; i++) { o[i][0] = 0.f; o[i][1] = 0.f; o[i][2] = 0.f; o[i][3] = 0.f; }
    float m0 = -1e30f, m1 = -1e30f, l0 = 0.f, l1 = 0.f;

    for (int it = 0; it < ntiles; it++) {
        const bool snk = (sink && it == 0);
        const int ts = snk ? 0 : t0 + (it - sink) * 64;
        const int n2max = snk ? 1 : 4;

        if (it + 1 < ntiles) { CP_WAIT(1); } else { CP_WAIT(0); }
        __syncthreads();

        if (it + 2 < ntiles) {
            int tsn = t0 + (it + 2 - sink) * 64;
            uint32_t st = sKV + ((it + 2) % 3) * 32768;
            const __half* pk = kh_g + kvbase + (size_t)tsn * DHEAD + goff0;
            const __half* pv = vh_g + kvbase + (size_t)tsn * DHEAD + goff0;
#pragma unroll
            for (int p = 0; p < 4; p++) {
                cp16(st +     0 + ldst0 + p * 4096, pk + p * (16 * DHEAD));
                cp16(st + 16384 + ldst0 + p * 4096, pv + p * (16 * DHEAD));
            }
            CP_COMMIT();
        }

        uint32_t stg = sKV + (it % 3) * 32768;
        uint32_t sK = stg, sV = stg + 16384;

        float sc[8][4];
#pragma unroll
        for (int i = 0; i < 8; i++) { sc[i][0] = 0.f; sc[i][1] = 0.f; sc[i][2] = 0.f; sc[i][3] = 0.f; }

        for (int n2 = 0; n2 < n2max; n2++) {
            if (ts + n2 * 16 > iwmax) break;
#pragma unroll
            for (int kc = 0; kc < 8; kc++) {
                uint32_t kf[4];
                LDSM4(kf, sK + adr128(n2 * 16 + brow, 2 * kc + bcb));
                MMA_H(sc[2 * n2],     qf[kc], kf[0], kf[1]);
                MMA_H(sc[2 * n2 + 1], qf[kc], kf[2], kf[3]);
            }
        }

        float rm0 = -1e30f, rm1 = -1e30f;
        const bool full = (!snk) && (ts + 63 <= iwmin) && (ts >= iwmax - SWIN);
        if (full) {
#pragma unroll
            for (int nt = 0; nt < 8; nt++) {
                rm0 = fmaxf(rm0, fmaxf(sc[nt][0], sc[nt][1]));
                rm1 = fmaxf(rm1, fmaxf(sc[nt][2], sc[nt][3]));
            }
        } else {
#pragma unroll
            for (int nt = 0; nt < 8; nt++) {
                int j0 = ts + nt * 8 + cbs, j1 = j0 + 1;
                sc[nt][0] = (j0 <= i0 && (j0 >= i0 - SWIN || j0 < SINK)) ? sc[nt][0] : -1e30f;
                sc[nt][1] = (j1 <= i0 && (j1 >= i0 - SWIN || j1 < SINK)) ? sc[nt][1] : -1e30f;
                sc[nt][2] = (j0 <= i1 && (j0 >= i1 - SWIN || j0 < SINK)) ? sc[nt][2] : -1e30f;
                sc[nt][3] = (j1 <= i1 && (j1 >= i1 - SWIN || j1 < SINK)) ? sc[nt][3] : -1e30f;
                rm0 = fmaxf(rm0, fmaxf(sc[nt][0], sc[nt][1]));
                rm1 = fmaxf(rm1, fmaxf(sc[nt][2], sc[nt][3]));
            }
        }
        rm0 = fmaxf(rm0, __shfl_xor_sync(0xffffffffu, rm0, 1));
        rm0 = fmaxf(rm0, __shfl_xor_sync(0xffffffffu, rm0, 2));
        rm1 = fmaxf(rm1, __shfl_xor_sync(0xffffffffu, rm1, 1));
        rm1 = fmaxf(rm1, __shfl_xor_sync(0xffffffffu, rm1, 2));
        float mn0 = fmaxf(m0, rm0), mn1 = fmaxf(m1, rm1);
        float c0 = __expf(m0 - mn0), c1 = __expf(m1 - mn1);
        m0 = mn0; m1 = mn1;

        if (c0 != 1.f || c1 != 1.f) {
#pragma unroll
            for (int nd = 0; nd < 16; nd++) {
                o[nd][0] *= c0; o[nd][1] *= c0; o[nd][2] *= c1; o[nd][3] *= c1;
            }
        }

        float rs0 = 0.f, rs1 = 0.f;
        for (int k2 = 0; k2 < n2max; k2++) {
            if (ts + k2 * 16 > iwmax) break;
            uint32_t aP[4];
#pragma unroll
            for (int q2 = 0; q2 < 2; q2++) {
                int nt = 2 * k2 + q2;
                float p00 = __expf(sc[nt][0] - mn0), p01 = __expf(sc[nt][1] - mn0);
                float p10 = __expf(sc[nt][2] - mn1), p11 = __expf(sc[nt][3] - mn1);
                rs0 += p00 + p01; rs1 += p10 + p11;
                __half2 h0v = __floats2half2_rn(p00, p01);
                __half2 h1v = __floats2half2_rn(p10, p11);
                aP[2 * q2]     = *(uint32_t*)&h0v;
                aP[2 * q2 + 1] = *(uint32_t*)&h1v;
            }
#pragma unroll
            for (int ndp = 0; ndp < 8; ndp++) {
                uint32_t bv[4];
                LDSM4T(bv, sV + adr128(k2 * 16 + vr_i, ndp * 2 + vc_i));
                MMA_H(o[ndp * 2],     aP, bv[0], bv[1]);
                MMA_H(o[ndp * 2 + 1], aP, bv[2], bv[3]);
            }
        }
        rs0 += __shfl_xor_sync(0xffffffffu, rs0, 1);
        rs0 += __shfl_xor_sync(0xffffffffu, rs0, 2);
        rs1 += __shfl_xor_sync(0xffffffffu, rs1, 1);
        rs1 += __shfl_xor_sync(0xffffffffu, rs1, 2);
        l0 = l0 * c0 + rs0;
        l1 = l1 * c1 + rs1;
    }

    float il0 = 1.f / l0, il1 = 1.f / l1;
    size_t or0 = (size_t)(b * TSEQ + qs + w * 16 + (lane >> 2)) * CEMB + h * DHEAD;
    size_t or1 = or0 + (size_t)8 * CEMB;
#pragma unroll
    for (int nd = 0; nd < 16; nd++) {
        int col = nd * 8 + cbs;
        *(__half2*)(oh + or0 + col) = __floats2half2_rn(o[nd][0] * il0, o[nd][1] * il0);
        *(__half2*)(oh + or1 + col) = __floats2half2_rn(o[nd][2] * il1, o[nd][3] * il1);
    }
}

// ---------------------------------------------------------------------------
extern "C" void kernel_launch(void* const* d_in, const int* in_sizes, int n_in,
                              void* d_out, int out_size)
{
    const float* x  = (const float*)d_in[0];
    const float* Wq = (const float*)d_in[1];
    const float* bq = (const float*)d_in[2];
    const float* Wk = (const float*)d_in[3];
    const float* bk = (const float*)d_in[4];
    const float* Wv = (const float*)d_in[5];
    const float* bv = (const float*)d_in[6];
    const float* Wo = (const float*)d_in[7];
    const float* bo = (const float*)d_in[8];
    float* out = (float*)d_out;

    __half *xh, *qh, *kh, *vh, *oh, *wt, *wot;
    float2* rope;
    cudaGetSymbolAddress((void**)&xh,  g_xh);
    cudaGetSymbolAddress((void**)&qh,  g_qh);
    cudaGetSymbolAddress((void**)&kh,  g_kh);
    cudaGetSymbolAddress((void**)&vh,  g_vh);
    cudaGetSymbolAddress((void**)&oh,  g_oh);
    cudaGetSymbolAddress((void**)&wt,  g_WT);
    cudaGetSymbolAddress((void**)&wot, g_WoT);
    cudaGetSymbolAddress((void**)&rope, g_rope);

    const int GEMM_SMEM = 99328;    // 3*32KB + align
    cudaFuncSetAttribute(gemm_qkv, cudaFuncAttributeMaxDynamicSharedMemorySize, GEMM_SMEM);
    cudaFuncSetAttribute(gemm_wo,  cudaFuncAttributeMaxDynamicSharedMemorySize, GEMM_SMEM);
    const int ATTN_SMEM = 132096;   // 32KB Q + 3*32KB KV + align
    cudaFuncSetAttribute(attn_mma, cudaFuncAttributeMaxDynamicSharedMemorySize, ATTN_SMEM);

    // (0) prep  (1) QKV weights  (2) Wo weights
    prep<<<512 + (MROWS * CEMB / 4) / 256, 256>>>(x, xh, rope);
    tsplit_qkv<<<dim3(96, 64), dim3(32, 8)>>>(Wq, Wk, Wv, wt);
    tsplit_wo<<<dim3(64, 64), dim3(32, 8)>>>(Wo, wot);

    // (3) fused QKV projection + rope + pack  ← ncu capture slot
    gemm_qkv<<<dim3(NQKV / 128, MROWS / 128), 256, GEMM_SMEM>>>(
        xh, wt, bq, bk, bv, qh, kh, vh, rope);

    // (4) flash attention
    attn_mma<<<dim3(TSEQ / 128, 2 * NHEAD), 256, ATTN_SMEM>>>(qh, kh, vh, oh);

    // (5) output projection
    gemm_wo<<<dim3(CEMB / 128, MROWS / 128), 256, GEMM_SMEM>>>(oh, wot, bo, out);
}